// round 2
// baseline (speedup 1.0000x reference)
#include <cuda_runtime.h>
#include <cuda_bf16.h>
#include <math.h>
#include <float.h>

#define NN 50000
#define EE 300000
#define EL (EE + NN)
#define GG 64
#define FD 64
#define NH 4
#define HC 256
#define LATD 256
#define GFD 832
#define SCAN_B 1024
#define NB1 ((NN + SCAN_B - 1) / SCAN_B)   // 49

// ---------------- device scratch ----------------
__device__ __nv_bfloat16 d_n0h[NN * FD], d_n0l[NN * FD];
__device__ __nv_bfloat16 d_x1h[NN * HC], d_x1l[NN * HC];
__device__ __nv_bfloat16 d_x2h[NN * HC], d_x2l[NN * HC];
__device__ __nv_bfloat16 d_x3h[NN * HC], d_x3l[NN * HC];
__device__ __nv_bfloat16 d_wth[3 * HC * HC], d_wtl[3 * HC * HC];
__device__ float d_h [NN * HC];
__device__ float d_as[NN * NH];
__device__ float d_ad[NN * NH];
__device__ int   d_deg[NN];
__device__ int   d_off[NN + 1];
__device__ int   d_cur[NN];
__device__ int   d_csr_src[EL];
__device__ int   d_bsum[NB1 + 1];
__device__ int   d_gstart[GG];
__device__ int   d_gend[GG];
__device__ float d_gfeat[GG * GFD];
__device__ float d_lat[GG * LATD];

// ---------------- CSR build ----------------
__global__ void k_init() {
    int i = blockIdx.x * blockDim.x + threadIdx.x;
    if (i < NN) d_deg[i] = 0;
    if (i < GG) { d_gstart[i] = NN; d_gend[i] = 0; }
    if (i == 0) d_off[0] = 0;
}

__global__ void k_deg(const int* __restrict__ ei) {
    int i = blockIdx.x * blockDim.x + threadIdx.x;
    if (i >= EL) return;
    int dst = (i < EE) ? ei[EE + i] : (i - EE);
    atomicAdd(&d_deg[dst], 1);
}

__global__ void k_scan1() {
    __shared__ int sm[SCAN_B];
    int tid = threadIdx.x;
    int i = blockIdx.x * SCAN_B + tid;
    int v = (i < NN) ? d_deg[i] : 0;
    sm[tid] = v;
    __syncthreads();
    for (int d = 1; d < SCAN_B; d <<= 1) {
        int t = 0;
        if (tid >= d) t = sm[tid - d];
        __syncthreads();
        sm[tid] += t;
        __syncthreads();
    }
    if (i < NN) d_off[i + 1] = sm[tid];
    if (tid == SCAN_B - 1) d_bsum[blockIdx.x] = sm[tid];
}

// warp-parallel exclusive scan over NB1 (<=64) block sums
__global__ void k_scan2() {
    int lane = threadIdx.x;
    int a = (lane < NB1) ? d_bsum[lane] : 0;
    int b = (lane + 32 < NB1) ? d_bsum[lane + 32] : 0;
    int ia = a;
#pragma unroll
    for (int o = 1; o < 32; o <<= 1) {
        int t = __shfl_up_sync(0xffffffffu, ia, o);
        if (lane >= o) ia += t;
    }
    int tot0 = __shfl_sync(0xffffffffu, ia, 31);
    int ib = b;
#pragma unroll
    for (int o = 1; o < 32; o <<= 1) {
        int t = __shfl_up_sync(0xffffffffu, ib, o);
        if (lane >= o) ib += t;
    }
    if (lane < NB1) d_bsum[lane] = ia - a;                    // exclusive
    if (lane + 32 < NB1) d_bsum[lane + 32] = tot0 + ib - b;
}

__global__ void k_scan3() {
    int i = blockIdx.x * blockDim.x + threadIdx.x;
    if (i < NN) d_off[i + 1] += d_bsum[i >> 10];
}

__global__ void k_cursor() {
    int i = blockIdx.x * blockDim.x + threadIdx.x;
    if (i < NN) d_cur[i] = d_off[i];
}

__global__ void k_scatter(const int* __restrict__ ei) {
    int i = blockIdx.x * blockDim.x + threadIdx.x;
    if (i >= EL) return;
    int src, dst;
    if (i < EE) { src = ei[i]; dst = ei[EE + i]; }
    else        { src = i - EE; dst = i - EE; }
    int pos = atomicAdd(&d_cur[dst], 1);
    d_csr_src[pos] = src;
}

__global__ void k_bounds(const int* __restrict__ batch) {
    int i = blockIdx.x * blockDim.x + threadIdx.x;
    if (i >= NN) return;
    int b = batch[i];
    atomicMin(&d_gstart[b], i);
    atomicMax(&d_gend[b], i + 1);
}

// ---------------- weight convert: W[K,256] fp32 -> Wt[256,K] bf16 hi/lo ----------------
__global__ void k_cvt_wt(const float* __restrict__ W, __nv_bfloat16* __restrict__ th,
                         __nv_bfloat16* __restrict__ tl, int K) {
    int i = blockIdx.x * blockDim.x + threadIdx.x;
    if (i >= K * HC) return;
    int k = i / HC, n = i % HC;
    float v = W[i];
    __nv_bfloat16 h = __float2bfloat16(v);
    th[n * K + k] = h;
    tl[n * K + k] = __float2bfloat16(v - __bfloat162float(h));
}

// ---------------- input projection: n0 = relu(bf @ bf_W + bf_b), stored bf16 hi/lo ----------------
__global__ void k_proj(const float* __restrict__ bf, const float* __restrict__ W,
                       const float* __restrict__ b) {
    int t = blockIdx.x * blockDim.x + threadIdx.x;
    if (t >= NN * FD) return;
    int n = t >> 6, f = t & 63;
    const float* r = &bf[n * 5];
    float acc = b[f];
    acc += r[0] * W[0 * FD + f];
    acc += r[1] * W[1 * FD + f];
    acc += r[2] * W[2 * FD + f];
    acc += r[3] * W[3 * FD + f];
    acc += r[4] * W[4 * FD + f];
    acc = acc > 0.f ? acc : 0.f;
    __nv_bfloat16 h = __float2bfloat16(acc);
    d_n0h[t] = h;
    d_n0l[t] = __float2bfloat16(acc - __bfloat162float(h));
}

// ---------------- bf16 split-precision tensor-core GEMM ----------------
// out[M,256] = x[M,K] @ W[K,256], x given as hi/lo bf16 [M,K], W as Wt hi/lo bf16 [256,K]
__device__ __forceinline__ void mma16816(float* d, const unsigned* a, unsigned b0, unsigned b1) {
    asm volatile(
        "mma.sync.aligned.m16n8k16.row.col.f32.bf16.bf16.f32 "
        "{%0,%1,%2,%3}, {%4,%5,%6,%7}, {%8,%9}, {%0,%1,%2,%3};\n"
        : "+f"(d[0]), "+f"(d[1]), "+f"(d[2]), "+f"(d[3])
        : "r"(a[0]), "r"(a[1]), "r"(a[2]), "r"(a[3]), "r"(b0), "r"(b1));
}

__global__ void __launch_bounds__(256) k_gemm(
    const __nv_bfloat16* __restrict__ xh, const __nv_bfloat16* __restrict__ xl,
    const __nv_bfloat16* __restrict__ wh, const __nv_bfloat16* __restrict__ wl,
    float* __restrict__ out, int K)
{
    int tid = threadIdx.x;
    int wid = tid >> 5, lane = tid & 31;
    int warp_m = wid >> 1, warp_n = wid & 1;
    int row0 = blockIdx.x * 128 + warp_m * 32;     // warp: 32 rows x 64 cols
    int col0 = blockIdx.y * 128 + warp_n * 64;
    int r = lane >> 2, c = (lane & 3) * 2;

    float acc[2][8][4];
#pragma unroll
    for (int mt = 0; mt < 2; mt++)
#pragma unroll
        for (int nt = 0; nt < 8; nt++)
#pragma unroll
            for (int i = 0; i < 4; i++) acc[mt][nt][i] = 0.f;

    for (int k0 = 0; k0 < K; k0 += 16) {
        unsigned ah[2][4], al[2][4];
#pragma unroll
        for (int mt = 0; mt < 2; mt++) {
            int r0_ = row0 + mt * 16 + r;
            int r1_ = r0_ + 8;
            const __nv_bfloat16* p0h = &xh[r0_ * K + k0 + c];
            const __nv_bfloat16* p1h = &xh[r1_ * K + k0 + c];
            const __nv_bfloat16* p0l = &xl[r0_ * K + k0 + c];
            const __nv_bfloat16* p1l = &xl[r1_ * K + k0 + c];
            ah[mt][0] = (r0_ < NN) ? *(const unsigned*)p0h : 0u;
            ah[mt][1] = (r1_ < NN) ? *(const unsigned*)p1h : 0u;
            ah[mt][2] = (r0_ < NN) ? *(const unsigned*)(p0h + 8) : 0u;
            ah[mt][3] = (r1_ < NN) ? *(const unsigned*)(p1h + 8) : 0u;
            al[mt][0] = (r0_ < NN) ? *(const unsigned*)p0l : 0u;
            al[mt][1] = (r1_ < NN) ? *(const unsigned*)p1l : 0u;
            al[mt][2] = (r0_ < NN) ? *(const unsigned*)(p0l + 8) : 0u;
            al[mt][3] = (r1_ < NN) ? *(const unsigned*)(p1l + 8) : 0u;
        }
#pragma unroll
        for (int nt = 0; nt < 8; nt++) {
            int n_ = col0 + nt * 8 + r;
            const __nv_bfloat16* pbh = &wh[n_ * K + k0 + c];
            const __nv_bfloat16* pbl = &wl[n_ * K + k0 + c];
            unsigned bh0 = *(const unsigned*)pbh;
            unsigned bh1 = *(const unsigned*)(pbh + 8);
            unsigned bl0 = *(const unsigned*)pbl;
            unsigned bl1 = *(const unsigned*)(pbl + 8);
#pragma unroll
            for (int mt = 0; mt < 2; mt++) {
                mma16816(acc[mt][nt], ah[mt], bh0, bh1);   // hi*hi
                mma16816(acc[mt][nt], ah[mt], bl0, bl1);   // hi*lo
                mma16816(acc[mt][nt], al[mt], bh0, bh1);   // lo*hi
            }
        }
    }
#pragma unroll
    for (int mt = 0; mt < 2; mt++) {
#pragma unroll
        for (int nt = 0; nt < 8; nt++) {
            int rr = row0 + mt * 16 + r;
            int cc = col0 + nt * 8 + c;
            if (rr < NN)
                *(float2*)&out[rr * HC + cc] = make_float2(acc[mt][nt][0], acc[mt][nt][1]);
            if (rr + 8 < NN)
                *(float2*)&out[(rr + 8) * HC + cc] = make_float2(acc[mt][nt][2], acc[mt][nt][3]);
        }
    }
}

// ---------------- attention dots ----------------
__global__ void k_att(const float* __restrict__ h, const float* __restrict__ asw,
                      const float* __restrict__ adw) {
    int w = (blockIdx.x * blockDim.x + threadIdx.x) >> 5;
    int lane = threadIdx.x & 31;
    if (w >= NN) return;
    float pa[4] = {0, 0, 0, 0}, pd[4] = {0, 0, 0, 0};
#pragma unroll
    for (int i = 0; i < 8; i++) {
        int col = lane + 32 * i;
        float hv = h[w * HC + col];
        pa[i >> 1] += hv * __ldg(&asw[col]);
        pd[i >> 1] += hv * __ldg(&adw[col]);
    }
#pragma unroll
    for (int hh = 0; hh < 4; hh++) {
        float a = pa[hh], d = pd[hh];
#pragma unroll
        for (int o = 16; o > 0; o >>= 1) {
            a += __shfl_xor_sync(0xffffffffu, a, o);
            d += __shfl_xor_sync(0xffffffffu, d, o);
        }
        if (lane == 0) { d_as[w * 4 + hh] = a; d_ad[w * 4 + hh] = d; }
    }
}

__device__ __forceinline__ float lrelu(float v) { return v > 0.f ? v : 0.2f * v; }

// ---------------- GAT aggregate (2 passes), writes bf16 hi/lo ----------------
__global__ void k_agg(const float* __restrict__ h, const float* __restrict__ bias,
                      __nv_bfloat16* __restrict__ oh, __nv_bfloat16* __restrict__ ol) {
    int n = (blockIdx.x * blockDim.x + threadIdx.x) >> 5;
    int lane = threadIdx.x & 31;
    if (n >= NN) return;
    int beg = d_off[n], end = d_off[n + 1];
    float4 ad4 = *(const float4*)&d_ad[n * 4];
    float adv[4] = {ad4.x, ad4.y, ad4.z, ad4.w};

    // pass 1: per-head max
    float mx[4] = {-FLT_MAX, -FLT_MAX, -FLT_MAX, -FLT_MAX};
    for (int j = beg + lane; j < end; j += 32) {
        int s = d_csr_src[j];
        float4 a4 = *(const float4*)&d_as[s * 4];
        mx[0] = fmaxf(mx[0], lrelu(a4.x + adv[0]));
        mx[1] = fmaxf(mx[1], lrelu(a4.y + adv[1]));
        mx[2] = fmaxf(mx[2], lrelu(a4.z + adv[2]));
        mx[3] = fmaxf(mx[3], lrelu(a4.w + adv[3]));
    }
#pragma unroll
    for (int hh = 0; hh < 4; hh++)
#pragma unroll
        for (int o = 16; o > 0; o >>= 1)
            mx[hh] = fmaxf(mx[hh], __shfl_xor_sync(0xffffffffu, mx[hh], o));

    // pass 2: weighted sum + normalizer (all lanes walk every edge)
    float sum0 = 0.f, sum1 = 0.f, sum2 = 0.f, sum3 = 0.f;
    float acc[8] = {0, 0, 0, 0, 0, 0, 0, 0};
    for (int j = beg; j < end; j++) {
        int s = d_csr_src[j];
        float4 a4 = *(const float4*)&d_as[s * 4];
        float w0 = expf(lrelu(a4.x + adv[0]) - mx[0]);
        float w1 = expf(lrelu(a4.y + adv[1]) - mx[1]);
        float w2 = expf(lrelu(a4.z + adv[2]) - mx[2]);
        float w3 = expf(lrelu(a4.w + adv[3]) - mx[3]);
        sum0 += w0; sum1 += w1; sum2 += w2; sum3 += w3;
        const float* hr = &h[s * HC];
        acc[0] += w0 * hr[lane +   0]; acc[1] += w0 * hr[lane +  32];
        acc[2] += w1 * hr[lane +  64]; acc[3] += w1 * hr[lane +  96];
        acc[4] += w2 * hr[lane + 128]; acc[5] += w2 * hr[lane + 160];
        acc[6] += w3 * hr[lane + 192]; acc[7] += w3 * hr[lane + 224];
    }
    float rs[4] = {1.f / sum0, 1.f / sum1, 1.f / sum2, 1.f / sum3};
#pragma unroll
    for (int i = 0; i < 8; i++) {
        int col = lane + 32 * i;
        float v = acc[i] * rs[i >> 1] + bias[col];
        v = v > 0.f ? v : 0.f;
        __nv_bfloat16 hv = __float2bfloat16(v);
        oh[n * HC + col] = hv;
        ol[n * HC + col] = __float2bfloat16(v - __bfloat162float(hv));
    }
}

// ---------------- graph pooling ----------------
__global__ void k_pool() {
    int g = blockIdx.x;
    int col = blockIdx.y * 128 + threadIdx.x;
    if (col >= GFD) return;
    const __nv_bfloat16 *bh, *bl; int stride, c;
    if (col < 64)       { bh = d_n0h; bl = d_n0l; stride = 64;  c = col; }
    else if (col < 320) { bh = d_x1h; bl = d_x1l; stride = 256; c = col - 64; }
    else if (col < 576) { bh = d_x2h; bl = d_x2l; stride = 256; c = col - 320; }
    else                { bh = d_x3h; bl = d_x3l; stride = 256; c = col - 576; }
    int s = d_gstart[g], e = d_gend[g];
    float v = -FLT_MAX;
    int i = s;
    for (; i + 4 <= e; i += 4) {
        float v0 = (float)bh[(i + 0) * stride + c] + (float)bl[(i + 0) * stride + c];
        float v1 = (float)bh[(i + 1) * stride + c] + (float)bl[(i + 1) * stride + c];
        float v2 = (float)bh[(i + 2) * stride + c] + (float)bl[(i + 2) * stride + c];
        float v3 = (float)bh[(i + 3) * stride + c] + (float)bl[(i + 3) * stride + c];
        v = fmaxf(v, fmaxf(fmaxf(v0, v1), fmaxf(v2, v3)));
    }
    for (; i < e; i++)
        v = fmaxf(v, (float)bh[i * stride + c] + (float)bl[i * stride + c]);
    d_gfeat[g * GFD + col] = v;
}

// ---------------- head MLPs ----------------
__global__ void k_latent(const float* __restrict__ W, const float* __restrict__ b) {
    __shared__ float gs[GFD];
    int g = blockIdx.x, t = threadIdx.x;
    for (int i = t; i < GFD; i += 256) gs[i] = d_gfeat[g * GFD + i];
    __syncthreads();
    float acc = b[t];
    for (int k = 0; k < GFD; k++) acc += gs[k] * W[k * LATD + t];
    d_lat[g * LATD + t] = acc;
}

__global__ void k_heads(const float* __restrict__ muW, const float* __restrict__ mub,
                        const float* __restrict__ vW, const float* __restrict__ vb,
                        float* __restrict__ out) {
    __shared__ float ls[LATD];
    int g = blockIdx.x, t = threadIdx.x;
    ls[t] = d_lat[g * LATD + t];
    __syncthreads();
    float am = mub[t], av = vb[t];
    for (int k = 0; k < LATD; k++) {
        float lv = ls[k];
        am += lv * muW[k * LATD + t];
        av += lv * vW[k * LATD + t];
    }
    out[g * LATD + t] = am;
    out[GG * LATD + g * LATD + t] = av;
}

// ---------------- launch ----------------
extern "C" void kernel_launch(void* const* d_in, const int* in_sizes, int n_in,
                              void* d_out, int out_size) {
    const float* bf   = (const float*)d_in[0];
    const int*   ei   = (const int*)  d_in[1];
    const int*   batch= (const int*)  d_in[2];
    const float* bfW  = (const float*)d_in[3];
    const float* bfb  = (const float*)d_in[4];
    const float* W1   = (const float*)d_in[5];
    const float* as1  = (const float*)d_in[6];
    const float* ad1  = (const float*)d_in[7];
    const float* b1   = (const float*)d_in[8];
    const float* W2   = (const float*)d_in[9];
    const float* as2  = (const float*)d_in[10];
    const float* ad2  = (const float*)d_in[11];
    const float* b2   = (const float*)d_in[12];
    const float* W3   = (const float*)d_in[13];
    const float* as3  = (const float*)d_in[14];
    const float* ad3  = (const float*)d_in[15];
    const float* b3   = (const float*)d_in[16];
    const float* aggW = (const float*)d_in[17];
    const float* aggb = (const float*)d_in[18];
    const float* muW  = (const float*)d_in[19];
    const float* mub  = (const float*)d_in[20];
    const float* vW   = (const float*)d_in[21];
    const float* vb   = (const float*)d_in[22];
    float* out = (float*)d_out;

    __nv_bfloat16 *p_n0h, *p_n0l, *p_x1h, *p_x1l, *p_x2h, *p_x2l, *p_x3h, *p_x3l, *p_wth, *p_wtl;
    float *p_h;
    cudaGetSymbolAddress((void**)&p_n0h, d_n0h);
    cudaGetSymbolAddress((void**)&p_n0l, d_n0l);
    cudaGetSymbolAddress((void**)&p_x1h, d_x1h);
    cudaGetSymbolAddress((void**)&p_x1l, d_x1l);
    cudaGetSymbolAddress((void**)&p_x2h, d_x2h);
    cudaGetSymbolAddress((void**)&p_x2l, d_x2l);
    cudaGetSymbolAddress((void**)&p_x3h, d_x3h);
    cudaGetSymbolAddress((void**)&p_x3l, d_x3l);
    cudaGetSymbolAddress((void**)&p_wth, d_wth);
    cudaGetSymbolAddress((void**)&p_wtl, d_wtl);
    cudaGetSymbolAddress((void**)&p_h,   d_h);

    const int T = 256;
    // CSR build
    k_init   <<<(NN + T - 1) / T, T>>>();
    k_deg    <<<(EL + T - 1) / T, T>>>(ei);
    k_scan1  <<<NB1, SCAN_B>>>();
    k_scan2  <<<1, 32>>>();
    k_scan3  <<<(NN + T - 1) / T, T>>>();
    k_cursor <<<(NN + T - 1) / T, T>>>();
    k_scatter<<<(EL + T - 1) / T, T>>>(ei);
    k_bounds <<<(NN + T - 1) / T, T>>>(batch);

    // weight transforms
    k_cvt_wt<<<(FD * HC + T - 1) / T, T>>>(W1, p_wth,              p_wtl,              FD);
    k_cvt_wt<<<(HC * HC + T - 1) / T, T>>>(W2, p_wth + HC * HC,     p_wtl + HC * HC,     HC);
    k_cvt_wt<<<(HC * HC + T - 1) / T, T>>>(W3, p_wth + 2 * HC * HC, p_wtl + 2 * HC * HC, HC);

    // input projection
    k_proj<<<(NN * FD + T - 1) / T, T>>>(bf, bfW, bfb);

    dim3 ggrid((NN + 127) / 128, 2);
    int wgrid = (NN + 7) / 8;   // 8 warps per 256-thread block

    // layer 1
    k_gemm<<<ggrid, 256>>>(p_n0h, p_n0l, p_wth, p_wtl, p_h, FD);
    k_att <<<wgrid, 256>>>(p_h, as1, ad1);
    k_agg <<<wgrid, 256>>>(p_h, b1, p_x1h, p_x1l);
    // layer 2
    k_gemm<<<ggrid, 256>>>(p_x1h, p_x1l, p_wth + HC * HC, p_wtl + HC * HC, p_h, HC);
    k_att <<<wgrid, 256>>>(p_h, as2, ad2);
    k_agg <<<wgrid, 256>>>(p_h, b2, p_x2h, p_x2l);
    // layer 3
    k_gemm<<<ggrid, 256>>>(p_x2h, p_x2l, p_wth + 2 * HC * HC, p_wtl + 2 * HC * HC, p_h, HC);
    k_att <<<wgrid, 256>>>(p_h, as3, ad3);
    k_agg <<<wgrid, 256>>>(p_h, b3, p_x3h, p_x3l);

    // pooling + heads
    dim3 pgrid(GG, (GFD + 127) / 128);
    k_pool  <<<pgrid, 128>>>();
    k_latent<<<GG, 256>>>(aggW, aggb);
    k_heads <<<GG, 256>>>(muW, mub, vW, vb, out);
}

// round 3
// speedup vs baseline: 1.4236x; 1.4236x over previous
#include <cuda_runtime.h>
#include <cuda_bf16.h>
#include <math.h>
#include <float.h>

#define NN 50000
#define EE 300000
#define EL (EE + NN)
#define GG 64
#define FD 64
#define NH 4
#define HC 256
#define LATD 256
#define GFD 832
#define SCAN_B 1024
#define NB1 ((NN + SCAN_B - 1) / SCAN_B)   // 49

// smem plane byte offsets for GEMM (row stride 80B = 32 bf16 + 8 pad)
#define AH_OFF 0
#define AL_OFF 10240
#define BH_OFF 20480
#define BL_OFF 30720
#define BUF_STRIDE 40960
#define SMEM_BYTES (2 * BUF_STRIDE)

// ---------------- device scratch ----------------
__device__ __nv_bfloat16 d_n0h[NN * FD], d_n0l[NN * FD];
__device__ __nv_bfloat16 d_x1h[NN * HC], d_x1l[NN * HC];
__device__ __nv_bfloat16 d_x2h[NN * HC], d_x2l[NN * HC];
__device__ __nv_bfloat16 d_x3h[NN * HC], d_x3l[NN * HC];
__device__ __nv_bfloat16 d_wth[3 * HC * HC], d_wtl[3 * HC * HC];
__device__ float d_h [NN * HC];
__device__ float d_as[NN * NH];
__device__ float d_ad[NN * NH];
__device__ int   d_deg[NN];
__device__ int   d_off[NN + 1];
__device__ int   d_cur[NN];
__device__ int   d_csr_src[EL];
__device__ int   d_bsum[NB1 + 1];
__device__ int   d_gstart[GG];
__device__ int   d_gend[GG];
__device__ float d_gfeat[GG * GFD];
__device__ float d_lat[GG * LATD];

// ---------------- CSR build ----------------
__global__ void k_init() {
    int i = blockIdx.x * blockDim.x + threadIdx.x;
    if (i < NN) d_deg[i] = 0;
    if (i < GG) { d_gstart[i] = NN; d_gend[i] = 0; }
    if (i == 0) d_off[0] = 0;
}

__global__ void k_deg(const int* __restrict__ ei) {
    int i = blockIdx.x * blockDim.x + threadIdx.x;
    if (i >= EL) return;
    int dst = (i < EE) ? ei[EE + i] : (i - EE);
    atomicAdd(&d_deg[dst], 1);
}

__global__ void k_scan1() {
    __shared__ int sm[SCAN_B];
    int tid = threadIdx.x;
    int i = blockIdx.x * SCAN_B + tid;
    int v = (i < NN) ? d_deg[i] : 0;
    sm[tid] = v;
    __syncthreads();
    for (int d = 1; d < SCAN_B; d <<= 1) {
        int t = 0;
        if (tid >= d) t = sm[tid - d];
        __syncthreads();
        sm[tid] += t;
        __syncthreads();
    }
    if (i < NN) d_off[i + 1] = sm[tid];
    if (tid == SCAN_B - 1) d_bsum[blockIdx.x] = sm[tid];
}

__global__ void k_scan2() {
    int lane = threadIdx.x;
    int a = (lane < NB1) ? d_bsum[lane] : 0;
    int b = (lane + 32 < NB1) ? d_bsum[lane + 32] : 0;
    int ia = a;
#pragma unroll
    for (int o = 1; o < 32; o <<= 1) {
        int t = __shfl_up_sync(0xffffffffu, ia, o);
        if (lane >= o) ia += t;
    }
    int tot0 = __shfl_sync(0xffffffffu, ia, 31);
    int ib = b;
#pragma unroll
    for (int o = 1; o < 32; o <<= 1) {
        int t = __shfl_up_sync(0xffffffffu, ib, o);
        if (lane >= o) ib += t;
    }
    if (lane < NB1) d_bsum[lane] = ia - a;
    if (lane + 32 < NB1) d_bsum[lane + 32] = tot0 + ib - b;
}

__global__ void k_scan3() {
    int i = blockIdx.x * blockDim.x + threadIdx.x;
    if (i < NN) d_off[i + 1] += d_bsum[i >> 10];
}

__global__ void k_cursor() {
    int i = blockIdx.x * blockDim.x + threadIdx.x;
    if (i < NN) d_cur[i] = d_off[i];
}

__global__ void k_scatter(const int* __restrict__ ei) {
    int i = blockIdx.x * blockDim.x + threadIdx.x;
    if (i >= EL) return;
    int src, dst;
    if (i < EE) { src = ei[i]; dst = ei[EE + i]; }
    else        { src = i - EE; dst = i - EE; }
    int pos = atomicAdd(&d_cur[dst], 1);
    d_csr_src[pos] = src;
}

__global__ void k_bounds(const int* __restrict__ batch) {
    int i = blockIdx.x * blockDim.x + threadIdx.x;
    if (i >= NN) return;
    int b = batch[i];
    atomicMin(&d_gstart[b], i);
    atomicMax(&d_gend[b], i + 1);
}

// ---------------- weight convert: W[K,256] fp32 -> Wt[256,K] bf16 hi/lo ----------------
__global__ void k_cvt_wt(const float* __restrict__ W, __nv_bfloat16* __restrict__ th,
                         __nv_bfloat16* __restrict__ tl, int K) {
    int i = blockIdx.x * blockDim.x + threadIdx.x;
    if (i >= K * HC) return;
    int k = i / HC, n = i % HC;
    float v = W[i];
    __nv_bfloat16 h = __float2bfloat16(v);
    th[n * K + k] = h;
    tl[n * K + k] = __float2bfloat16(v - __bfloat162float(h));
}

// ---------------- input projection ----------------
__global__ void k_proj(const float* __restrict__ bf, const float* __restrict__ W,
                       const float* __restrict__ b) {
    int t = blockIdx.x * blockDim.x + threadIdx.x;
    if (t >= NN * FD) return;
    int n = t >> 6, f = t & 63;
    const float* r = &bf[n * 5];
    float acc = b[f];
    acc += r[0] * W[0 * FD + f];
    acc += r[1] * W[1 * FD + f];
    acc += r[2] * W[2 * FD + f];
    acc += r[3] * W[3 * FD + f];
    acc += r[4] * W[4 * FD + f];
    acc = acc > 0.f ? acc : 0.f;
    __nv_bfloat16 h = __float2bfloat16(acc);
    d_n0h[t] = h;
    d_n0l[t] = __float2bfloat16(acc - __bfloat162float(h));
}

// ---------------- tensor-core GEMM + fused attention dots ----------------
__device__ __forceinline__ void mma16816(float* d, const unsigned* a, unsigned b0, unsigned b1) {
    asm volatile(
        "mma.sync.aligned.m16n8k16.row.col.f32.bf16.bf16.f32 "
        "{%0,%1,%2,%3}, {%4,%5,%6,%7}, {%8,%9}, {%0,%1,%2,%3};\n"
        : "+f"(d[0]), "+f"(d[1]), "+f"(d[2]), "+f"(d[3])
        : "r"(a[0]), "r"(a[1]), "r"(a[2]), "r"(a[3]), "r"(b0), "r"(b1));
}

__device__ __forceinline__ void ldm4(unsigned& r0, unsigned& r1, unsigned& r2, unsigned& r3,
                                     unsigned addr) {
    asm volatile("ldmatrix.sync.aligned.m8n8.x4.shared.b16 {%0,%1,%2,%3}, [%4];\n"
                 : "=r"(r0), "=r"(r1), "=r"(r2), "=r"(r3) : "r"(addr));
}

#define CPA(dst, src) asm volatile("cp.async.cg.shared.global [%0], [%1], 16;\n" :: "r"(dst), "l"(src))

extern __shared__ char smem_raw[];

__global__ void __launch_bounds__(256, 2) k_gemm(
    const __nv_bfloat16* __restrict__ xh, const __nv_bfloat16* __restrict__ xl,
    const __nv_bfloat16* __restrict__ wh, const __nv_bfloat16* __restrict__ wl,
    const float* __restrict__ asw, const float* __restrict__ adw,
    float* __restrict__ out, int K)
{
    unsigned sbase;
    asm("{ .reg .u64 t; cvta.to.shared.u64 t, %1; cvt.u32.u64 %0, t; }"
        : "=r"(sbase) : "l"(smem_raw));
    int tid = threadIdx.x, lane = tid & 31, wid = tid >> 5;
    int warp_m = wid & 3, warp_n = wid >> 2;
    int row0 = blockIdx.x * 128, col0 = blockIdx.y * 128;

    int lrow = tid >> 2;              // loader row 0..63 (two halves)
    unsigned lsegB = (tid & 3) * 16;  // byte segment within 64B row
    int nch = K >> 5;

    // fragment smem lane offsets
    unsigned a_off = (unsigned)((warp_m * 32 + (lane & 15)) * 80 + (lane >> 4) * 16);
    unsigned b_off = (unsigned)((warp_n * 64 + ((lane >> 4) << 3) + (lane & 7)) * 80
                                + ((lane >> 3) & 1) * 16);

    float acc[2][8][4];
#pragma unroll
    for (int mt = 0; mt < 2; mt++)
#pragma unroll
        for (int nt = 0; nt < 8; nt++)
#pragma unroll
            for (int i = 0; i < 4; i++) acc[mt][nt][i] = 0.f;

    auto load_chunk = [&](int c) {
        unsigned sb = sbase + (unsigned)((c & 1) * BUF_STRIDE);
        int k0 = c << 5;
#pragma unroll
        for (int half = 0; half < 2; half++) {
            int r = lrow + half * 64;
            unsigned so = (unsigned)(r * 80) + lsegB;
            int gr = row0 + r;
            if (gr < NN) {
                const char* pAh = (const char*)xh + ((size_t)gr * K + k0) * 2 + lsegB;
                const char* pAl = (const char*)xl + ((size_t)gr * K + k0) * 2 + lsegB;
                CPA(sb + AH_OFF + so, pAh);
                CPA(sb + AL_OFF + so, pAl);
            } else {
                asm volatile("st.shared.v4.b32 [%0], {%1,%1,%1,%1};" :: "r"(sb + AH_OFF + so), "r"(0u));
                asm volatile("st.shared.v4.b32 [%0], {%1,%1,%1,%1};" :: "r"(sb + AL_OFF + so), "r"(0u));
            }
            int gc = col0 + r;
            const char* pBh = (const char*)wh + ((size_t)gc * K + k0) * 2 + lsegB;
            const char* pBl = (const char*)wl + ((size_t)gc * K + k0) * 2 + lsegB;
            CPA(sb + BH_OFF + so, pBh);
            CPA(sb + BL_OFF + so, pBl);
        }
        asm volatile("cp.async.commit_group;\n");
    };

    load_chunk(0);
    for (int c = 0; c < nch; c++) {
        if (c + 1 < nch) {
            load_chunk(c + 1);
            asm volatile("cp.async.wait_group 1;\n");
        } else {
            asm volatile("cp.async.wait_group 0;\n");
        }
        __syncthreads();

        unsigned base = sbase + (unsigned)((c & 1) * BUF_STRIDE);
#pragma unroll
        for (int ko = 0; ko < 2; ko++) {
            unsigned kb = ko * 32;
            unsigned ah[2][4], al[2][4];
#pragma unroll
            for (int mt = 0; mt < 2; mt++) {
                ldm4(ah[mt][0], ah[mt][1], ah[mt][2], ah[mt][3],
                     base + AH_OFF + a_off + mt * 1280 + kb);
                ldm4(al[mt][0], al[mt][1], al[mt][2], al[mt][3],
                     base + AL_OFF + a_off + mt * 1280 + kb);
            }
#pragma unroll
            for (int p = 0; p < 4; p++) {
                unsigned bh[4], bl[4];
                ldm4(bh[0], bh[1], bh[2], bh[3], base + BH_OFF + b_off + p * 1280 + kb);
                ldm4(bl[0], bl[1], bl[2], bl[3], base + BL_OFF + b_off + p * 1280 + kb);
#pragma unroll
                for (int q = 0; q < 2; q++) {
                    int nt = p * 2 + q;
#pragma unroll
                    for (int mt = 0; mt < 2; mt++) {
                        mma16816(acc[mt][nt], ah[mt], bh[q * 2], bh[q * 2 + 1]);
                        mma16816(acc[mt][nt], ah[mt], bl[q * 2], bl[q * 2 + 1]);
                        mma16816(acc[mt][nt], al[mt], bh[q * 2], bh[q * 2 + 1]);
                    }
                }
            }
        }
        __syncthreads();
    }

    // ---- epilogue: store h + fused attention dots ----
    int head = blockIdx.y * 2 + warp_n;
    float pa[4] = {0, 0, 0, 0}, pd[4] = {0, 0, 0, 0};
#pragma unroll
    for (int nt = 0; nt < 8; nt++) {
        int cc = col0 + warp_n * 64 + nt * 8 + (lane & 3) * 2;
        float s0 = __ldg(&asw[cc]), s1 = __ldg(&asw[cc + 1]);
        float t0 = __ldg(&adw[cc]), t1 = __ldg(&adw[cc + 1]);
#pragma unroll
        for (int mt = 0; mt < 2; mt++) {
            float* a = acc[mt][nt];
            pa[mt * 2]     += a[0] * s0 + a[1] * s1;
            pa[mt * 2 + 1] += a[2] * s0 + a[3] * s1;
            pd[mt * 2]     += a[0] * t0 + a[1] * t1;
            pd[mt * 2 + 1] += a[2] * t0 + a[3] * t1;
            int rr = row0 + warp_m * 32 + mt * 16 + (lane >> 2);
            if (rr < NN)     *(float2*)&out[(size_t)rr * HC + cc]       = make_float2(a[0], a[1]);
            if (rr + 8 < NN) *(float2*)&out[(size_t)(rr + 8) * HC + cc] = make_float2(a[2], a[3]);
        }
    }
#pragma unroll
    for (int s = 0; s < 4; s++) {
        pa[s] += __shfl_xor_sync(0xffffffffu, pa[s], 1);
        pa[s] += __shfl_xor_sync(0xffffffffu, pa[s], 2);
        pd[s] += __shfl_xor_sync(0xffffffffu, pd[s], 1);
        pd[s] += __shfl_xor_sync(0xffffffffu, pd[s], 2);
    }
    if ((lane & 3) == 0) {
#pragma unroll
        for (int s = 0; s < 4; s++) {
            int rr = row0 + warp_m * 32 + (s >> 1) * 16 + (s & 1) * 8 + (lane >> 2);
            if (rr < NN) {
                d_as[rr * 4 + head] = pa[s];   // exactly one writer per (row, head)
                d_ad[rr * 4 + head] = pd[s];
            }
        }
    }
}

__device__ __forceinline__ float lrelu(float v) { return v > 0.f ? v : 0.2f * v; }

// ---------------- GAT aggregate (2 passes), writes bf16 hi/lo ----------------
__global__ void k_agg(const float* __restrict__ h, const float* __restrict__ bias,
                      __nv_bfloat16* __restrict__ oh, __nv_bfloat16* __restrict__ ol) {
    int n = (blockIdx.x * blockDim.x + threadIdx.x) >> 5;
    int lane = threadIdx.x & 31;
    if (n >= NN) return;
    int beg = d_off[n], end = d_off[n + 1];
    float4 ad4 = *(const float4*)&d_ad[n * 4];
    float adv[4] = {ad4.x, ad4.y, ad4.z, ad4.w};

    float mx[4] = {-FLT_MAX, -FLT_MAX, -FLT_MAX, -FLT_MAX};
    for (int j = beg + lane; j < end; j += 32) {
        int s = d_csr_src[j];
        float4 a4 = *(const float4*)&d_as[s * 4];
        mx[0] = fmaxf(mx[0], lrelu(a4.x + adv[0]));
        mx[1] = fmaxf(mx[1], lrelu(a4.y + adv[1]));
        mx[2] = fmaxf(mx[2], lrelu(a4.z + adv[2]));
        mx[3] = fmaxf(mx[3], lrelu(a4.w + adv[3]));
    }
#pragma unroll
    for (int hh = 0; hh < 4; hh++)
#pragma unroll
        for (int o = 16; o > 0; o >>= 1)
            mx[hh] = fmaxf(mx[hh], __shfl_xor_sync(0xffffffffu, mx[hh], o));

    float sum0 = 0.f, sum1 = 0.f, sum2 = 0.f, sum3 = 0.f;
    float acc[8] = {0, 0, 0, 0, 0, 0, 0, 0};
    for (int j = beg; j < end; j++) {
        int s = d_csr_src[j];
        float4 a4 = *(const float4*)&d_as[s * 4];
        float w0 = expf(lrelu(a4.x + adv[0]) - mx[0]);
        float w1 = expf(lrelu(a4.y + adv[1]) - mx[1]);
        float w2 = expf(lrelu(a4.z + adv[2]) - mx[2]);
        float w3 = expf(lrelu(a4.w + adv[3]) - mx[3]);
        sum0 += w0; sum1 += w1; sum2 += w2; sum3 += w3;
        const float* hr = &h[(size_t)s * HC];
        acc[0] += w0 * hr[lane +   0]; acc[1] += w0 * hr[lane +  32];
        acc[2] += w1 * hr[lane +  64]; acc[3] += w1 * hr[lane +  96];
        acc[4] += w2 * hr[lane + 128]; acc[5] += w2 * hr[lane + 160];
        acc[6] += w3 * hr[lane + 192]; acc[7] += w3 * hr[lane + 224];
    }
    float rs[4] = {1.f / sum0, 1.f / sum1, 1.f / sum2, 1.f / sum3};
#pragma unroll
    for (int i = 0; i < 8; i++) {
        int col = lane + 32 * i;
        float v = acc[i] * rs[i >> 1] + bias[col];
        v = v > 0.f ? v : 0.f;
        __nv_bfloat16 hv = __float2bfloat16(v);
        oh[n * HC + col] = hv;
        ol[n * HC + col] = __float2bfloat16(v - __bfloat162float(hv));
    }
}

// ---------------- graph pooling ----------------
__global__ void k_pool() {
    int g = blockIdx.x;
    int col = blockIdx.y * 128 + threadIdx.x;
    if (col >= GFD) return;
    const __nv_bfloat16 *bh, *bl; int stride, c;
    if (col < 64)       { bh = d_n0h; bl = d_n0l; stride = 64;  c = col; }
    else if (col < 320) { bh = d_x1h; bl = d_x1l; stride = 256; c = col - 64; }
    else if (col < 576) { bh = d_x2h; bl = d_x2l; stride = 256; c = col - 320; }
    else                { bh = d_x3h; bl = d_x3l; stride = 256; c = col - 576; }
    int s = d_gstart[g], e = d_gend[g];
    float v = -FLT_MAX;
    int i = s;
    for (; i + 4 <= e; i += 4) {
        float v0 = (float)bh[(i + 0) * stride + c] + (float)bl[(i + 0) * stride + c];
        float v1 = (float)bh[(i + 1) * stride + c] + (float)bl[(i + 1) * stride + c];
        float v2 = (float)bh[(i + 2) * stride + c] + (float)bl[(i + 2) * stride + c];
        float v3 = (float)bh[(i + 3) * stride + c] + (float)bl[(i + 3) * stride + c];
        v = fmaxf(v, fmaxf(fmaxf(v0, v1), fmaxf(v2, v3)));
    }
    for (; i < e; i++)
        v = fmaxf(v, (float)bh[i * stride + c] + (float)bl[i * stride + c]);
    d_gfeat[g * GFD + col] = v;
}

// ---------------- head MLPs ----------------
__global__ void k_latent(const float* __restrict__ W, const float* __restrict__ b) {
    __shared__ float gs[GFD];
    int g = blockIdx.x, t = threadIdx.x;
    for (int i = t; i < GFD; i += 256) gs[i] = d_gfeat[g * GFD + i];
    __syncthreads();
    float acc = b[t];
    for (int k = 0; k < GFD; k++) acc += gs[k] * W[k * LATD + t];
    d_lat[g * LATD + t] = acc;
}

__global__ void k_heads(const float* __restrict__ muW, const float* __restrict__ mub,
                        const float* __restrict__ vW, const float* __restrict__ vb,
                        float* __restrict__ out) {
    __shared__ float ls[LATD];
    int g = blockIdx.x, t = threadIdx.x;
    ls[t] = d_lat[g * LATD + t];
    __syncthreads();
    float am = mub[t], av = vb[t];
    for (int k = 0; k < LATD; k++) {
        float lv = ls[k];
        am += lv * muW[k * LATD + t];
        av += lv * vW[k * LATD + t];
    }
    out[g * LATD + t] = am;
    out[GG * LATD + g * LATD + t] = av;
}

// ---------------- launch ----------------
extern "C" void kernel_launch(void* const* d_in, const int* in_sizes, int n_in,
                              void* d_out, int out_size) {
    const float* bf   = (const float*)d_in[0];
    const int*   ei   = (const int*)  d_in[1];
    const int*   batch= (const int*)  d_in[2];
    const float* bfW  = (const float*)d_in[3];
    const float* bfb  = (const float*)d_in[4];
    const float* W1   = (const float*)d_in[5];
    const float* as1  = (const float*)d_in[6];
    const float* ad1  = (const float*)d_in[7];
    const float* b1   = (const float*)d_in[8];
    const float* W2   = (const float*)d_in[9];
    const float* as2  = (const float*)d_in[10];
    const float* ad2  = (const float*)d_in[11];
    const float* b2   = (const float*)d_in[12];
    const float* W3   = (const float*)d_in[13];
    const float* as3  = (const float*)d_in[14];
    const float* ad3  = (const float*)d_in[15];
    const float* b3   = (const float*)d_in[16];
    const float* aggW = (const float*)d_in[17];
    const float* aggb = (const float*)d_in[18];
    const float* muW  = (const float*)d_in[19];
    const float* mub  = (const float*)d_in[20];
    const float* vW   = (const float*)d_in[21];
    const float* vb   = (const float*)d_in[22];
    float* out = (float*)d_out;

    __nv_bfloat16 *p_n0h, *p_n0l, *p_x1h, *p_x1l, *p_x2h, *p_x2l, *p_x3h, *p_x3l, *p_wth, *p_wtl;
    float *p_h;
    cudaGetSymbolAddress((void**)&p_n0h, d_n0h);
    cudaGetSymbolAddress((void**)&p_n0l, d_n0l);
    cudaGetSymbolAddress((void**)&p_x1h, d_x1h);
    cudaGetSymbolAddress((void**)&p_x1l, d_x1l);
    cudaGetSymbolAddress((void**)&p_x2h, d_x2h);
    cudaGetSymbolAddress((void**)&p_x2l, d_x2l);
    cudaGetSymbolAddress((void**)&p_x3h, d_x3h);
    cudaGetSymbolAddress((void**)&p_x3l, d_x3l);
    cudaGetSymbolAddress((void**)&p_wth, d_wth);
    cudaGetSymbolAddress((void**)&p_wtl, d_wtl);
    cudaGetSymbolAddress((void**)&p_h,   d_h);

    static bool attr_done = false;
    if (!attr_done) {
        cudaFuncSetAttribute(k_gemm, cudaFuncAttributeMaxDynamicSharedMemorySize, SMEM_BYTES);
        attr_done = true;
    }

    const int T = 256;
    dim3 ggrid((NN + 127) / 128, 2);
    int wgrid = (NN + 7) / 8;

    // input projection + layer-1 weights first so a GEMM lands in the ncu window
    k_proj  <<<(NN * FD + T - 1) / T, T>>>(bf, bfW, bfb);
    k_cvt_wt<<<(FD * HC + T - 1) / T, T>>>(W1, p_wth, p_wtl, FD);
    k_init  <<<(NN + T - 1) / T, T>>>();
    k_gemm  <<<ggrid, 256, SMEM_BYTES>>>(p_n0h, p_n0l, p_wth, p_wtl, as1, ad1, p_h, FD);

    // CSR build
    k_deg    <<<(EL + T - 1) / T, T>>>(ei);
    k_scan1  <<<NB1, SCAN_B>>>();
    k_scan2  <<<1, 32>>>();
    k_scan3  <<<(NN + T - 1) / T, T>>>();
    k_cursor <<<(NN + T - 1) / T, T>>>();
    k_scatter<<<(EL + T - 1) / T, T>>>(ei);
    k_bounds <<<(NN + T - 1) / T, T>>>(batch);

    // remaining weight transforms
    k_cvt_wt<<<(HC * HC + T - 1) / T, T>>>(W2, p_wth + HC * HC,     p_wtl + HC * HC,     HC);
    k_cvt_wt<<<(HC * HC + T - 1) / T, T>>>(W3, p_wth + 2 * HC * HC, p_wtl + 2 * HC * HC, HC);

    // layer 1 aggregate
    k_agg<<<wgrid, 256>>>(p_h, b1, p_x1h, p_x1l);
    // layer 2
    k_gemm<<<ggrid, 256, SMEM_BYTES>>>(p_x1h, p_x1l, p_wth + HC * HC, p_wtl + HC * HC, as2, ad2, p_h, HC);
    k_agg <<<wgrid, 256>>>(p_h, b2, p_x2h, p_x2l);
    // layer 3
    k_gemm<<<ggrid, 256, SMEM_BYTES>>>(p_x2h, p_x2l, p_wth + 2 * HC * HC, p_wtl + 2 * HC * HC, as3, ad3, p_h, HC);
    k_agg <<<wgrid, 256>>>(p_h, b3, p_x3h, p_x3l);

    // pooling + heads
    dim3 pgrid(GG, (GFD + 127) / 128);
    k_pool  <<<pgrid, 128>>>();
    k_latent<<<GG, 256>>>(aggW, aggb);
    k_heads <<<GG, 256>>>(muW, mub, vW, vb, out);
}

// round 4
// speedup vs baseline: 1.4611x; 1.0264x over previous
#include <cuda_runtime.h>
#include <cuda_bf16.h>
#include <math.h>
#include <float.h>

#define NN 50000
#define EE 300000
#define EL (EE + NN)
#define GG 64
#define FD 64
#define NH 4
#define HC 256
#define LATD 256
#define GFD 832
#define SCAN_B 1024
#define NB1 ((NN + SCAN_B - 1) / SCAN_B)   // 49

// GEMM smem: 64B rows, XOR swizzle, 3 stages
#define AH_OFF 0
#define AL_OFF 8192
#define BH_OFF 16384
#define BL_OFF 24576
#define STAGE 32768
#define SMEM_BYTES (3 * STAGE)

// ---------------- device scratch ----------------
__device__ __nv_bfloat16 d_n0h[NN * FD], d_n0l[NN * FD];
__device__ __nv_bfloat16 d_x1h[NN * HC], d_x1l[NN * HC];
__device__ __nv_bfloat16 d_x2h[NN * HC], d_x2l[NN * HC];
__device__ __nv_bfloat16 d_x3h[NN * HC], d_x3l[NN * HC];
__device__ __nv_bfloat16 d_wth[3 * HC * HC], d_wtl[3 * HC * HC];
__device__ float d_h [NN * HC];
__device__ float d_as[NN * NH];
__device__ float d_ad[NN * NH];
__device__ float d_mx[NN * NH];
__device__ float d_rs[NN * NH];
__device__ float d_alpha[EL * NH];
__device__ int   d_deg[NN];
__device__ int   d_off[NN + 1];
__device__ int   d_cur[NN];
__device__ int   d_csr_src[EL];
__device__ int   d_csr_dst[EL];
__device__ int   d_bsum[NB1 + 1];
__device__ int   d_gstart[GG];
__device__ int   d_gend[GG];
__device__ float d_gfeat[GG * GFD];
__device__ float d_lat[GG * LATD];

// ---------------- CSR build ----------------
__global__ void k_init() {
    int i = blockIdx.x * blockDim.x + threadIdx.x;
    if (i < NN) d_deg[i] = 0;
    if (i < GG) { d_gstart[i] = NN; d_gend[i] = 0; }
    if (i == 0) d_off[0] = 0;
}

__global__ void k_deg(const int* __restrict__ ei) {
    int i = blockIdx.x * blockDim.x + threadIdx.x;
    if (i >= EL) return;
    int dst = (i < EE) ? ei[EE + i] : (i - EE);
    atomicAdd(&d_deg[dst], 1);
}

__global__ void k_scan1() {
    __shared__ int sm[SCAN_B];
    int tid = threadIdx.x;
    int i = blockIdx.x * SCAN_B + tid;
    int v = (i < NN) ? d_deg[i] : 0;
    sm[tid] = v;
    __syncthreads();
    for (int d = 1; d < SCAN_B; d <<= 1) {
        int t = 0;
        if (tid >= d) t = sm[tid - d];
        __syncthreads();
        sm[tid] += t;
        __syncthreads();
    }
    if (i < NN) d_off[i + 1] = sm[tid];
    if (tid == SCAN_B - 1) d_bsum[blockIdx.x] = sm[tid];
}

__global__ void k_scan2() {
    int lane = threadIdx.x;
    int a = (lane < NB1) ? d_bsum[lane] : 0;
    int b = (lane + 32 < NB1) ? d_bsum[lane + 32] : 0;
    int ia = a;
#pragma unroll
    for (int o = 1; o < 32; o <<= 1) {
        int t = __shfl_up_sync(0xffffffffu, ia, o);
        if (lane >= o) ia += t;
    }
    int tot0 = __shfl_sync(0xffffffffu, ia, 31);
    int ib = b;
#pragma unroll
    for (int o = 1; o < 32; o <<= 1) {
        int t = __shfl_up_sync(0xffffffffu, ib, o);
        if (lane >= o) ib += t;
    }
    if (lane < NB1) d_bsum[lane] = ia - a;
    if (lane + 32 < NB1) d_bsum[lane + 32] = tot0 + ib - b;
}

// merged scan-fixup + cursor init
__global__ void k_scan3() {
    int i = blockIdx.x * blockDim.x + threadIdx.x;
    if (i >= NN) return;
    int val = d_off[i + 1] + d_bsum[i >> 10];
    d_off[i + 1] = val;
    if (i + 1 < NN) d_cur[i + 1] = val;
    if (i == 0) d_cur[0] = 0;
}

__global__ void k_scatter(const int* __restrict__ ei) {
    int i = blockIdx.x * blockDim.x + threadIdx.x;
    if (i >= EL) return;
    int src, dst;
    if (i < EE) { src = ei[i]; dst = ei[EE + i]; }
    else        { src = i - EE; dst = i - EE; }
    int pos = atomicAdd(&d_cur[dst], 1);
    d_csr_src[pos] = src;
    d_csr_dst[pos] = dst;
}

__global__ void k_bounds(const int* __restrict__ batch) {
    int i = blockIdx.x * blockDim.x + threadIdx.x;
    if (i >= NN) return;
    int b = batch[i];
    atomicMin(&d_gstart[b], i);
    atomicMax(&d_gend[b], i + 1);
}

// ---------------- weight convert: W[K,256] fp32 -> Wt[256,K] bf16 hi/lo ----------------
__global__ void k_cvt_wt(const float* __restrict__ W, __nv_bfloat16* __restrict__ th,
                         __nv_bfloat16* __restrict__ tl, int K) {
    int i = blockIdx.x * blockDim.x + threadIdx.x;
    if (i >= K * HC) return;
    int k = i / HC, n = i % HC;
    float v = W[i];
    __nv_bfloat16 h = __float2bfloat16(v);
    th[n * K + k] = h;
    tl[n * K + k] = __float2bfloat16(v - __bfloat162float(h));
}

// ---------------- input projection ----------------
__global__ void k_proj(const float* __restrict__ bf, const float* __restrict__ W,
                       const float* __restrict__ b) {
    int t = blockIdx.x * blockDim.x + threadIdx.x;
    if (t >= NN * FD) return;
    int n = t >> 6, f = t & 63;
    const float* r = &bf[n * 5];
    float acc = b[f];
    acc += r[0] * W[0 * FD + f];
    acc += r[1] * W[1 * FD + f];
    acc += r[2] * W[2 * FD + f];
    acc += r[3] * W[3 * FD + f];
    acc += r[4] * W[4 * FD + f];
    acc = acc > 0.f ? acc : 0.f;
    __nv_bfloat16 h = __float2bfloat16(acc);
    d_n0h[t] = h;
    d_n0l[t] = __float2bfloat16(acc - __bfloat162float(h));
}

// ---------------- tensor-core GEMM + fused attention dots ----------------
__device__ __forceinline__ void mma16816(float* d, const unsigned* a, unsigned b0, unsigned b1) {
    asm volatile(
        "mma.sync.aligned.m16n8k16.row.col.f32.bf16.bf16.f32 "
        "{%0,%1,%2,%3}, {%4,%5,%6,%7}, {%8,%9}, {%0,%1,%2,%3};\n"
        : "+f"(d[0]), "+f"(d[1]), "+f"(d[2]), "+f"(d[3])
        : "r"(a[0]), "r"(a[1]), "r"(a[2]), "r"(a[3]), "r"(b0), "r"(b1));
}

__device__ __forceinline__ void ldm4(unsigned& r0, unsigned& r1, unsigned& r2, unsigned& r3,
                                     unsigned addr) {
    asm volatile("ldmatrix.sync.aligned.m8n8.x4.shared.b16 {%0,%1,%2,%3}, [%4];\n"
                 : "=r"(r0), "=r"(r1), "=r"(r2), "=r"(r3) : "r"(addr));
}

#define CPA(dst, src) asm volatile("cp.async.cg.shared.global [%0], [%1], 16;\n" :: "r"(dst), "l"(src))

extern __shared__ char smem_raw[];

__global__ void __launch_bounds__(256, 2) k_gemm(
    const __nv_bfloat16* __restrict__ xh, const __nv_bfloat16* __restrict__ xl,
    const __nv_bfloat16* __restrict__ wh, const __nv_bfloat16* __restrict__ wl,
    const float* __restrict__ asw, const float* __restrict__ adw,
    float* __restrict__ out, int K)
{
    unsigned sbase;
    asm("{ .reg .u64 t; cvta.to.shared.u64 t, %1; cvt.u32.u64 %0, t; }"
        : "=r"(sbase) : "l"(smem_raw));
    int tid = threadIdx.x, lane = tid & 31, wid = tid >> 5;
    int warp_m = wid & 3, warp_n = wid >> 2;
    int row0 = blockIdx.x * 128, col0 = blockIdx.y * 128;

    int lrow = tid >> 2;              // loader row 0..63 (two halves)
    unsigned lseg = tid & 3;          // logical 16B segment
    int nch = K >> 5;

    // swizzled fragment base offsets (ko=0); ko=1 -> XOR 32
    int a_row = warp_m * 32 + (lane & 15);
    unsigned a_base = (unsigned)(a_row * 64) + ((((lane >> 4) ^ ((a_row >> 1) & 3)) & 3u) << 4);
    int b_row = warp_n * 64 + ((lane >> 4) << 3) + (lane & 7);
    unsigned b_base = (unsigned)(b_row * 64) + (((((lane >> 3) & 1) ^ ((b_row >> 1) & 3)) & 3u) << 4);

    float acc[2][8][4];
#pragma unroll
    for (int mt = 0; mt < 2; mt++)
#pragma unroll
        for (int nt = 0; nt < 8; nt++)
#pragma unroll
            for (int i = 0; i < 4; i++) acc[mt][nt][i] = 0.f;

    auto load_chunk = [&](int c) {
        unsigned sb = sbase + (unsigned)((c % 3) * STAGE);
        int k0 = c << 5;
#pragma unroll
        for (int half = 0; half < 2; half++) {
            int r = lrow + half * 64;
            unsigned phys = (lseg ^ ((unsigned)(r >> 1) & 3u)) << 4;
            unsigned so = (unsigned)(r * 64) + phys;
            unsigned gofs = lseg * 16;
            int gr = row0 + r;
            if (gr < NN) {
                const char* pAh = (const char*)xh + ((size_t)gr * K + k0) * 2 + gofs;
                const char* pAl = (const char*)xl + ((size_t)gr * K + k0) * 2 + gofs;
                CPA(sb + AH_OFF + so, pAh);
                CPA(sb + AL_OFF + so, pAl);
            } else {
                asm volatile("st.shared.v4.b32 [%0], {%1,%1,%1,%1};" :: "r"(sb + AH_OFF + so), "r"(0u));
                asm volatile("st.shared.v4.b32 [%0], {%1,%1,%1,%1};" :: "r"(sb + AL_OFF + so), "r"(0u));
            }
            int gc = col0 + r;
            const char* pBh = (const char*)wh + ((size_t)gc * K + k0) * 2 + gofs;
            const char* pBl = (const char*)wl + ((size_t)gc * K + k0) * 2 + gofs;
            CPA(sb + BH_OFF + so, pBh);
            CPA(sb + BL_OFF + so, pBl);
        }
        asm volatile("cp.async.commit_group;\n");
    };

    load_chunk(0);
    load_chunk(1);
    for (int c = 0; c < nch; c++) {
        if (c < nch - 1) asm volatile("cp.async.wait_group 1;\n");
        else             asm volatile("cp.async.wait_group 0;\n");
        __syncthreads();
        if (c + 2 < nch) load_chunk(c + 2);

        unsigned base = sbase + (unsigned)((c % 3) * STAGE);
#pragma unroll
        for (int ko = 0; ko < 2; ko++) {
            unsigned kx = (unsigned)(ko << 5);
            unsigned ah[2][4], al[2][4];
#pragma unroll
            for (int mt = 0; mt < 2; mt++) {
                ldm4(ah[mt][0], ah[mt][1], ah[mt][2], ah[mt][3],
                     (base + AH_OFF + a_base + mt * 1024) ^ kx);
                ldm4(al[mt][0], al[mt][1], al[mt][2], al[mt][3],
                     (base + AL_OFF + a_base + mt * 1024) ^ kx);
            }
#pragma unroll
            for (int p = 0; p < 4; p++) {
                unsigned bh[4], bl[4];
                ldm4(bh[0], bh[1], bh[2], bh[3], (base + BH_OFF + b_base + p * 1024) ^ kx);
                ldm4(bl[0], bl[1], bl[2], bl[3], (base + BL_OFF + b_base + p * 1024) ^ kx);
#pragma unroll
                for (int q = 0; q < 2; q++) {
                    int nt = p * 2 + q;
#pragma unroll
                    for (int mt = 0; mt < 2; mt++) {
                        mma16816(acc[mt][nt], ah[mt], bh[q * 2], bh[q * 2 + 1]);
                        mma16816(acc[mt][nt], ah[mt], bl[q * 2], bl[q * 2 + 1]);
                        mma16816(acc[mt][nt], al[mt], bh[q * 2], bh[q * 2 + 1]);
                    }
                }
            }
        }
    }

    // ---- epilogue: store h + fused attention dots ----
    int head = blockIdx.y * 2 + warp_n;
    float pa[4] = {0, 0, 0, 0}, pd[4] = {0, 0, 0, 0};
#pragma unroll
    for (int nt = 0; nt < 8; nt++) {
        int cc = col0 + warp_n * 64 + nt * 8 + (lane & 3) * 2;
        float s0 = __ldg(&asw[cc]), s1 = __ldg(&asw[cc + 1]);
        float t0 = __ldg(&adw[cc]), t1 = __ldg(&adw[cc + 1]);
#pragma unroll
        for (int mt = 0; mt < 2; mt++) {
            float* a = acc[mt][nt];
            pa[mt * 2]     += a[0] * s0 + a[1] * s1;
            pa[mt * 2 + 1] += a[2] * s0 + a[3] * s1;
            pd[mt * 2]     += a[0] * t0 + a[1] * t1;
            pd[mt * 2 + 1] += a[2] * t0 + a[3] * t1;
            int rr = row0 + warp_m * 32 + mt * 16 + (lane >> 2);
            if (rr < NN)     *(float2*)&out[(size_t)rr * HC + cc]       = make_float2(a[0], a[1]);
            if (rr + 8 < NN) *(float2*)&out[(size_t)(rr + 8) * HC + cc] = make_float2(a[2], a[3]);
        }
    }
#pragma unroll
    for (int s = 0; s < 4; s++) {
        pa[s] += __shfl_xor_sync(0xffffffffu, pa[s], 1);
        pa[s] += __shfl_xor_sync(0xffffffffu, pa[s], 2);
        pd[s] += __shfl_xor_sync(0xffffffffu, pd[s], 1);
        pd[s] += __shfl_xor_sync(0xffffffffu, pd[s], 2);
    }
    if ((lane & 3) == 0) {
#pragma unroll
        for (int s = 0; s < 4; s++) {
            int rr = row0 + warp_m * 32 + (s >> 1) * 16 + (s & 1) * 8 + (lane >> 2);
            if (rr < NN) {
                d_as[rr * 4 + head] = pa[s];
                d_ad[rr * 4 + head] = pd[s];
            }
        }
    }
}

__device__ __forceinline__ float lrelu(float v) { return v > 0.f ? v : 0.2f * v; }

// ---------------- softmax stats: warp per node, lane-parallel ----------------
__global__ void k_attmax() {
    int n = (blockIdx.x * blockDim.x + threadIdx.x) >> 5;
    int lane = threadIdx.x & 31;
    if (n >= NN) return;
    int beg = d_off[n], end = d_off[n + 1];
    float4 ad4 = *(const float4*)&d_ad[n * 4];
    float adv[4] = {ad4.x, ad4.y, ad4.z, ad4.w};

    float mx[4] = {-FLT_MAX, -FLT_MAX, -FLT_MAX, -FLT_MAX};
    for (int j = beg + lane; j < end; j += 32) {
        int s = d_csr_src[j];
        float4 a4 = *(const float4*)&d_as[s * 4];
        mx[0] = fmaxf(mx[0], lrelu(a4.x + adv[0]));
        mx[1] = fmaxf(mx[1], lrelu(a4.y + adv[1]));
        mx[2] = fmaxf(mx[2], lrelu(a4.z + adv[2]));
        mx[3] = fmaxf(mx[3], lrelu(a4.w + adv[3]));
    }
#pragma unroll
    for (int hh = 0; hh < 4; hh++)
#pragma unroll
        for (int o = 16; o > 0; o >>= 1)
            mx[hh] = fmaxf(mx[hh], __shfl_xor_sync(0xffffffffu, mx[hh], o));

    float sm[4] = {0, 0, 0, 0};
    for (int j = beg + lane; j < end; j += 32) {
        int s = d_csr_src[j];
        float4 a4 = *(const float4*)&d_as[s * 4];
        sm[0] += __expf(lrelu(a4.x + adv[0]) - mx[0]);
        sm[1] += __expf(lrelu(a4.y + adv[1]) - mx[1]);
        sm[2] += __expf(lrelu(a4.z + adv[2]) - mx[2]);
        sm[3] += __expf(lrelu(a4.w + adv[3]) - mx[3]);
    }
#pragma unroll
    for (int hh = 0; hh < 4; hh++)
#pragma unroll
        for (int o = 16; o > 0; o >>= 1)
            sm[hh] += __shfl_xor_sync(0xffffffffu, sm[hh], o);

    if (lane == 0) {
        *(float4*)&d_mx[n * 4] = make_float4(mx[0], mx[1], mx[2], mx[3]);
        *(float4*)&d_rs[n * 4] = make_float4(1.f / sm[0], 1.f / sm[1], 1.f / sm[2], 1.f / sm[3]);
    }
}

// ---------------- per-edge normalized attention, edge-parallel ----------------
__global__ void k_alpha() {
    int j = blockIdx.x * blockDim.x + threadIdx.x;
    if (j >= EL) return;
    int s = d_csr_src[j];
    int d = d_csr_dst[j];
    float4 a4 = *(const float4*)&d_as[s * 4];
    float4 b4 = *(const float4*)&d_ad[d * 4];
    float4 m4 = *(const float4*)&d_mx[d * 4];
    float4 r4 = *(const float4*)&d_rs[d * 4];
    float4 w;
    w.x = __expf(lrelu(a4.x + b4.x) - m4.x) * r4.x;
    w.y = __expf(lrelu(a4.y + b4.y) - m4.y) * r4.y;
    w.z = __expf(lrelu(a4.z + b4.z) - m4.z) * r4.z;
    w.w = __expf(lrelu(a4.w + b4.w) - m4.w) * r4.w;
    *(float4*)&d_alpha[j * 4] = w;
}

// ---------------- weighted aggregation: 2 warps per node ----------------
__global__ void k_agg2(const float* __restrict__ h, const float* __restrict__ bias,
                       __nv_bfloat16* __restrict__ oh, __nv_bfloat16* __restrict__ ol) {
    int gw = (blockIdx.x * blockDim.x + threadIdx.x) >> 5;
    int lane = threadIdx.x & 31;
    int n = gw >> 1, half = gw & 1;
    if (n >= NN) return;
    int beg = d_off[n], end = d_off[n + 1];
    int cbase = half * 128;

    float acc[4] = {0, 0, 0, 0};
    for (int j = beg; j < end; j++) {
        int s = d_csr_src[j];
        float4 w4 = *(const float4*)&d_alpha[j * 4];
        float wa = half ? w4.z : w4.x;
        float wb = half ? w4.w : w4.y;
        const float* hr = &h[(size_t)s * HC + cbase];
        acc[0] += wa * hr[lane];
        acc[1] += wa * hr[lane + 32];
        acc[2] += wb * hr[lane + 64];
        acc[3] += wb * hr[lane + 96];
    }
#pragma unroll
    for (int i = 0; i < 4; i++) {
        int col = cbase + i * 32 + lane;
        float v = acc[i] + bias[col];
        v = v > 0.f ? v : 0.f;
        __nv_bfloat16 hv = __float2bfloat16(v);
        oh[(size_t)n * HC + col] = hv;
        ol[(size_t)n * HC + col] = __float2bfloat16(v - __bfloat162float(hv));
    }
}

// ---------------- graph pooling ----------------
__global__ void k_pool() {
    int g = blockIdx.x;
    int col = blockIdx.y * 128 + threadIdx.x;
    if (col >= GFD) return;
    const __nv_bfloat16 *bh, *bl; int stride, c;
    if (col < 64)       { bh = d_n0h; bl = d_n0l; stride = 64;  c = col; }
    else if (col < 320) { bh = d_x1h; bl = d_x1l; stride = 256; c = col - 64; }
    else if (col < 576) { bh = d_x2h; bl = d_x2l; stride = 256; c = col - 320; }
    else                { bh = d_x3h; bl = d_x3l; stride = 256; c = col - 576; }
    int s = d_gstart[g], e = d_gend[g];
    float v = -FLT_MAX;
    int i = s;
    for (; i + 4 <= e; i += 4) {
        float v0 = (float)bh[(i + 0) * stride + c] + (float)bl[(i + 0) * stride + c];
        float v1 = (float)bh[(i + 1) * stride + c] + (float)bl[(i + 1) * stride + c];
        float v2 = (float)bh[(i + 2) * stride + c] + (float)bl[(i + 2) * stride + c];
        float v3 = (float)bh[(i + 3) * stride + c] + (float)bl[(i + 3) * stride + c];
        v = fmaxf(v, fmaxf(fmaxf(v0, v1), fmaxf(v2, v3)));
    }
    for (; i < e; i++)
        v = fmaxf(v, (float)bh[i * stride + c] + (float)bl[i * stride + c]);
    d_gfeat[g * GFD + col] = v;
}

// ---------------- head MLPs ----------------
__global__ void k_latent(const float* __restrict__ W, const float* __restrict__ b) {
    __shared__ float gs[GFD];
    int g = blockIdx.x, t = threadIdx.x;
    for (int i = t; i < GFD; i += 256) gs[i] = d_gfeat[g * GFD + i];
    __syncthreads();
    float acc = b[t];
    for (int k = 0; k < GFD; k++) acc += gs[k] * W[k * LATD + t];
    d_lat[g * LATD + t] = acc;
}

__global__ void k_heads(const float* __restrict__ muW, const float* __restrict__ mub,
                        const float* __restrict__ vW, const float* __restrict__ vb,
                        float* __restrict__ out) {
    __shared__ float ls[LATD];
    int g = blockIdx.x, t = threadIdx.x;
    ls[t] = d_lat[g * LATD + t];
    __syncthreads();
    float am = mub[t], av = vb[t];
    for (int k = 0; k < LATD; k++) {
        float lv = ls[k];
        am += lv * muW[k * LATD + t];
        av += lv * vW[k * LATD + t];
    }
    out[g * LATD + t] = am;
    out[GG * LATD + g * LATD + t] = av;
}

// ---------------- launch ----------------
extern "C" void kernel_launch(void* const* d_in, const int* in_sizes, int n_in,
                              void* d_out, int out_size) {
    const float* bf   = (const float*)d_in[0];
    const int*   ei   = (const int*)  d_in[1];
    const int*   batch= (const int*)  d_in[2];
    const float* bfW  = (const float*)d_in[3];
    const float* bfb  = (const float*)d_in[4];
    const float* W1   = (const float*)d_in[5];
    const float* as1  = (const float*)d_in[6];
    const float* ad1  = (const float*)d_in[7];
    const float* b1   = (const float*)d_in[8];
    const float* W2   = (const float*)d_in[9];
    const float* as2  = (const float*)d_in[10];
    const float* ad2  = (const float*)d_in[11];
    const float* b2   = (const float*)d_in[12];
    const float* W3   = (const float*)d_in[13];
    const float* as3  = (const float*)d_in[14];
    const float* ad3  = (const float*)d_in[15];
    const float* b3   = (const float*)d_in[16];
    const float* aggW = (const float*)d_in[17];
    const float* aggb = (const float*)d_in[18];
    const float* muW  = (const float*)d_in[19];
    const float* mub  = (const float*)d_in[20];
    const float* vW   = (const float*)d_in[21];
    const float* vb   = (const float*)d_in[22];
    float* out = (float*)d_out;

    __nv_bfloat16 *p_n0h, *p_n0l, *p_x1h, *p_x1l, *p_x2h, *p_x2l, *p_x3h, *p_x3l, *p_wth, *p_wtl;
    float *p_h;
    cudaGetSymbolAddress((void**)&p_n0h, d_n0h);
    cudaGetSymbolAddress((void**)&p_n0l, d_n0l);
    cudaGetSymbolAddress((void**)&p_x1h, d_x1h);
    cudaGetSymbolAddress((void**)&p_x1l, d_x1l);
    cudaGetSymbolAddress((void**)&p_x2h, d_x2h);
    cudaGetSymbolAddress((void**)&p_x2l, d_x2l);
    cudaGetSymbolAddress((void**)&p_x3h, d_x3h);
    cudaGetSymbolAddress((void**)&p_x3l, d_x3l);
    cudaGetSymbolAddress((void**)&p_wth, d_wth);
    cudaGetSymbolAddress((void**)&p_wtl, d_wtl);
    cudaGetSymbolAddress((void**)&p_h,   d_h);

    static bool attr_done = false;
    if (!attr_done) {
        cudaFuncSetAttribute(k_gemm, cudaFuncAttributeMaxDynamicSharedMemorySize, SMEM_BYTES);
        attr_done = true;
    }

    const int T = 256;
    dim3 ggrid((NN + 127) / 128, 2);
    int wgrid = (NN + 7) / 8;                 // warp-per-node kernels
    int agrid = (2 * NN + 7) / 8;             // 2 warps per node
    int egrid = (EL + T - 1) / T;

    k_proj  <<<(NN * FD + T - 1) / T, T>>>(bf, bfW, bfb);
    k_cvt_wt<<<(FD * HC + T - 1) / T, T>>>(W1, p_wth, p_wtl, FD);
    k_init  <<<(NN + T - 1) / T, T>>>();
    k_gemm  <<<ggrid, 256, SMEM_BYTES>>>(p_n0h, p_n0l, p_wth, p_wtl, as1, ad1, p_h, FD);

    // CSR build
    k_deg    <<<egrid, T>>>(ei);
    k_scan1  <<<NB1, SCAN_B>>>();
    k_scan2  <<<1, 32>>>();
    k_scan3  <<<(NN + T - 1) / T, T>>>();
    k_scatter<<<egrid, T>>>(ei);
    k_bounds <<<(NN + T - 1) / T, T>>>(batch);

    k_cvt_wt<<<(HC * HC + T - 1) / T, T>>>(W2, p_wth + HC * HC,     p_wtl + HC * HC,     HC);
    k_cvt_wt<<<(HC * HC + T - 1) / T, T>>>(W3, p_wth + 2 * HC * HC, p_wtl + 2 * HC * HC, HC);

    // layer 1 aggregate
    k_attmax<<<wgrid, 256>>>();
    k_alpha <<<egrid, T>>>();
    k_agg2  <<<agrid, 256>>>(p_h, b1, p_x1h, p_x1l);
    // layer 2
    k_gemm  <<<ggrid, 256, SMEM_BYTES>>>(p_x1h, p_x1l, p_wth + HC * HC, p_wtl + HC * HC, as2, ad2, p_h, HC);
    k_attmax<<<wgrid, 256>>>();
    k_alpha <<<egrid, T>>>();
    k_agg2  <<<agrid, 256>>>(p_h, b2, p_x2h, p_x2l);
    // layer 3
    k_gemm  <<<ggrid, 256, SMEM_BYTES>>>(p_x2h, p_x2l, p_wth + 2 * HC * HC, p_wtl + 2 * HC * HC, as3, ad3, p_h, HC);
    k_attmax<<<wgrid, 256>>>();
    k_alpha <<<egrid, T>>>();
    k_agg2  <<<agrid, 256>>>(p_h, b3, p_x3h, p_x3l);

    // pooling + heads
    dim3 pgrid(GG, (GFD + 127) / 128);
    k_pool  <<<pgrid, 128>>>();
    k_latent<<<GG, 256>>>(aggW, aggb);
    k_heads <<<GG, 256>>>(muW, mub, vW, vb, out);
}

// round 6
// speedup vs baseline: 1.4905x; 1.0201x over previous
#include <cuda_runtime.h>
#include <cuda_bf16.h>
#include <math.h>
#include <float.h>

#define NN 50000
#define EE 300000
#define EL (EE + NN)
#define GG 64
#define FD 64
#define NH 4
#define HC 256
#define LATD 256
#define GFD 832
#define SCAN_B 1024
#define NB1 ((NN + SCAN_B - 1) / SCAN_B)   // 49

// GEMM smem: 64B rows, XOR swizzle, 3 stages
#define AH_OFF 0
#define AL_OFF 8192
#define BH_OFF 16384
#define BL_OFF 24576
#define STAGE 32768
#define SMEM_BYTES (3 * STAGE)

// ---------------- device scratch ----------------
__device__ __nv_bfloat16 d_n0h[NN * FD], d_n0l[NN * FD];
__device__ __nv_bfloat16 d_x1h[NN * HC], d_x1l[NN * HC];
__device__ __nv_bfloat16 d_x2h[NN * HC], d_x2l[NN * HC];
__device__ __nv_bfloat16 d_x3h[NN * HC], d_x3l[NN * HC];
__device__ __nv_bfloat16 d_wth[3 * HC * HC], d_wtl[3 * HC * HC];
__device__ float d_h [NN * HC];
__device__ float d_as[NN * NH];
__device__ float d_ad[NN * NH];
__device__ float d_rs[NN * NH];
__device__ float d_alpha[(size_t)EL * NH];
__device__ int   d_deg[NN];
__device__ int   d_off[NN + 1];
__device__ int   d_cur[NN];
__device__ int   d_csr_src[EL];
__device__ int   d_bsum[NB1 + 1];
__device__ int   d_gstart[GG];
__device__ int   d_gend[GG];
__device__ float d_gfeat[GG * GFD];
__device__ float d_lat[GG * LATD];

// ---------------- CSR build ----------------
__global__ void k_init() {
    int i = blockIdx.x * blockDim.x + threadIdx.x;
    if (i < NN) d_deg[i] = 0;
    if (i < GG) { d_gstart[i] = NN; d_gend[i] = 0; }
    if (i == 0) d_off[0] = 0;
}

__global__ void k_deg(const int* __restrict__ ei) {
    int i = blockIdx.x * blockDim.x + threadIdx.x;
    if (i >= EL) return;
    int dst = (i < EE) ? ei[EE + i] : (i - EE);
    atomicAdd(&d_deg[dst], 1);
}

__global__ void k_scan1() {
    __shared__ int sm[SCAN_B];
    int tid = threadIdx.x;
    int i = blockIdx.x * SCAN_B + tid;
    int v = (i < NN) ? d_deg[i] : 0;
    sm[tid] = v;
    __syncthreads();
    for (int d = 1; d < SCAN_B; d <<= 1) {
        int t = 0;
        if (tid >= d) t = sm[tid - d];
        __syncthreads();
        sm[tid] += t;
        __syncthreads();
    }
    if (i < NN) d_off[i + 1] = sm[tid];
    if (tid == SCAN_B - 1) d_bsum[blockIdx.x] = sm[tid];
}

__global__ void k_scan2() {
    int lane = threadIdx.x;
    int a = (lane < NB1) ? d_bsum[lane] : 0;
    int b = (lane + 32 < NB1) ? d_bsum[lane + 32] : 0;
    int ia = a;
#pragma unroll
    for (int o = 1; o < 32; o <<= 1) {
        int t = __shfl_up_sync(0xffffffffu, ia, o);
        if (lane >= o) ia += t;
    }
    int tot0 = __shfl_sync(0xffffffffu, ia, 31);
    int ib = b;
#pragma unroll
    for (int o = 1; o < 32; o <<= 1) {
        int t = __shfl_up_sync(0xffffffffu, ib, o);
        if (lane >= o) ib += t;
    }
    if (lane < NB1) d_bsum[lane] = ia - a;
    if (lane + 32 < NB1) d_bsum[lane + 32] = tot0 + ib - b;
}

// merged scan-fixup + cursor init
__global__ void k_scan3() {
    int i = blockIdx.x * blockDim.x + threadIdx.x;
    if (i >= NN) return;
    int val = d_off[i + 1] + d_bsum[i >> 10];
    d_off[i + 1] = val;
    if (i + 1 < NN) d_cur[i + 1] = val;
    if (i == 0) d_cur[0] = 0;
}

__global__ void k_scatter(const int* __restrict__ ei) {
    int i = blockIdx.x * blockDim.x + threadIdx.x;
    if (i >= EL) return;
    int src, dst;
    if (i < EE) { src = ei[i]; dst = ei[EE + i]; }
    else        { src = i - EE; dst = i - EE; }
    int pos = atomicAdd(&d_cur[dst], 1);
    d_csr_src[pos] = src;
}

__global__ void k_bounds(const int* __restrict__ batch) {
    int i = blockIdx.x * blockDim.x + threadIdx.x;
    if (i >= NN) return;
    int b = batch[i];
    atomicMin(&d_gstart[b], i);
    atomicMax(&d_gend[b], i + 1);
}

// ---------------- weight convert: W[K,256] fp32 -> Wt[256,K] bf16 hi/lo ----------------
__global__ void k_cvt_wt(const float* __restrict__ W, __nv_bfloat16* __restrict__ th,
                         __nv_bfloat16* __restrict__ tl, int K) {
    int i = blockIdx.x * blockDim.x + threadIdx.x;
    if (i >= K * HC) return;
    int k = i / HC, n = i % HC;
    float v = W[i];
    __nv_bfloat16 h = __float2bfloat16(v);
    th[n * K + k] = h;
    tl[n * K + k] = __float2bfloat16(v - __bfloat162float(h));
}

// ---------------- input projection ----------------
__global__ void k_proj(const float* __restrict__ bf, const float* __restrict__ W,
                       const float* __restrict__ b) {
    int t = blockIdx.x * blockDim.x + threadIdx.x;
    if (t >= NN * FD) return;
    int n = t >> 6, f = t & 63;
    const float* r = &bf[n * 5];
    float acc = b[f];
    acc += r[0] * W[0 * FD + f];
    acc += r[1] * W[1 * FD + f];
    acc += r[2] * W[2 * FD + f];
    acc += r[3] * W[3 * FD + f];
    acc += r[4] * W[4 * FD + f];
    acc = acc > 0.f ? acc : 0.f;
    __nv_bfloat16 h = __float2bfloat16(acc);
    d_n0h[t] = h;
    d_n0l[t] = __float2bfloat16(acc - __bfloat162float(h));
}

// ---------------- tensor-core GEMM + fused attention dots ----------------
__device__ __forceinline__ void mma16816(float* d, const unsigned* a, unsigned b0, unsigned b1) {
    asm volatile(
        "mma.sync.aligned.m16n8k16.row.col.f32.bf16.bf16.f32 "
        "{%0,%1,%2,%3}, {%4,%5,%6,%7}, {%8,%9}, {%0,%1,%2,%3};\n"
        : "+f"(d[0]), "+f"(d[1]), "+f"(d[2]), "+f"(d[3])
        : "r"(a[0]), "r"(a[1]), "r"(a[2]), "r"(a[3]), "r"(b0), "r"(b1));
}

__device__ __forceinline__ void ldm4(unsigned& r0, unsigned& r1, unsigned& r2, unsigned& r3,
                                     unsigned addr) {
    asm volatile("ldmatrix.sync.aligned.m8n8.x4.shared.b16 {%0,%1,%2,%3}, [%4];\n"
                 : "=r"(r0), "=r"(r1), "=r"(r2), "=r"(r3) : "r"(addr));
}

#define CPA(dst, src) asm volatile("cp.async.cg.shared.global [%0], [%1], 16;\n" :: "r"(dst), "l"(src))

extern __shared__ char smem_raw[];

__global__ void __launch_bounds__(256, 2) k_gemm(
    const __nv_bfloat16* __restrict__ xh, const __nv_bfloat16* __restrict__ xl,
    const __nv_bfloat16* __restrict__ wh, const __nv_bfloat16* __restrict__ wl,
    const float* __restrict__ asw, const float* __restrict__ adw,
    float* __restrict__ out, int K)
{
    unsigned sbase;
    asm("{ .reg .u64 t; cvta.to.shared.u64 t, %1; cvt.u32.u64 %0, t; }"
        : "=r"(sbase) : "l"(smem_raw));
    int tid = threadIdx.x, lane = tid & 31, wid = tid >> 5;
    int warp_m = wid & 3, warp_n = wid >> 2;
    int row0 = blockIdx.x * 128, col0 = blockIdx.y * 128;

    int lrow = tid >> 2;              // loader row 0..63 (two halves)
    unsigned lseg = tid & 3;          // logical 16B segment
    int nch = K >> 5;

    // swizzled fragment base offsets (ko=0); ko=1 -> XOR 32
    int a_row = warp_m * 32 + (lane & 15);
    unsigned a_base = (unsigned)(a_row * 64) + ((((lane >> 4) ^ ((a_row >> 1) & 3)) & 3u) << 4);
    int b_row = warp_n * 64 + ((lane >> 4) << 3) + (lane & 7);
    unsigned b_base = (unsigned)(b_row * 64) + (((((lane >> 3) & 1) ^ ((b_row >> 1) & 3)) & 3u) << 4);

    float acc[2][8][4];
#pragma unroll
    for (int mt = 0; mt < 2; mt++)
#pragma unroll
        for (int nt = 0; nt < 8; nt++)
#pragma unroll
            for (int i = 0; i < 4; i++) acc[mt][nt][i] = 0.f;

    auto load_chunk = [&](int c) {
        unsigned sb = sbase + (unsigned)((c % 3) * STAGE);
        int k0 = c << 5;
#pragma unroll
        for (int half = 0; half < 2; half++) {
            int r = lrow + half * 64;
            unsigned phys = (lseg ^ ((unsigned)(r >> 1) & 3u)) << 4;
            unsigned so = (unsigned)(r * 64) + phys;
            unsigned gofs = lseg * 16;
            int gr = row0 + r;
            if (gr < NN) {
                const char* pAh = (const char*)xh + ((size_t)gr * K + k0) * 2 + gofs;
                const char* pAl = (const char*)xl + ((size_t)gr * K + k0) * 2 + gofs;
                CPA(sb + AH_OFF + so, pAh);
                CPA(sb + AL_OFF + so, pAl);
            } else {
                asm volatile("st.shared.v4.b32 [%0], {%1,%1,%1,%1};" :: "r"(sb + AH_OFF + so), "r"(0u));
                asm volatile("st.shared.v4.b32 [%0], {%1,%1,%1,%1};" :: "r"(sb + AL_OFF + so), "r"(0u));
            }
            int gc = col0 + r;
            const char* pBh = (const char*)wh + ((size_t)gc * K + k0) * 2 + gofs;
            const char* pBl = (const char*)wl + ((size_t)gc * K + k0) * 2 + gofs;
            CPA(sb + BH_OFF + so, pBh);
            CPA(sb + BL_OFF + so, pBl);
        }
        asm volatile("cp.async.commit_group;\n");
    };

    load_chunk(0);
    load_chunk(1);
    for (int c = 0; c < nch; c++) {
        if (c < nch - 1) asm volatile("cp.async.wait_group 1;\n");
        else             asm volatile("cp.async.wait_group 0;\n");
        __syncthreads();
        if (c + 2 < nch) load_chunk(c + 2);

        unsigned base = sbase + (unsigned)((c % 3) * STAGE);
#pragma unroll
        for (int ko = 0; ko < 2; ko++) {
            unsigned kx = (unsigned)(ko << 5);
            unsigned ah[2][4], al[2][4];
#pragma unroll
            for (int mt = 0; mt < 2; mt++) {
                ldm4(ah[mt][0], ah[mt][1], ah[mt][2], ah[mt][3],
                     (base + AH_OFF + a_base + mt * 1024) ^ kx);
                ldm4(al[mt][0], al[mt][1], al[mt][2], al[mt][3],
                     (base + AL_OFF + a_base + mt * 1024) ^ kx);
            }
            // B-fragment double buffer: prefetch p+1 while issuing p's mma
            unsigned bh[2][4], bl[2][4];
            ldm4(bh[0][0], bh[0][1], bh[0][2], bh[0][3], (base + BH_OFF + b_base) ^ kx);
            ldm4(bl[0][0], bl[0][1], bl[0][2], bl[0][3], (base + BL_OFF + b_base) ^ kx);
#pragma unroll
            for (int p = 0; p < 4; p++) {
                int cur = p & 1, nxt = cur ^ 1;
                if (p < 3) {
                    ldm4(bh[nxt][0], bh[nxt][1], bh[nxt][2], bh[nxt][3],
                         (base + BH_OFF + b_base + (p + 1) * 1024) ^ kx);
                    ldm4(bl[nxt][0], bl[nxt][1], bl[nxt][2], bl[nxt][3],
                         (base + BL_OFF + b_base + (p + 1) * 1024) ^ kx);
                }
#pragma unroll
                for (int q = 0; q < 2; q++) {
                    int nt = p * 2 + q;
#pragma unroll
                    for (int mt = 0; mt < 2; mt++) {
                        mma16816(acc[mt][nt], ah[mt], bh[cur][q * 2], bh[cur][q * 2 + 1]);
                        mma16816(acc[mt][nt], ah[mt], bl[cur][q * 2], bl[cur][q * 2 + 1]);
                        mma16816(acc[mt][nt], al[mt], bh[cur][q * 2], bh[cur][q * 2 + 1]);
                    }
                }
            }
        }
    }

    // ---- epilogue: store h + fused attention dots ----
    int head = blockIdx.y * 2 + warp_n;
    float pa[4] = {0, 0, 0, 0}, pd[4] = {0, 0, 0, 0};
#pragma unroll
    for (int nt = 0; nt < 8; nt++) {
        int cc = col0 + warp_n * 64 + nt * 8 + (lane & 3) * 2;
        float s0 = __ldg(&asw[cc]), s1 = __ldg(&asw[cc + 1]);
        float t0 = __ldg(&adw[cc]), t1 = __ldg(&adw[cc + 1]);
#pragma unroll
        for (int mt = 0; mt < 2; mt++) {
            float* a = acc[mt][nt];
            pa[mt * 2]     += a[0] * s0 + a[1] * s1;
            pa[mt * 2 + 1] += a[2] * s0 + a[3] * s1;
            pd[mt * 2]     += a[0] * t0 + a[1] * t1;
            pd[mt * 2 + 1] += a[2] * t0 + a[3] * t1;
            int rr = row0 + warp_m * 32 + mt * 16 + (lane >> 2);
            if (rr < NN)     *(float2*)&out[(size_t)rr * HC + cc]       = make_float2(a[0], a[1]);
            if (rr + 8 < NN) *(float2*)&out[(size_t)(rr + 8) * HC + cc] = make_float2(a[2], a[3]);
        }
    }
#pragma unroll
    for (int s = 0; s < 4; s++) {
        pa[s] += __shfl_xor_sync(0xffffffffu, pa[s], 1);
        pa[s] += __shfl_xor_sync(0xffffffffu, pa[s], 2);
        pd[s] += __shfl_xor_sync(0xffffffffu, pd[s], 1);
        pd[s] += __shfl_xor_sync(0xffffffffu, pd[s], 2);
    }
    if ((lane & 3) == 0) {
#pragma unroll
        for (int s = 0; s < 4; s++) {
            int rr = row0 + warp_m * 32 + (s >> 1) * 16 + (s & 1) * 8 + (lane >> 2);
            if (rr < NN) {
                d_as[rr * 4 + head] = pa[s];
                d_ad[rr * 4 + head] = pd[s];
            }
        }
    }
}

__device__ __forceinline__ float lrelu(float v) { return v > 0.f ? v : 0.2f * v; }

// ---------------- softmax stats + unnormalized alpha: warp per node ----------------
__global__ void k_attmax() {
    int n = (blockIdx.x * blockDim.x + threadIdx.x) >> 5;
    int lane = threadIdx.x & 31;
    if (n >= NN) return;
    int beg = d_off[n], end = d_off[n + 1];
    float4 ad4 = *(const float4*)&d_ad[n * 4];
    float adv[4] = {ad4.x, ad4.y, ad4.z, ad4.w};

    float mx[4] = {-FLT_MAX, -FLT_MAX, -FLT_MAX, -FLT_MAX};
    for (int j = beg + lane; j < end; j += 32) {
        int s = d_csr_src[j];
        float4 a4 = *(const float4*)&d_as[s * 4];
        mx[0] = fmaxf(mx[0], lrelu(a4.x + adv[0]));
        mx[1] = fmaxf(mx[1], lrelu(a4.y + adv[1]));
        mx[2] = fmaxf(mx[2], lrelu(a4.z + adv[2]));
        mx[3] = fmaxf(mx[3], lrelu(a4.w + adv[3]));
    }
#pragma unroll
    for (int hh = 0; hh < 4; hh++)
#pragma unroll
        for (int o = 16; o > 0; o >>= 1)
            mx[hh] = fmaxf(mx[hh], __shfl_xor_sync(0xffffffffu, mx[hh], o));

    float sm[4] = {0, 0, 0, 0};
    for (int j = beg + lane; j < end; j += 32) {
        int s = d_csr_src[j];
        float4 a4 = *(const float4*)&d_as[s * 4];
        float4 p;
        p.x = __expf(lrelu(a4.x + adv[0]) - mx[0]);
        p.y = __expf(lrelu(a4.y + adv[1]) - mx[1]);
        p.z = __expf(lrelu(a4.z + adv[2]) - mx[2]);
        p.w = __expf(lrelu(a4.w + adv[3]) - mx[3]);
        sm[0] += p.x; sm[1] += p.y; sm[2] += p.z; sm[3] += p.w;
        *(float4*)&d_alpha[(size_t)j * 4] = p;
    }
#pragma unroll
    for (int hh = 0; hh < 4; hh++)
#pragma unroll
        for (int o = 16; o > 0; o >>= 1)
            sm[hh] += __shfl_xor_sync(0xffffffffu, sm[hh], o);

    if (lane == 0)
        *(float4*)&d_rs[n * 4] = make_float4(1.f / sm[0], 1.f / sm[1], 1.f / sm[2], 1.f / sm[3]);
}

// ---------------- weighted aggregation: 2 warps per node ----------------
__global__ void k_agg2(const float* __restrict__ h, const float* __restrict__ bias,
                       __nv_bfloat16* __restrict__ oh, __nv_bfloat16* __restrict__ ol) {
    int gw = (blockIdx.x * blockDim.x + threadIdx.x) >> 5;
    int lane = threadIdx.x & 31;
    int n = gw >> 1, half = gw & 1;
    if (n >= NN) return;
    int beg = d_off[n], end = d_off[n + 1];
    int cbase = half * 128;

    float acc[4] = {0, 0, 0, 0};
    int j = beg;
    for (; j + 2 <= end; j += 2) {
        int s0 = d_csr_src[j], s1 = d_csr_src[j + 1];
        float4 w40 = *(const float4*)&d_alpha[(size_t)j * 4];
        float4 w41 = *(const float4*)&d_alpha[(size_t)(j + 1) * 4];
        float wa0 = half ? w40.z : w40.x, wb0 = half ? w40.w : w40.y;
        float wa1 = half ? w41.z : w41.x, wb1 = half ? w41.w : w41.y;
        const float* h0 = &h[(size_t)s0 * HC + cbase];
        const float* h1 = &h[(size_t)s1 * HC + cbase];
        acc[0] += wa0 * h0[lane]       + wa1 * h1[lane];
        acc[1] += wa0 * h0[lane + 32]  + wa1 * h1[lane + 32];
        acc[2] += wb0 * h0[lane + 64]  + wb1 * h1[lane + 64];
        acc[3] += wb0 * h0[lane + 96]  + wb1 * h1[lane + 96];
    }
    for (; j < end; j++) {
        int s = d_csr_src[j];
        float4 w4 = *(const float4*)&d_alpha[(size_t)j * 4];
        float wa = half ? w4.z : w4.x;
        float wb = half ? w4.w : w4.y;
        const float* hr = &h[(size_t)s * HC + cbase];
        acc[0] += wa * hr[lane];
        acc[1] += wa * hr[lane + 32];
        acc[2] += wb * hr[lane + 64];
        acc[3] += wb * hr[lane + 96];
    }
    float4 r4 = *(const float4*)&d_rs[n * 4];
    float rsa = half ? r4.z : r4.x;
    float rsb = half ? r4.w : r4.y;
#pragma unroll
    for (int i = 0; i < 4; i++) {
        int col = cbase + i * 32 + lane;
        float v = acc[i] * (i < 2 ? rsa : rsb) + bias[col];
        v = v > 0.f ? v : 0.f;
        __nv_bfloat16 hv = __float2bfloat16(v);
        oh[(size_t)n * HC + col] = hv;
        ol[(size_t)n * HC + col] = __float2bfloat16(v - __bfloat162float(hv));
    }
}

// ---------------- graph pooling ----------------
__global__ void k_pool() {
    int g = blockIdx.x;
    int col = blockIdx.y * 128 + threadIdx.x;
    if (col >= GFD) return;
    const __nv_bfloat16 *bh, *bl; int stride, c;
    if (col < 64)       { bh = d_n0h; bl = d_n0l; stride = 64;  c = col; }
    else if (col < 320) { bh = d_x1h; bl = d_x1l; stride = 256; c = col - 64; }
    else if (col < 576) { bh = d_x2h; bl = d_x2l; stride = 256; c = col - 320; }
    else                { bh = d_x3h; bl = d_x3l; stride = 256; c = col - 576; }
    int s = d_gstart[g], e = d_gend[g];
    float v = -FLT_MAX;
    int i = s;
    for (; i + 4 <= e; i += 4) {
        float v0 = (float)bh[(i + 0) * stride + c] + (float)bl[(i + 0) * stride + c];
        float v1 = (float)bh[(i + 1) * stride + c] + (float)bl[(i + 1) * stride + c];
        float v2 = (float)bh[(i + 2) * stride + c] + (float)bl[(i + 2) * stride + c];
        float v3 = (float)bh[(i + 3) * stride + c] + (float)bl[(i + 3) * stride + c];
        v = fmaxf(v, fmaxf(fmaxf(v0, v1), fmaxf(v2, v3)));
    }
    for (; i < e; i++)
        v = fmaxf(v, (float)bh[i * stride + c] + (float)bl[i * stride + c]);
    d_gfeat[g * GFD + col] = v;
}

// ---------------- head MLPs ----------------
__global__ void k_latent(const float* __restrict__ W, const float* __restrict__ b) {
    __shared__ float gs[GFD];
    int g = blockIdx.x, t = threadIdx.x;
    for (int i = t; i < GFD; i += 256) gs[i] = d_gfeat[g * GFD + i];
    __syncthreads();
    float acc = b[t];
    for (int k = 0; k < GFD; k++) acc += gs[k] * W[k * LATD + t];
    d_lat[g * LATD + t] = acc;
}

__global__ void k_heads(const float* __restrict__ muW, const float* __restrict__ mub,
                        const float* __restrict__ vW, const float* __restrict__ vb,
                        float* __restrict__ out) {
    __shared__ float ls[LATD];
    int g = blockIdx.x, t = threadIdx.x;
    ls[t] = d_lat[g * LATD + t];
    __syncthreads();
    float am = mub[t], av = vb[t];
    for (int k = 0; k < LATD; k++) {
        float lv = ls[k];
        am += lv * muW[k * LATD + t];
        av += lv * vW[k * LATD + t];
    }
    out[g * LATD + t] = am;
    out[GG * LATD + g * LATD + t] = av;
}

// ---------------- launch ----------------
extern "C" void kernel_launch(void* const* d_in, const int* in_sizes, int n_in,
                              void* d_out, int out_size) {
    const float* bf   = (const float*)d_in[0];
    const int*   ei   = (const int*)  d_in[1];
    const int*   batch= (const int*)  d_in[2];
    const float* bfW  = (const float*)d_in[3];
    const float* bfb  = (const float*)d_in[4];
    const float* W1   = (const float*)d_in[5];
    const float* as1  = (const float*)d_in[6];
    const float* ad1  = (const float*)d_in[7];
    const float* b1   = (const float*)d_in[8];
    const float* W2   = (const float*)d_in[9];
    const float* as2  = (const float*)d_in[10];
    const float* ad2  = (const float*)d_in[11];
    const float* b2   = (const float*)d_in[12];
    const float* W3   = (const float*)d_in[13];
    const float* as3  = (const float*)d_in[14];
    const float* ad3  = (const float*)d_in[15];
    const float* b3   = (const float*)d_in[16];
    const float* aggW = (const float*)d_in[17];
    const float* aggb = (const float*)d_in[18];
    const float* muW  = (const float*)d_in[19];
    const float* mub  = (const float*)d_in[20];
    const float* vW   = (const float*)d_in[21];
    const float* vb   = (const float*)d_in[22];
    float* out = (float*)d_out;

    __nv_bfloat16 *p_n0h, *p_n0l, *p_x1h, *p_x1l, *p_x2h, *p_x2l, *p_x3h, *p_x3l, *p_wth, *p_wtl;
    float *p_h;
    cudaGetSymbolAddress((void**)&p_n0h, d_n0h);
    cudaGetSymbolAddress((void**)&p_n0l, d_n0l);
    cudaGetSymbolAddress((void**)&p_x1h, d_x1h);
    cudaGetSymbolAddress((void**)&p_x1l, d_x1l);
    cudaGetSymbolAddress((void**)&p_x2h, d_x2h);
    cudaGetSymbolAddress((void**)&p_x2l, d_x2l);
    cudaGetSymbolAddress((void**)&p_x3h, d_x3h);
    cudaGetSymbolAddress((void**)&p_x3l, d_x3l);
    cudaGetSymbolAddress((void**)&p_wth, d_wth);
    cudaGetSymbolAddress((void**)&p_wtl, d_wtl);
    cudaGetSymbolAddress((void**)&p_h,   d_h);

    static bool attr_done = false;
    if (!attr_done) {
        cudaFuncSetAttribute(k_gemm, cudaFuncAttributeMaxDynamicSharedMemorySize, SMEM_BYTES);
        attr_done = true;
    }

    const int T = 256;
    dim3 ggrid((NN + 127) / 128, 2);
    int wgrid = (NN + 7) / 8;                 // warp-per-node
    int agrid = (2 * NN + 7) / 8;             // 2 warps per node
    int egrid = (EL + T - 1) / T;

    k_proj  <<<(NN * FD + T - 1) / T, T>>>(bf, bfW, bfb);
    k_cvt_wt<<<(FD * HC + T - 1) / T, T>>>(W1, p_wth, p_wtl, FD);
    k_init  <<<(NN + T - 1) / T, T>>>();
    k_gemm  <<<ggrid, 256, SMEM_BYTES>>>(p_n0h, p_n0l, p_wth, p_wtl, as1, ad1, p_h, FD);

    // CSR build
    k_deg    <<<egrid, T>>>(ei);
    k_scan1  <<<NB1, SCAN_B>>>();
    k_scan2  <<<1, 32>>>();
    k_scan3  <<<(NN + T - 1) / T, T>>>();
    k_scatter<<<egrid, T>>>(ei);
    k_bounds <<<(NN + T - 1) / T, T>>>(batch);

    k_cvt_wt<<<(HC * HC + T - 1) / T, T>>>(W2, p_wth + HC * HC,     p_wtl + HC * HC,     HC);
    k_cvt_wt<<<(HC * HC + T - 1) / T, T>>>(W3, p_wth + 2 * HC * HC, p_wtl + 2 * HC * HC, HC);

    // layer 1 aggregate
    k_attmax<<<wgrid, 256>>>();
    k_agg2  <<<agrid, 256>>>(p_h, b1, p_x1h, p_x1l);
    // layer 2
    k_gemm  <<<ggrid, 256, SMEM_BYTES>>>(p_x1h, p_x1l, p_wth + HC * HC, p_wtl + HC * HC, as2, ad2, p_h, HC);
    k_attmax<<<wgrid, 256>>>();
    k_agg2  <<<agrid, 256>>>(p_h, b2, p_x2h, p_x2l);
    // layer 3
    k_gemm  <<<ggrid, 256, SMEM_BYTES>>>(p_x2h, p_x2l, p_wth + 2 * HC * HC, p_wtl + 2 * HC * HC, as3, ad3, p_h, HC);
    k_attmax<<<wgrid, 256>>>();
    k_agg2  <<<agrid, 256>>>(p_h, b3, p_x3h, p_x3l);

    // pooling + heads
    dim3 pgrid(GG, (GFD + 127) / 128);
    k_pool  <<<pgrid, 128>>>();
    k_latent<<<GG, 256>>>(aggW, aggb);
    k_heads <<<GG, 256>>>(muW, mub, vW, vb, out);
}

// round 8
// speedup vs baseline: 1.9317x; 1.2960x over previous
#include <cuda_runtime.h>
#include <cuda_fp16.h>
#include <math.h>
#include <float.h>

#define NN 50000
#define EE 300000
#define EL (EE + NN)
#define GG 64
#define FD 64
#define NH 4
#define HC 256
#define LATD 256
#define GFD 832
#define SCAN_B 1024
#define NB1 ((NN + SCAN_B - 1) / SCAN_B)   // 49

// GEMM smem: 64B rows, XOR swizzle, 3 stages, single fp16 plane
#define A_OFF 0
#define B_OFF 8192
#define STAGE 16384
#define SMEM_BYTES (3 * STAGE)

// ---------------- device scratch ----------------
__device__ __half d_n0[NN * FD];
__device__ __half d_x1[NN * HC];
__device__ __half d_x2[NN * HC];
__device__ __half d_x3[NN * HC];
__device__ __half d_wt[3 * HC * HC];
__device__ __half d_h [NN * HC];
__device__ float d_as[NN * NH];
__device__ float d_ad[NN * NH];
__device__ float d_rs[NN * NH];
__device__ float d_alpha[(size_t)EL * NH];
__device__ int   d_deg[NN];
__device__ int   d_off[NN + 1];
__device__ int   d_cur[NN];
__device__ int   d_csr_src[EL];
__device__ int   d_bsum[NB1 + 1];
__device__ int   d_gstart[GG];
__device__ int   d_gend[GG];
__device__ float d_gfeat[GG * GFD];
__device__ float d_lat[GG * LATD];

// ---------------- CSR build ----------------
__global__ void k_init() {
    int i = blockIdx.x * blockDim.x + threadIdx.x;
    if (i < NN) d_deg[i] = 0;
    if (i < GG) { d_gstart[i] = NN; d_gend[i] = 0; }
    if (i == 0) d_off[0] = 0;
}

__global__ void k_deg(const int* __restrict__ ei) {
    int i = blockIdx.x * blockDim.x + threadIdx.x;
    if (i >= EL) return;
    int dst = (i < EE) ? ei[EE + i] : (i - EE);
    atomicAdd(&d_deg[dst], 1);
}

__global__ void k_scan1() {
    __shared__ int sm[SCAN_B];
    int tid = threadIdx.x;
    int i = blockIdx.x * SCAN_B + tid;
    int v = (i < NN) ? d_deg[i] : 0;
    sm[tid] = v;
    __syncthreads();
    for (int d = 1; d < SCAN_B; d <<= 1) {
        int t = 0;
        if (tid >= d) t = sm[tid - d];
        __syncthreads();
        sm[tid] += t;
        __syncthreads();
    }
    if (i < NN) d_off[i + 1] = sm[tid];
    if (tid == SCAN_B - 1) d_bsum[blockIdx.x] = sm[tid];
}

__global__ void k_scan2() {
    int lane = threadIdx.x;
    int a = (lane < NB1) ? d_bsum[lane] : 0;
    int b = (lane + 32 < NB1) ? d_bsum[lane + 32] : 0;
    int ia = a;
#pragma unroll
    for (int o = 1; o < 32; o <<= 1) {
        int t = __shfl_up_sync(0xffffffffu, ia, o);
        if (lane >= o) ia += t;
    }
    int tot0 = __shfl_sync(0xffffffffu, ia, 31);
    int ib = b;
#pragma unroll
    for (int o = 1; o < 32; o <<= 1) {
        int t = __shfl_up_sync(0xffffffffu, ib, o);
        if (lane >= o) ib += t;
    }
    if (lane < NB1) d_bsum[lane] = ia - a;
    if (lane + 32 < NB1) d_bsum[lane + 32] = tot0 + ib - b;
}

__global__ void k_scan3() {
    int i = blockIdx.x * blockDim.x + threadIdx.x;
    if (i >= NN) return;
    int val = d_off[i + 1] + d_bsum[i >> 10];
    d_off[i + 1] = val;
    if (i + 1 < NN) d_cur[i + 1] = val;
    if (i == 0) d_cur[0] = 0;
}

__global__ void k_scatter(const int* __restrict__ ei) {
    int i = blockIdx.x * blockDim.x + threadIdx.x;
    if (i >= EL) return;
    int src, dst;
    if (i < EE) { src = ei[i]; dst = ei[EE + i]; }
    else        { src = i - EE; dst = i - EE; }
    int pos = atomicAdd(&d_cur[dst], 1);
    d_csr_src[pos] = src;
}

__global__ void k_bounds(const int* __restrict__ batch) {
    int i = blockIdx.x * blockDim.x + threadIdx.x;
    if (i >= NN) return;
    int b = batch[i];
    atomicMin(&d_gstart[b], i);
    atomicMax(&d_gend[b], i + 1);
}

// ---------------- weight convert: W[K,256] fp32 -> Wt[256,K] fp16 ----------------
__global__ void k_cvt_wt(const float* __restrict__ W, __half* __restrict__ wt, int K) {
    int i = blockIdx.x * blockDim.x + threadIdx.x;
    if (i >= K * HC) return;
    int k = i / HC, n = i % HC;
    wt[n * K + k] = __float2half(W[i]);
}

// ---------------- input projection ----------------
__global__ void k_proj(const float* __restrict__ bf, const float* __restrict__ W,
                       const float* __restrict__ b) {
    int t = blockIdx.x * blockDim.x + threadIdx.x;
    if (t >= NN * FD) return;
    int n = t >> 6, f = t & 63;
    const float* r = &bf[n * 5];
    float acc = b[f];
    acc += r[0] * W[0 * FD + f];
    acc += r[1] * W[1 * FD + f];
    acc += r[2] * W[2 * FD + f];
    acc += r[3] * W[3 * FD + f];
    acc += r[4] * W[4 * FD + f];
    acc = acc > 0.f ? acc : 0.f;
    d_n0[t] = __float2half(acc);
}

// ---------------- fp16 tensor-core GEMM + fused attention dots ----------------
__device__ __forceinline__ void mma16816(float* d, const unsigned* a, unsigned b0, unsigned b1) {
    asm volatile(
        "mma.sync.aligned.m16n8k16.row.col.f32.f16.f16.f32 "
        "{%0,%1,%2,%3}, {%4,%5,%6,%7}, {%8,%9}, {%0,%1,%2,%3};\n"
        : "+f"(d[0]), "+f"(d[1]), "+f"(d[2]), "+f"(d[3])
        : "r"(a[0]), "r"(a[1]), "r"(a[2]), "r"(a[3]), "r"(b0), "r"(b1));
}

__device__ __forceinline__ void ldm4(unsigned& r0, unsigned& r1, unsigned& r2, unsigned& r3,
                                     unsigned addr) {
    asm volatile("ldmatrix.sync.aligned.m8n8.x4.shared.b16 {%0,%1,%2,%3}, [%4];\n"
                 : "=r"(r0), "=r"(r1), "=r"(r2), "=r"(r3) : "r"(addr));
}

#define CPA(dst, src) asm volatile("cp.async.cg.shared.global [%0], [%1], 16;\n" :: "r"(dst), "l"(src))

extern __shared__ char smem_raw[];

__global__ void __launch_bounds__(256, 2) k_gemm(
    const __half* __restrict__ x, const __half* __restrict__ w,
    const float* __restrict__ asw, const float* __restrict__ adw,
    __half* __restrict__ out, int K)
{
    unsigned sbase;
    asm("{ .reg .u64 t; cvta.to.shared.u64 t, %1; cvt.u32.u64 %0, t; }"
        : "=r"(sbase) : "l"(smem_raw));
    int tid = threadIdx.x, lane = tid & 31, wid = tid >> 5;
    int warp_m = wid & 3, warp_n = wid >> 2;
    int row0 = blockIdx.x * 128, col0 = blockIdx.y * 128;

    int lrow = tid >> 2;              // loader row 0..63
    unsigned lseg = tid & 3;          // logical 16B segment
    int nch = K >> 5;

    // swizzled fragment base offsets (ko=0); ko=1 -> XOR 32
    int a_row = warp_m * 32 + (lane & 15);
    unsigned a_base = (unsigned)(a_row * 64) + ((((lane >> 4) ^ ((a_row >> 1) & 3)) & 3u) << 4);
    int b_row = warp_n * 64 + ((lane >> 4) << 3) + (lane & 7);
    unsigned b_base = (unsigned)(b_row * 64) + (((((lane >> 3) & 1) ^ ((b_row >> 1) & 3)) & 3u) << 4);

    float acc[2][8][4];
#pragma unroll
    for (int mt = 0; mt < 2; mt++)
#pragma unroll
        for (int nt = 0; nt < 8; nt++)
#pragma unroll
            for (int i = 0; i < 4; i++) acc[mt][nt][i] = 0.f;

    auto load_chunk = [&](int c) {
        unsigned sb = sbase + (unsigned)((c % 3) * STAGE);
        int k0 = c << 5;
#pragma unroll
        for (int half_ = 0; half_ < 2; half_++) {
            int r = lrow + half_ * 64;
            unsigned phys = (lseg ^ ((unsigned)(r >> 1) & 3u)) << 4;
            unsigned so = (unsigned)(r * 64) + phys;
            unsigned gofs = lseg * 16;
            int gr = row0 + r;
            if (gr < NN) {
                CPA(sb + A_OFF + so, (const char*)x + ((size_t)gr * K + k0) * 2 + gofs);
            } else {
                asm volatile("st.shared.v4.b32 [%0], {%1,%1,%1,%1};" :: "r"(sb + A_OFF + so), "r"(0u));
            }
            int gc = col0 + r;
            CPA(sb + B_OFF + so, (const char*)w + ((size_t)gc * K + k0) * 2 + gofs);
        }
        asm volatile("cp.async.commit_group;\n");
    };

    load_chunk(0);
    load_chunk(1);
    for (int c = 0; c < nch; c++) {
        if (c < nch - 1) asm volatile("cp.async.wait_group 1;\n");
        else             asm volatile("cp.async.wait_group 0;\n");
        __syncthreads();
        if (c + 2 < nch) load_chunk(c + 2);

        unsigned base = sbase + (unsigned)((c % 3) * STAGE);
#pragma unroll
        for (int ko = 0; ko < 2; ko++) {
            unsigned kx = (unsigned)(ko << 5);
            unsigned ah[2][4];
#pragma unroll
            for (int mt = 0; mt < 2; mt++)
                ldm4(ah[mt][0], ah[mt][1], ah[mt][2], ah[mt][3],
                     (base + A_OFF + a_base + mt * 1024) ^ kx);
            // B double buffer across the 4 n-subtiles
            unsigned bh[2][4];
            ldm4(bh[0][0], bh[0][1], bh[0][2], bh[0][3], (base + B_OFF + b_base) ^ kx);
#pragma unroll
            for (int p = 0; p < 4; p++) {
                int cur = p & 1, nxt = cur ^ 1;
                if (p < 3)
                    ldm4(bh[nxt][0], bh[nxt][1], bh[nxt][2], bh[nxt][3],
                         (base + B_OFF + b_base + (p + 1) * 1024) ^ kx);
#pragma unroll
                for (int q = 0; q < 2; q++) {
                    int nt = p * 2 + q;
#pragma unroll
                    for (int mt = 0; mt < 2; mt++)
                        mma16816(acc[mt][nt], ah[mt], bh[cur][q * 2], bh[cur][q * 2 + 1]);
                }
            }
        }
    }

    // ---- epilogue: store h (fp16) + fused attention dots (fp32) ----
    int head = blockIdx.y * 2 + warp_n;
    float pa[4] = {0, 0, 0, 0}, pd[4] = {0, 0, 0, 0};
#pragma unroll
    for (int nt = 0; nt < 8; nt++) {
        int cc = col0 + warp_n * 64 + nt * 8 + (lane & 3) * 2;
        float s0 = __ldg(&asw[cc]), s1 = __ldg(&asw[cc + 1]);
        float t0 = __ldg(&adw[cc]), t1 = __ldg(&adw[cc + 1]);
#pragma unroll
        for (int mt = 0; mt < 2; mt++) {
            float* a = acc[mt][nt];
            pa[mt * 2]     += a[0] * s0 + a[1] * s1;
            pa[mt * 2 + 1] += a[2] * s0 + a[3] * s1;
            pd[mt * 2]     += a[0] * t0 + a[1] * t1;
            pd[mt * 2 + 1] += a[2] * t0 + a[3] * t1;
            int rr = row0 + warp_m * 32 + mt * 16 + (lane >> 2);
            if (rr < NN)
                *(__half2*)&out[(size_t)rr * HC + cc] = __floats2half2_rn(a[0], a[1]);
            if (rr + 8 < NN)
                *(__half2*)&out[(size_t)(rr + 8) * HC + cc] = __floats2half2_rn(a[2], a[3]);
        }
    }
#pragma unroll
    for (int s = 0; s < 4; s++) {
        pa[s] += __shfl_xor_sync(0xffffffffu, pa[s], 1);
        pa[s] += __shfl_xor_sync(0xffffffffu, pa[s], 2);
        pd[s] += __shfl_xor_sync(0xffffffffu, pd[s], 1);
        pd[s] += __shfl_xor_sync(0xffffffffu, pd[s], 2);
    }
    if ((lane & 3) == 0) {
#pragma unroll
        for (int s = 0; s < 4; s++) {
            int rr = row0 + warp_m * 32 + (s >> 1) * 16 + (s & 1) * 8 + (lane >> 2);
            if (rr < NN) {
                d_as[rr * 4 + head] = pa[s];
                d_ad[rr * 4 + head] = pd[s];
            }
        }
    }
}

__device__ __forceinline__ float lrelu(float v) { return v > 0.f ? v : 0.2f * v; }

// ---------------- softmax stats + unnormalized alpha: warp per node ----------------
__global__ void k_attmax() {
    int n = (blockIdx.x * blockDim.x + threadIdx.x) >> 5;
    int lane = threadIdx.x & 31;
    if (n >= NN) return;
    int beg = d_off[n], end = d_off[n + 1];
    float4 ad4 = *(const float4*)&d_ad[n * 4];
    float adv[4] = {ad4.x, ad4.y, ad4.z, ad4.w};

    float mx[4] = {-FLT_MAX, -FLT_MAX, -FLT_MAX, -FLT_MAX};
    for (int j = beg + lane; j < end; j += 32) {
        int s = d_csr_src[j];
        float4 a4 = *(const float4*)&d_as[s * 4];
        mx[0] = fmaxf(mx[0], lrelu(a4.x + adv[0]));
        mx[1] = fmaxf(mx[1], lrelu(a4.y + adv[1]));
        mx[2] = fmaxf(mx[2], lrelu(a4.z + adv[2]));
        mx[3] = fmaxf(mx[3], lrelu(a4.w + adv[3]));
    }
#pragma unroll
    for (int hh = 0; hh < 4; hh++)
#pragma unroll
        for (int o = 16; o > 0; o >>= 1)
            mx[hh] = fmaxf(mx[hh], __shfl_xor_sync(0xffffffffu, mx[hh], o));

    float sm[4] = {0, 0, 0, 0};
    for (int j = beg + lane; j < end; j += 32) {
        int s = d_csr_src[j];
        float4 a4 = *(const float4*)&d_as[s * 4];
        float4 p;
        p.x = __expf(lrelu(a4.x + adv[0]) - mx[0]);
        p.y = __expf(lrelu(a4.y + adv[1]) - mx[1]);
        p.z = __expf(lrelu(a4.z + adv[2]) - mx[2]);
        p.w = __expf(lrelu(a4.w + adv[3]) - mx[3]);
        sm[0] += p.x; sm[1] += p.y; sm[2] += p.z; sm[3] += p.w;
        *(float4*)&d_alpha[(size_t)j * 4] = p;
    }
#pragma unroll
    for (int hh = 0; hh < 4; hh++)
#pragma unroll
        for (int o = 16; o > 0; o >>= 1)
            sm[hh] += __shfl_xor_sync(0xffffffffu, sm[hh], o);

    if (lane == 0)
        *(float4*)&d_rs[n * 4] = make_float4(1.f / sm[0], 1.f / sm[1], 1.f / sm[2], 1.f / sm[3]);
}

// ---------------- weighted aggregation: 2 warps per node, fp16 h ----------------
__global__ void k_agg2(const __half* __restrict__ h, const float* __restrict__ bias,
                       __half* __restrict__ ox) {
    int gw = (blockIdx.x * blockDim.x + threadIdx.x) >> 5;
    int lane = threadIdx.x & 31;
    int n = gw >> 1, half_ = gw & 1;
    if (n >= NN) return;
    int beg = d_off[n], end = d_off[n + 1];
    int cb2 = half_ * 64;              // half2 index base

    float2 acc0 = make_float2(0.f, 0.f), acc1 = make_float2(0.f, 0.f);
    int j = beg;
    for (; j + 2 <= end; j += 2) {
        int s0 = d_csr_src[j], s1 = d_csr_src[j + 1];
        float4 w40 = *(const float4*)&d_alpha[(size_t)j * 4];
        float4 w41 = *(const float4*)&d_alpha[(size_t)(j + 1) * 4];
        float wa0 = half_ ? w40.z : w40.x, wb0 = half_ ? w40.w : w40.y;
        float wa1 = half_ ? w41.z : w41.x, wb1 = half_ ? w41.w : w41.y;
        const __half2* p0 = (const __half2*)&h[(size_t)s0 * HC] + cb2;
        const __half2* p1 = (const __half2*)&h[(size_t)s1 * HC] + cb2;
        float2 a0 = __half22float2(p0[lane]);
        float2 b0 = __half22float2(p0[lane + 32]);
        float2 a1 = __half22float2(p1[lane]);
        float2 b1 = __half22float2(p1[lane + 32]);
        acc0.x += wa0 * a0.x + wa1 * a1.x;
        acc0.y += wa0 * a0.y + wa1 * a1.y;
        acc1.x += wb0 * b0.x + wb1 * b1.x;
        acc1.y += wb0 * b0.y + wb1 * b1.y;
    }
    for (; j < end; j++) {
        int s = d_csr_src[j];
        float4 w4 = *(const float4*)&d_alpha[(size_t)j * 4];
        float wa = half_ ? w4.z : w4.x;
        float wb = half_ ? w4.w : w4.y;
        const __half2* p = (const __half2*)&h[(size_t)s * HC] + cb2;
        float2 a = __half22float2(p[lane]);
        float2 b = __half22float2(p[lane + 32]);
        acc0.x += wa * a.x; acc0.y += wa * a.y;
        acc1.x += wb * b.x; acc1.y += wb * b.y;
    }
    float4 r4 = *(const float4*)&d_rs[n * 4];
    float rsa = half_ ? r4.z : r4.x;
    float rsb = half_ ? r4.w : r4.y;
    int c0 = half_ * 128 + 2 * lane;
    int c1 = c0 + 64;
    float v0 = acc0.x * rsa + bias[c0],     v1 = acc0.y * rsa + bias[c0 + 1];
    float v2 = acc1.x * rsb + bias[c1],     v3 = acc1.y * rsb + bias[c1 + 1];
    v0 = v0 > 0.f ? v0 : 0.f; v1 = v1 > 0.f ? v1 : 0.f;
    v2 = v2 > 0.f ? v2 : 0.f; v3 = v3 > 0.f ? v3 : 0.f;
    *(__half2*)&ox[(size_t)n * HC + c0] = __floats2half2_rn(v0, v1);
    *(__half2*)&ox[(size_t)n * HC + c1] = __floats2half2_rn(v2, v3);
}

// ---------------- graph pooling ----------------
__global__ void k_pool() {
    int g = blockIdx.x;
    int col = blockIdx.y * 128 + threadIdx.x;
    if (col >= GFD) return;
    const __half* bp; int stride, c;
    if (col < 64)       { bp = d_n0; stride = 64;  c = col; }
    else if (col < 320) { bp = d_x1; stride = 256; c = col - 64; }
    else if (col < 576) { bp = d_x2; stride = 256; c = col - 320; }
    else                { bp = d_x3; stride = 256; c = col - 576; }
    int s = d_gstart[g], e = d_gend[g];
    float v = -FLT_MAX;
    int i = s;
    for (; i + 4 <= e; i += 4) {
        float v0 = __half2float(__ldg(&bp[(i + 0) * stride + c]));
        float v1 = __half2float(__ldg(&bp[(i + 1) * stride + c]));
        float v2 = __half2float(__ldg(&bp[(i + 2) * stride + c]));
        float v3 = __half2float(__ldg(&bp[(i + 3) * stride + c]));
        v = fmaxf(v, fmaxf(fmaxf(v0, v1), fmaxf(v2, v3)));
    }
    for (; i < e; i++)
        v = fmaxf(v, __half2float(__ldg(&bp[i * stride + c])));
    d_gfeat[g * GFD + col] = v;
}

// ---------------- head MLPs ----------------
__global__ void k_latent(const float* __restrict__ W, const float* __restrict__ b) {
    __shared__ float gs[GFD];
    int g = blockIdx.x, t = threadIdx.x;
    for (int i = t; i < GFD; i += 256) gs[i] = d_gfeat[g * GFD + i];
    __syncthreads();
    float acc = b[t];
    for (int k = 0; k < GFD; k++) acc += gs[k] * W[k * LATD + t];
    d_lat[g * LATD + t] = acc;
}

__global__ void k_heads(const float* __restrict__ muW, const float* __restrict__ mub,
                        const float* __restrict__ vW, const float* __restrict__ vb,
                        float* __restrict__ out) {
    __shared__ float ls[LATD];
    int g = blockIdx.x, t = threadIdx.x;
    ls[t] = d_lat[g * LATD + t];
    __syncthreads();
    float am = mub[t], av = vb[t];
    for (int k = 0; k < LATD; k++) {
        float lv = ls[k];
        am += lv * muW[k * LATD + t];
        av += lv * vW[k * LATD + t];
    }
    out[g * LATD + t] = am;
    out[GG * LATD + g * LATD + t] = av;
}

// ---------------- launch ----------------
extern "C" void kernel_launch(void* const* d_in, const int* in_sizes, int n_in,
                              void* d_out, int out_size) {
    const float* bf   = (const float*)d_in[0];
    const int*   ei   = (const int*)  d_in[1];
    const int*   batch= (const int*)  d_in[2];
    const float* bfW  = (const float*)d_in[3];
    const float* bfb  = (const float*)d_in[4];
    const float* W1   = (const float*)d_in[5];
    const float* as1  = (const float*)d_in[6];
    const float* ad1  = (const float*)d_in[7];
    const float* b1   = (const float*)d_in[8];
    const float* W2   = (const float*)d_in[9];
    const float* as2  = (const float*)d_in[10];
    const float* ad2  = (const float*)d_in[11];
    const float* b2   = (const float*)d_in[12];
    const float* W3   = (const float*)d_in[13];
    const float* as3  = (const float*)d_in[14];
    const float* ad3  = (const float*)d_in[15];
    const float* b3   = (const float*)d_in[16];
    const float* aggW = (const float*)d_in[17];
    const float* aggb = (const float*)d_in[18];
    const float* muW  = (const float*)d_in[19];
    const float* mub  = (const float*)d_in[20];
    const float* vW   = (const float*)d_in[21];
    const float* vb   = (const float*)d_in[22];
    float* out = (float*)d_out;

    __half *p_n0, *p_x1, *p_x2, *p_x3, *p_wt, *p_h;
    cudaGetSymbolAddress((void**)&p_n0, d_n0);
    cudaGetSymbolAddress((void**)&p_x1, d_x1);
    cudaGetSymbolAddress((void**)&p_x2, d_x2);
    cudaGetSymbolAddress((void**)&p_x3, d_x3);
    cudaGetSymbolAddress((void**)&p_wt, d_wt);
    cudaGetSymbolAddress((void**)&p_h,  d_h);

    static bool attr_done = false;
    if (!attr_done) {
        cudaFuncSetAttribute(k_gemm, cudaFuncAttributeMaxDynamicSharedMemorySize, SMEM_BYTES);
        attr_done = true;
    }

    const int T = 256;
    dim3 ggrid((NN + 127) / 128, 2);
    int wgrid = (NN + 7) / 8;                 // warp-per-node
    int agrid = (2 * NN + 7) / 8;             // 2 warps per node
    int egrid = (EL + T - 1) / T;

    k_proj  <<<(NN * FD + T - 1) / T, T>>>(bf, bfW, bfb);
    k_cvt_wt<<<(FD * HC + T - 1) / T, T>>>(W1, p_wt, FD);
    k_init  <<<(NN + T - 1) / T, T>>>();
    k_gemm  <<<ggrid, 256, SMEM_BYTES>>>(p_n0, p_wt, as1, ad1, p_h, FD);

    // CSR build
    k_deg    <<<egrid, T>>>(ei);
    k_scan1  <<<NB1, SCAN_B>>>();
    k_scan2  <<<1, 32>>>();
    k_scan3  <<<(NN + T - 1) / T, T>>>();
    k_scatter<<<egrid, T>>>(ei);
    k_bounds <<<(NN + T - 1) / T, T>>>(batch);

    k_cvt_wt<<<(HC * HC + T - 1) / T, T>>>(W2, p_wt + HC * HC,     HC);
    k_cvt_wt<<<(HC * HC + T - 1) / T, T>>>(W3, p_wt + 2 * HC * HC, HC);

    // layer 1 aggregate
    k_attmax<<<wgrid, 256>>>();
    k_agg2  <<<agrid, 256>>>(p_h, b1, p_x1);
    // layer 2
    k_gemm  <<<ggrid, 256, SMEM_BYTES>>>(p_x1, p_wt + HC * HC, as2, ad2, p_h, HC);
    k_attmax<<<wgrid, 256>>>();
    k_agg2  <<<agrid, 256>>>(p_h, b2, p_x2);
    // layer 3
    k_gemm  <<<ggrid, 256, SMEM_BYTES>>>(p_x2, p_wt + 2 * HC * HC, as3, ad3, p_h, HC);
    k_attmax<<<wgrid, 256>>>();
    k_agg2  <<<agrid, 256>>>(p_h, b3, p_x3);

    // pooling + heads
    dim3 pgrid(GG, (GFD + 127) / 128);
    k_pool  <<<pgrid, 128>>>();
    k_latent<<<GG, 256>>>(aggW, aggb);
    k_heads <<<GG, 256>>>(muW, mub, vW, vb, out);
}

// round 9
// speedup vs baseline: 2.4887x; 1.2884x over previous
#include <cuda_runtime.h>
#include <cuda_fp16.h>
#include <math.h>
#include <float.h>

#define NN 50000
#define EE 300000
#define EL (EE + NN)
#define GG 64
#define FD 64
#define NH 4
#define HC 256
#define LATD 256
#define GFD 832
#define SCAN_B 1024
#define NB1 ((NN + SCAN_B - 1) / SCAN_B)   // 49

// GEMM smem: 64B rows, XOR swizzle, 3 stages, single fp16 plane
#define A_OFF 0
#define B_OFF 8192
#define STAGE 16384
#define SMEM_BYTES (3 * STAGE)

// ---------------- device scratch ----------------
__device__ __half d_n0[NN * FD];
__device__ __half d_x1[NN * HC];
__device__ __half d_x2[NN * HC];
__device__ __half d_x3[NN * HC];
__device__ __half d_wt[3 * HC * HC];
__device__ __half d_h [NN * HC];
__device__ float d_as[NN * NH];
__device__ float d_ad[NN * NH];
__device__ float d_rs[NN * NH];
__device__ float d_alpha[(size_t)EL * NH];
__device__ int   d_deg[NN];
__device__ int   d_off[NN + 1];
__device__ int   d_cur[NN];
__device__ int   d_csr_src[EL];
__device__ int   d_bsum[NB1 + 1];
__device__ int   d_gstart[GG];
__device__ int   d_gend[GG];
__device__ float d_gfeat[GG * GFD];

// ---------------- CSR build ----------------
__global__ void k_deg(const int* __restrict__ ei) {
    int i = blockIdx.x * blockDim.x + threadIdx.x;
    if (i >= EL) return;
    int dst = (i < EE) ? ei[EE + i] : (i - EE);
    atomicAdd(&d_deg[dst], 1);
}

__global__ void k_scan1() {
    __shared__ int sm[SCAN_B];
    int tid = threadIdx.x;
    int i = blockIdx.x * SCAN_B + tid;
    int v = (i < NN) ? d_deg[i] : 0;
    sm[tid] = v;
    __syncthreads();
    for (int d = 1; d < SCAN_B; d <<= 1) {
        int t = 0;
        if (tid >= d) t = sm[tid - d];
        __syncthreads();
        sm[tid] += t;
        __syncthreads();
    }
    if (i < NN) d_off[i + 1] = sm[tid];
    if (tid == SCAN_B - 1) d_bsum[blockIdx.x] = sm[tid];
}

__global__ void k_scan2() {
    int lane = threadIdx.x;
    int a = (lane < NB1) ? d_bsum[lane] : 0;
    int b = (lane + 32 < NB1) ? d_bsum[lane + 32] : 0;
    int ia = a;
#pragma unroll
    for (int o = 1; o < 32; o <<= 1) {
        int t = __shfl_up_sync(0xffffffffu, ia, o);
        if (lane >= o) ia += t;
    }
    int tot0 = __shfl_sync(0xffffffffu, ia, 31);
    int ib = b;
#pragma unroll
    for (int o = 1; o < 32; o <<= 1) {
        int t = __shfl_up_sync(0xffffffffu, ib, o);
        if (lane >= o) ib += t;
    }
    if (lane < NB1) d_bsum[lane] = ia - a;
    if (lane + 32 < NB1) d_bsum[lane + 32] = tot0 + ib - b;
}

// scan fixup + cursor init + per-graph bounds
__global__ void k_scan3b(const int* __restrict__ batch) {
    int i = blockIdx.x * blockDim.x + threadIdx.x;
    if (i >= NN) return;
    int val = d_off[i + 1] + d_bsum[i >> 10];
    d_off[i + 1] = val;
    if (i + 1 < NN) d_cur[i + 1] = val;
    if (i == 0) d_cur[0] = 0;
    int b = batch[i];
    atomicMin(&d_gstart[b], i);
    atomicMax(&d_gend[b], i + 1);
}

__global__ void k_scatter(const int* __restrict__ ei) {
    int i = blockIdx.x * blockDim.x + threadIdx.x;
    if (i >= EL) return;
    int src, dst;
    if (i < EE) { src = ei[i]; dst = ei[EE + i]; }
    else        { src = i - EE; dst = i - EE; }
    int pos = atomicAdd(&d_cur[dst], 1);
    d_csr_src[pos] = src;
}

// ---------------- all three weight transposes in one kernel ----------------
__global__ void k_cvt_all(const float* __restrict__ W1, const float* __restrict__ W2,
                          const float* __restrict__ W3, __half* __restrict__ wt) {
    int i = blockIdx.x * blockDim.x + threadIdx.x;
    if (i < FD * HC) {
        int k = i / HC, n = i % HC;
        wt[n * FD + k] = __float2half(W1[i]);
    } else if (i < FD * HC + HC * HC) {
        int j = i - FD * HC;
        int k = j / HC, n = j % HC;
        wt[HC * HC + n * HC + k] = __float2half(W2[j]);
    } else if (i < FD * HC + 2 * HC * HC) {
        int j = i - FD * HC - HC * HC;
        int k = j / HC, n = j % HC;
        wt[2 * HC * HC + n * HC + k] = __float2half(W3[j]);
    }
}

// ---------------- input projection ----------------
__global__ void k_proj(const float* __restrict__ bf, const float* __restrict__ W,
                       const float* __restrict__ b) {
    int t = blockIdx.x * blockDim.x + threadIdx.x;
    if (t >= NN * FD) return;
    int n = t >> 6, f = t & 63;
    const float* r = &bf[n * 5];
    float acc = b[f];
    acc += r[0] * W[0 * FD + f];
    acc += r[1] * W[1 * FD + f];
    acc += r[2] * W[2 * FD + f];
    acc += r[3] * W[3 * FD + f];
    acc += r[4] * W[4 * FD + f];
    acc = acc > 0.f ? acc : 0.f;
    d_n0[t] = __float2half(acc);
}

// ---------------- fp16 tensor-core GEMM + fused attention dots ----------------
__device__ __forceinline__ void mma16816(float* d, const unsigned* a, unsigned b0, unsigned b1) {
    asm volatile(
        "mma.sync.aligned.m16n8k16.row.col.f32.f16.f16.f32 "
        "{%0,%1,%2,%3}, {%4,%5,%6,%7}, {%8,%9}, {%0,%1,%2,%3};\n"
        : "+f"(d[0]), "+f"(d[1]), "+f"(d[2]), "+f"(d[3])
        : "r"(a[0]), "r"(a[1]), "r"(a[2]), "r"(a[3]), "r"(b0), "r"(b1));
}

__device__ __forceinline__ void ldm4(unsigned& r0, unsigned& r1, unsigned& r2, unsigned& r3,
                                     unsigned addr) {
    asm volatile("ldmatrix.sync.aligned.m8n8.x4.shared.b16 {%0,%1,%2,%3}, [%4];\n"
                 : "=r"(r0), "=r"(r1), "=r"(r2), "=r"(r3) : "r"(addr));
}

#define CPA(dst, src) asm volatile("cp.async.cg.shared.global [%0], [%1], 16;\n" :: "r"(dst), "l"(src))

extern __shared__ char smem_raw[];

__global__ void __launch_bounds__(256, 2) k_gemm(
    const __half* __restrict__ x, const __half* __restrict__ w,
    const float* __restrict__ asw, const float* __restrict__ adw,
    __half* __restrict__ out, int K)
{
    unsigned sbase;
    asm("{ .reg .u64 t; cvta.to.shared.u64 t, %1; cvt.u32.u64 %0, t; }"
        : "=r"(sbase) : "l"(smem_raw));
    int tid = threadIdx.x, lane = tid & 31, wid = tid >> 5;
    int warp_m = wid & 3, warp_n = wid >> 2;
    int row0 = blockIdx.x * 128, col0 = blockIdx.y * 128;

    int lrow = tid >> 2;
    unsigned lseg = tid & 3;
    int nch = K >> 5;

    int a_row = warp_m * 32 + (lane & 15);
    unsigned a_base = (unsigned)(a_row * 64) + ((((lane >> 4) ^ ((a_row >> 1) & 3)) & 3u) << 4);
    int b_row = warp_n * 64 + ((lane >> 4) << 3) + (lane & 7);
    unsigned b_base = (unsigned)(b_row * 64) + (((((lane >> 3) & 1) ^ ((b_row >> 1) & 3)) & 3u) << 4);

    float acc[2][8][4];
#pragma unroll
    for (int mt = 0; mt < 2; mt++)
#pragma unroll
        for (int nt = 0; nt < 8; nt++)
#pragma unroll
            for (int i = 0; i < 4; i++) acc[mt][nt][i] = 0.f;

    auto load_chunk = [&](int c) {
        unsigned sb = sbase + (unsigned)((c % 3) * STAGE);
        int k0 = c << 5;
#pragma unroll
        for (int half_ = 0; half_ < 2; half_++) {
            int r = lrow + half_ * 64;
            unsigned phys = (lseg ^ ((unsigned)(r >> 1) & 3u)) << 4;
            unsigned so = (unsigned)(r * 64) + phys;
            unsigned gofs = lseg * 16;
            int gr = row0 + r;
            if (gr < NN) {
                CPA(sb + A_OFF + so, (const char*)x + ((size_t)gr * K + k0) * 2 + gofs);
            } else {
                asm volatile("st.shared.v4.b32 [%0], {%1,%1,%1,%1};" :: "r"(sb + A_OFF + so), "r"(0u));
            }
            int gc = col0 + r;
            CPA(sb + B_OFF + so, (const char*)w + ((size_t)gc * K + k0) * 2 + gofs);
        }
        asm volatile("cp.async.commit_group;\n");
    };

    load_chunk(0);
    load_chunk(1);
    for (int c = 0; c < nch; c++) {
        if (c < nch - 1) asm volatile("cp.async.wait_group 1;\n");
        else             asm volatile("cp.async.wait_group 0;\n");
        __syncthreads();
        if (c + 2 < nch) load_chunk(c + 2);

        unsigned base = sbase + (unsigned)((c % 3) * STAGE);
#pragma unroll
        for (int ko = 0; ko < 2; ko++) {
            unsigned kx = (unsigned)(ko << 5);
            unsigned ah[2][4];
#pragma unroll
            for (int mt = 0; mt < 2; mt++)
                ldm4(ah[mt][0], ah[mt][1], ah[mt][2], ah[mt][3],
                     (base + A_OFF + a_base + mt * 1024) ^ kx);
            unsigned bh[2][4];
            ldm4(bh[0][0], bh[0][1], bh[0][2], bh[0][3], (base + B_OFF + b_base) ^ kx);
#pragma unroll
            for (int p = 0; p < 4; p++) {
                int cur = p & 1, nxt = cur ^ 1;
                if (p < 3)
                    ldm4(bh[nxt][0], bh[nxt][1], bh[nxt][2], bh[nxt][3],
                         (base + B_OFF + b_base + (p + 1) * 1024) ^ kx);
#pragma unroll
                for (int q = 0; q < 2; q++) {
                    int nt = p * 2 + q;
#pragma unroll
                    for (int mt = 0; mt < 2; mt++)
                        mma16816(acc[mt][nt], ah[mt], bh[cur][q * 2], bh[cur][q * 2 + 1]);
                }
            }
        }
    }

    // ---- epilogue: store h (fp16) + fused attention dots (fp32) ----
    int head = blockIdx.y * 2 + warp_n;
    float pa[4] = {0, 0, 0, 0}, pd[4] = {0, 0, 0, 0};
#pragma unroll
    for (int nt = 0; nt < 8; nt++) {
        int cc = col0 + warp_n * 64 + nt * 8 + (lane & 3) * 2;
        float s0 = __ldg(&asw[cc]), s1 = __ldg(&asw[cc + 1]);
        float t0 = __ldg(&adw[cc]), t1 = __ldg(&adw[cc + 1]);
#pragma unroll
        for (int mt = 0; mt < 2; mt++) {
            float* a = acc[mt][nt];
            pa[mt * 2]     += a[0] * s0 + a[1] * s1;
            pa[mt * 2 + 1] += a[2] * s0 + a[3] * s1;
            pd[mt * 2]     += a[0] * t0 + a[1] * t1;
            pd[mt * 2 + 1] += a[2] * t0 + a[3] * t1;
            int rr = row0 + warp_m * 32 + mt * 16 + (lane >> 2);
            if (rr < NN)
                *(__half2*)&out[(size_t)rr * HC + cc] = __floats2half2_rn(a[0], a[1]);
            if (rr + 8 < NN)
                *(__half2*)&out[(size_t)(rr + 8) * HC + cc] = __floats2half2_rn(a[2], a[3]);
        }
    }
#pragma unroll
    for (int s = 0; s < 4; s++) {
        pa[s] += __shfl_xor_sync(0xffffffffu, pa[s], 1);
        pa[s] += __shfl_xor_sync(0xffffffffu, pa[s], 2);
        pd[s] += __shfl_xor_sync(0xffffffffu, pd[s], 1);
        pd[s] += __shfl_xor_sync(0xffffffffu, pd[s], 2);
    }
    if ((lane & 3) == 0) {
#pragma unroll
        for (int s = 0; s < 4; s++) {
            int rr = row0 + warp_m * 32 + (s >> 1) * 16 + (s & 1) * 8 + (lane >> 2);
            if (rr < NN) {
                d_as[rr * 4 + head] = pa[s];
                d_ad[rr * 4 + head] = pd[s];
            }
        }
    }
}

__device__ __forceinline__ float lrelu(float v) { return v > 0.f ? v : 0.2f * v; }

// ---------------- softmax stats + unnormalized alpha: warp per node ----------------
__global__ void k_attmax() {
    int n = (blockIdx.x * blockDim.x + threadIdx.x) >> 5;
    int lane = threadIdx.x & 31;
    if (n >= NN) return;
    int beg = d_off[n], end = d_off[n + 1];
    float4 ad4 = *(const float4*)&d_ad[n * 4];
    float adv[4] = {ad4.x, ad4.y, ad4.z, ad4.w};

    float mx[4] = {-FLT_MAX, -FLT_MAX, -FLT_MAX, -FLT_MAX};
    for (int j = beg + lane; j < end; j += 32) {
        int s = d_csr_src[j];
        float4 a4 = *(const float4*)&d_as[s * 4];
        mx[0] = fmaxf(mx[0], lrelu(a4.x + adv[0]));
        mx[1] = fmaxf(mx[1], lrelu(a4.y + adv[1]));
        mx[2] = fmaxf(mx[2], lrelu(a4.z + adv[2]));
        mx[3] = fmaxf(mx[3], lrelu(a4.w + adv[3]));
    }
#pragma unroll
    for (int hh = 0; hh < 4; hh++)
#pragma unroll
        for (int o = 16; o > 0; o >>= 1)
            mx[hh] = fmaxf(mx[hh], __shfl_xor_sync(0xffffffffu, mx[hh], o));

    float sm[4] = {0, 0, 0, 0};
    for (int j = beg + lane; j < end; j += 32) {
        int s = d_csr_src[j];
        float4 a4 = *(const float4*)&d_as[s * 4];
        float4 p;
        p.x = __expf(lrelu(a4.x + adv[0]) - mx[0]);
        p.y = __expf(lrelu(a4.y + adv[1]) - mx[1]);
        p.z = __expf(lrelu(a4.z + adv[2]) - mx[2]);
        p.w = __expf(lrelu(a4.w + adv[3]) - mx[3]);
        sm[0] += p.x; sm[1] += p.y; sm[2] += p.z; sm[3] += p.w;
        *(float4*)&d_alpha[(size_t)j * 4] = p;
    }
#pragma unroll
    for (int hh = 0; hh < 4; hh++)
#pragma unroll
        for (int o = 16; o > 0; o >>= 1)
            sm[hh] += __shfl_xor_sync(0xffffffffu, sm[hh], o);

    if (lane == 0)
        *(float4*)&d_rs[n * 4] = make_float4(1.f / sm[0], 1.f / sm[1], 1.f / sm[2], 1.f / sm[3]);
}

// ---------------- weighted aggregation: 2 warps/node, 16 lanes x 16B per edge ----------------
__global__ void k_agg2(const __half* __restrict__ h, const float* __restrict__ bias,
                       __half* __restrict__ ox) {
    int gw = (blockIdx.x * blockDim.x + threadIdx.x) >> 5;
    int lane = threadIdx.x & 31;
    int n = gw >> 1, half_ = gw & 1;
    if (n >= NN) return;
    int beg = d_off[n], end = d_off[n + 1];
    int eg = lane >> 4;                 // edge group 0/1
    int sub = lane & 15;                // 16B sub-segment of the 256B half-row
    int cb = half_ * 128 + sub * 8;     // first col handled by this lane
    int head = half_ * 2 + (sub >> 3);

    float acc[8] = {0, 0, 0, 0, 0, 0, 0, 0};
#pragma unroll 2
    for (int j = beg + eg; j < end; j += 2) {
        int s = d_csr_src[j];
        float w = d_alpha[(size_t)j * 4 + head];
        uint4 v = __ldg((const uint4*)(h + (size_t)s * HC + cb));
        float2 f0 = __half22float2(*(__half2*)&v.x);
        float2 f1 = __half22float2(*(__half2*)&v.y);
        float2 f2 = __half22float2(*(__half2*)&v.z);
        float2 f3 = __half22float2(*(__half2*)&v.w);
        acc[0] += w * f0.x; acc[1] += w * f0.y;
        acc[2] += w * f1.x; acc[3] += w * f1.y;
        acc[4] += w * f2.x; acc[5] += w * f2.y;
        acc[6] += w * f3.x; acc[7] += w * f3.y;
    }
#pragma unroll
    for (int i = 0; i < 8; i++)
        acc[i] += __shfl_xor_sync(0xffffffffu, acc[i], 16);

    if (eg == 0) {
        float rs = d_rs[n * 4 + head];
        float4 b0 = *(const float4*)&bias[cb];
        float4 b1 = *(const float4*)&bias[cb + 4];
        float o0 = acc[0] * rs + b0.x, o1 = acc[1] * rs + b0.y;
        float o2 = acc[2] * rs + b0.z, o3 = acc[3] * rs + b0.w;
        float o4 = acc[4] * rs + b1.x, o5 = acc[5] * rs + b1.y;
        float o6 = acc[6] * rs + b1.z, o7 = acc[7] * rs + b1.w;
        o0 = o0 > 0.f ? o0 : 0.f; o1 = o1 > 0.f ? o1 : 0.f;
        o2 = o2 > 0.f ? o2 : 0.f; o3 = o3 > 0.f ? o3 : 0.f;
        o4 = o4 > 0.f ? o4 : 0.f; o5 = o5 > 0.f ? o5 : 0.f;
        o6 = o6 > 0.f ? o6 : 0.f; o7 = o7 > 0.f ? o7 : 0.f;
        uint4 pv;
        *(__half2*)&pv.x = __floats2half2_rn(o0, o1);
        *(__half2*)&pv.y = __floats2half2_rn(o2, o3);
        *(__half2*)&pv.z = __floats2half2_rn(o4, o5);
        *(__half2*)&pv.w = __floats2half2_rn(o6, o7);
        *(uint4*)(ox + (size_t)n * HC + cb) = pv;
    }
}

// ---------------- graph pooling: 4-way node-chunk parallel, int atomicMax ----------------
__global__ void k_pool() {
    int g = blockIdx.x;
    int col = blockIdx.y * 128 + threadIdx.x;
    if (col >= GFD) return;
    const __half* bp; int stride, c;
    if (col < 64)       { bp = d_n0; stride = 64;  c = col; }
    else if (col < 320) { bp = d_x1; stride = 256; c = col - 64; }
    else if (col < 576) { bp = d_x2; stride = 256; c = col - 320; }
    else                { bp = d_x3; stride = 256; c = col - 576; }
    int s0 = d_gstart[g], e0 = d_gend[g];
    int len = e0 - s0;
    if (len <= 0) return;
    int per = (len + 3) >> 2;
    int s = s0 + blockIdx.z * per;
    int e = s + per; if (e > e0) e = e0;
    if (s >= e) return;
    float v = 0.f;                       // all pooled values are post-ReLU >= 0
    int i = s;
    for (; i + 4 <= e; i += 4) {
        float v0 = __half2float(__ldg(&bp[(i + 0) * stride + c]));
        float v1 = __half2float(__ldg(&bp[(i + 1) * stride + c]));
        float v2 = __half2float(__ldg(&bp[(i + 2) * stride + c]));
        float v3 = __half2float(__ldg(&bp[(i + 3) * stride + c]));
        v = fmaxf(v, fmaxf(fmaxf(v0, v1), fmaxf(v2, v3)));
    }
    for (; i < e; i++)
        v = fmaxf(v, __half2float(__ldg(&bp[i * stride + c])));
    atomicMax((int*)&d_gfeat[g * GFD + col], __float_as_int(v));
}

// ---------------- fused head MLPs ----------------
__global__ void k_lathead(const float* __restrict__ aggW, const float* __restrict__ aggb,
                          const float* __restrict__ muW, const float* __restrict__ mub,
                          const float* __restrict__ vW, const float* __restrict__ vb,
                          float* __restrict__ out) {
    __shared__ float gs[GFD];
    __shared__ float ls[LATD];
    int g = blockIdx.x, t = threadIdx.x;
    for (int i = t; i < GFD; i += 256) gs[i] = d_gfeat[g * GFD + i];
    __syncthreads();
    float acc = aggb[t];
    for (int k = 0; k < GFD; k++) acc += gs[k] * aggW[k * LATD + t];
    ls[t] = acc;
    __syncthreads();
    float am = mub[t], av = vb[t];
    for (int k = 0; k < LATD; k++) {
        float lv = ls[k];
        am += lv * muW[k * LATD + t];
        av += lv * vW[k * LATD + t];
    }
    out[g * LATD + t] = am;
    out[GG * LATD + g * LATD + t] = av;
}

// ---------------- launch ----------------
extern "C" void kernel_launch(void* const* d_in, const int* in_sizes, int n_in,
                              void* d_out, int out_size) {
    const float* bf   = (const float*)d_in[0];
    const int*   ei   = (const int*)  d_in[1];
    const int*   batch= (const int*)  d_in[2];
    const float* bfW  = (const float*)d_in[3];
    const float* bfb  = (const float*)d_in[4];
    const float* W1   = (const float*)d_in[5];
    const float* as1  = (const float*)d_in[6];
    const float* ad1  = (const float*)d_in[7];
    const float* b1   = (const float*)d_in[8];
    const float* W2   = (const float*)d_in[9];
    const float* as2  = (const float*)d_in[10];
    const float* ad2  = (const float*)d_in[11];
    const float* b2   = (const float*)d_in[12];
    const float* W3   = (const float*)d_in[13];
    const float* as3  = (const float*)d_in[14];
    const float* ad3  = (const float*)d_in[15];
    const float* b3   = (const float*)d_in[16];
    const float* aggW = (const float*)d_in[17];
    const float* aggb = (const float*)d_in[18];
    const float* muW  = (const float*)d_in[19];
    const float* mub  = (const float*)d_in[20];
    const float* vW   = (const float*)d_in[21];
    const float* vb   = (const float*)d_in[22];
    float* out = (float*)d_out;

    __half *p_n0, *p_x1, *p_x2, *p_x3, *p_wt, *p_h;
    int *p_deg, *p_off, *p_gstart, *p_gend;
    float *p_gfeat;
    cudaGetSymbolAddress((void**)&p_n0, d_n0);
    cudaGetSymbolAddress((void**)&p_x1, d_x1);
    cudaGetSymbolAddress((void**)&p_x2, d_x2);
    cudaGetSymbolAddress((void**)&p_x3, d_x3);
    cudaGetSymbolAddress((void**)&p_wt, d_wt);
    cudaGetSymbolAddress((void**)&p_h,  d_h);
    cudaGetSymbolAddress((void**)&p_deg, d_deg);
    cudaGetSymbolAddress((void**)&p_off, d_off);
    cudaGetSymbolAddress((void**)&p_gstart, d_gstart);
    cudaGetSymbolAddress((void**)&p_gend, d_gend);
    cudaGetSymbolAddress((void**)&p_gfeat, d_gfeat);

    static cudaStream_t s2 = nullptr;
    static cudaEvent_t evFork = nullptr, evJoin = nullptr;
    if (!s2) {
        cudaFuncSetAttribute(k_gemm, cudaFuncAttributeMaxDynamicSharedMemorySize, SMEM_BYTES);
        cudaStreamCreateWithFlags(&s2, cudaStreamNonBlocking);
        cudaEventCreateWithFlags(&evFork, cudaEventDisableTiming);
        cudaEventCreateWithFlags(&evJoin, cudaEventDisableTiming);
    }

    const int T = 256;
    dim3 ggrid((NN + 127) / 128, 2);
    int wgrid = (NN + 7) / 8;                 // warp-per-node
    int agrid = (2 * NN + 7) / 8;             // 2 warps per node
    int egrid = (EL + T - 1) / T;

    // ---- fork: CSR build on side stream, concurrent with proj/cvt/gemm1 ----
    cudaEventRecord(evFork, 0);
    cudaStreamWaitEvent(s2, evFork, 0);
    cudaMemsetAsync(p_deg, 0, NN * sizeof(int), s2);
    cudaMemsetAsync(p_gstart, 0x7F, GG * sizeof(int), s2);   // 0x7F7F7F7F > NN
    cudaMemsetAsync(p_gend, 0, GG * sizeof(int), s2);
    cudaMemsetAsync(p_off, 0, sizeof(int), s2);              // d_off[0] = 0
    k_deg    <<<egrid, T, 0, s2>>>(ei);
    k_scan1  <<<NB1, SCAN_B, 0, s2>>>();
    k_scan2  <<<1, 32, 0, s2>>>();
    k_scan3b <<<(NN + T - 1) / T, T, 0, s2>>>(batch);
    k_scatter<<<egrid, T, 0, s2>>>(ei);
    cudaEventRecord(evJoin, s2);

    // ---- main stream: proj -> weights -> gemm1 ----
    cudaMemsetAsync(p_gfeat, 0, GG * GFD * sizeof(float), 0);
    k_proj   <<<(NN * FD + T - 1) / T, T>>>(bf, bfW, bfb);
    k_cvt_all<<<(FD * HC + 2 * HC * HC + T - 1) / T, T>>>(W1, W2, W3, p_wt);
    k_gemm   <<<ggrid, 256, SMEM_BYTES>>>(p_n0, p_wt, as1, ad1, p_h, FD);

    // join: attention needs CSR + gemm1 outputs
    cudaStreamWaitEvent(0, evJoin, 0);

    // layer 1 aggregate
    k_attmax<<<wgrid, 256>>>();
    k_agg2  <<<agrid, 256>>>(p_h, b1, p_x1);
    // layer 2
    k_gemm  <<<ggrid, 256, SMEM_BYTES>>>(p_x1, p_wt + HC * HC, as2, ad2, p_h, HC);
    k_attmax<<<wgrid, 256>>>();
    k_agg2  <<<agrid, 256>>>(p_h, b2, p_x2);
    // layer 3
    k_gemm  <<<ggrid, 256, SMEM_BYTES>>>(p_x2, p_wt + 2 * HC * HC, as3, ad3, p_h, HC);
    k_attmax<<<wgrid, 256>>>();
    k_agg2  <<<agrid, 256>>>(p_h, b3, p_x3);

    // pooling + heads
    dim3 pgrid(GG, (GFD + 127) / 128, 4);
    k_pool   <<<pgrid, 128>>>();
    k_lathead<<<GG, 256>>>(aggW, aggb, muW, mub, vW, vb, out);
}

// round 10
// speedup vs baseline: 2.6795x; 1.0766x over previous
#include <cuda_runtime.h>
#include <cuda_fp16.h>
#include <math.h>
#include <float.h>

#define NN 50000
#define EE 300000
#define EL (EE + NN)
#define GG 64
#define FD 64
#define NH 4
#define HC 256
#define LATD 256
#define GFD 832
#define SCAN_B 1024
#define NB1 ((NN + SCAN_B - 1) / SCAN_B)   // 49

// GEMM smem: 64B rows, XOR swizzle, 3 stages, single fp16 plane
#define A_OFF 0
#define B_OFF 8192
#define STAGE 16384
#define SMEM_BYTES (3 * STAGE)

// ---------------- device scratch ----------------
__device__ __half d_n0[NN * FD];
__device__ __half d_x1[NN * HC];
__device__ __half d_x2[NN * HC];
__device__ __half d_x3[NN * HC];
__device__ __half d_wt[3 * HC * HC];
__device__ __half d_h [NN * HC];
__device__ float d_as[NN * NH];
__device__ float d_ad[NN * NH];
__device__ float d_alpha[(size_t)EL * NH];
__device__ int   d_deg[NN];
__device__ int   d_off[NN + 1];
__device__ int   d_cur[NN];
__device__ int   d_csr_src[EL];
__device__ int   d_bsum[NB1 + 1];
__device__ int   d_gstart[GG];
__device__ int   d_gend[GG];
__device__ float d_gfeat[GG * GFD];

// ---------------- CSR build ----------------
__global__ void k_deg(const int* __restrict__ ei) {
    int i = blockIdx.x * blockDim.x + threadIdx.x;
    if (i >= EL) return;
    int dst = (i < EE) ? ei[EE + i] : (i - EE);
    atomicAdd(&d_deg[dst], 1);
}

__global__ void k_scan1() {
    __shared__ int sm[SCAN_B];
    int tid = threadIdx.x;
    int i = blockIdx.x * SCAN_B + tid;
    int v = (i < NN) ? d_deg[i] : 0;
    sm[tid] = v;
    __syncthreads();
    for (int d = 1; d < SCAN_B; d <<= 1) {
        int t = 0;
        if (tid >= d) t = sm[tid - d];
        __syncthreads();
        sm[tid] += t;
        __syncthreads();
    }
    if (i < NN) d_off[i + 1] = sm[tid];
    if (tid == SCAN_B - 1) d_bsum[blockIdx.x] = sm[tid];
}

__global__ void k_scan2() {
    int lane = threadIdx.x;
    int a = (lane < NB1) ? d_bsum[lane] : 0;
    int b = (lane + 32 < NB1) ? d_bsum[lane + 32] : 0;
    int ia = a;
#pragma unroll
    for (int o = 1; o < 32; o <<= 1) {
        int t = __shfl_up_sync(0xffffffffu, ia, o);
        if (lane >= o) ia += t;
    }
    int tot0 = __shfl_sync(0xffffffffu, ia, 31);
    int ib = b;
#pragma unroll
    for (int o = 1; o < 32; o <<= 1) {
        int t = __shfl_up_sync(0xffffffffu, ib, o);
        if (lane >= o) ib += t;
    }
    if (lane < NB1) d_bsum[lane] = ia - a;
    if (lane + 32 < NB1) d_bsum[lane + 32] = tot0 + ib - b;
}

// scan fixup + cursor init + per-graph bounds (sorted-boundary stores, NO atomics)
__global__ void k_scan3b(const int* __restrict__ batch) {
    int i = blockIdx.x * blockDim.x + threadIdx.x;
    if (i >= NN) return;
    int val = d_off[i + 1] + d_bsum[i >> 10];
    d_off[i + 1] = val;
    if (i + 1 < NN) d_cur[i + 1] = val;
    if (i == 0) d_cur[0] = 0;
    int b = batch[i];
    if (i == 0) d_gstart[b] = 0;
    if (i == NN - 1) d_gend[b] = NN;
    if (i + 1 < NN) {
        int b2 = batch[i + 1];
        if (b2 != b) { d_gend[b] = i + 1; d_gstart[b2] = i + 1; }
    }
}

__global__ void k_scatter(const int* __restrict__ ei) {
    int i = blockIdx.x * blockDim.x + threadIdx.x;
    if (i >= EL) return;
    int src, dst;
    if (i < EE) { src = ei[i]; dst = ei[EE + i]; }
    else        { src = i - EE; dst = i - EE; }
    int pos = atomicAdd(&d_cur[dst], 1);
    d_csr_src[pos] = src;
}

// ---------------- all three weight transposes in one kernel ----------------
__global__ void k_cvt_all(const float* __restrict__ W1, const float* __restrict__ W2,
                          const float* __restrict__ W3, __half* __restrict__ wt) {
    int i = blockIdx.x * blockDim.x + threadIdx.x;
    if (i < FD * HC) {
        int k = i / HC, n = i % HC;
        wt[n * FD + k] = __float2half(W1[i]);
    } else if (i < FD * HC + HC * HC) {
        int j = i - FD * HC;
        int k = j / HC, n = j % HC;
        wt[HC * HC + n * HC + k] = __float2half(W2[j]);
    } else if (i < FD * HC + 2 * HC * HC) {
        int j = i - FD * HC - HC * HC;
        int k = j / HC, n = j % HC;
        wt[2 * HC * HC + n * HC + k] = __float2half(W3[j]);
    }
}

// ---------------- input projection ----------------
__global__ void k_proj(const float* __restrict__ bf, const float* __restrict__ W,
                       const float* __restrict__ b) {
    int t = blockIdx.x * blockDim.x + threadIdx.x;
    if (t >= NN * FD) return;
    int n = t >> 6, f = t & 63;
    const float* r = &bf[n * 5];
    float acc = b[f];
    acc += r[0] * W[0 * FD + f];
    acc += r[1] * W[1 * FD + f];
    acc += r[2] * W[2 * FD + f];
    acc += r[3] * W[3 * FD + f];
    acc += r[4] * W[4 * FD + f];
    acc = acc > 0.f ? acc : 0.f;
    d_n0[t] = __float2half(acc);
}

// ---------------- fp16 tensor-core GEMM + fused attention dots ----------------
__device__ __forceinline__ void mma16816(float* d, const unsigned* a, unsigned b0, unsigned b1) {
    asm volatile(
        "mma.sync.aligned.m16n8k16.row.col.f32.f16.f16.f32 "
        "{%0,%1,%2,%3}, {%4,%5,%6,%7}, {%8,%9}, {%0,%1,%2,%3};\n"
        : "+f"(d[0]), "+f"(d[1]), "+f"(d[2]), "+f"(d[3])
        : "r"(a[0]), "r"(a[1]), "r"(a[2]), "r"(a[3]), "r"(b0), "r"(b1));
}

__device__ __forceinline__ void ldm4(unsigned& r0, unsigned& r1, unsigned& r2, unsigned& r3,
                                     unsigned addr) {
    asm volatile("ldmatrix.sync.aligned.m8n8.x4.shared.b16 {%0,%1,%2,%3}, [%4];\n"
                 : "=r"(r0), "=r"(r1), "=r"(r2), "=r"(r3) : "r"(addr));
}

#define CPA(dst, src) asm volatile("cp.async.cg.shared.global [%0], [%1], 16;\n" :: "r"(dst), "l"(src))

extern __shared__ char smem_raw[];

__global__ void __launch_bounds__(256, 2) k_gemm(
    const __half* __restrict__ x, const __half* __restrict__ w,
    const float* __restrict__ asw, const float* __restrict__ adw,
    __half* __restrict__ out, int K)
{
    unsigned sbase;
    asm("{ .reg .u64 t; cvta.to.shared.u64 t, %1; cvt.u32.u64 %0, t; }"
        : "=r"(sbase) : "l"(smem_raw));
    int tid = threadIdx.x, lane = tid & 31, wid = tid >> 5;
    int warp_m = wid & 3, warp_n = wid >> 2;
    int row0 = blockIdx.x * 128, col0 = blockIdx.y * 128;

    int lrow = tid >> 2;
    unsigned lseg = tid & 3;
    int nch = K >> 5;

    int a_row = warp_m * 32 + (lane & 15);
    unsigned a_base = (unsigned)(a_row * 64) + ((((lane >> 4) ^ ((a_row >> 1) & 3)) & 3u) << 4);
    int b_row = warp_n * 64 + ((lane >> 4) << 3) + (lane & 7);
    unsigned b_base = (unsigned)(b_row * 64) + (((((lane >> 3) & 1) ^ ((b_row >> 1) & 3)) & 3u) << 4);

    float acc[2][8][4];
#pragma unroll
    for (int mt = 0; mt < 2; mt++)
#pragma unroll
        for (int nt = 0; nt < 8; nt++)
#pragma unroll
            for (int i = 0; i < 4; i++) acc[mt][nt][i] = 0.f;

    auto load_chunk = [&](int c) {
        unsigned sb = sbase + (unsigned)((c % 3) * STAGE);
        int k0 = c << 5;
#pragma unroll
        for (int half_ = 0; half_ < 2; half_++) {
            int r = lrow + half_ * 64;
            unsigned phys = (lseg ^ ((unsigned)(r >> 1) & 3u)) << 4;
            unsigned so = (unsigned)(r * 64) + phys;
            unsigned gofs = lseg * 16;
            int gr = row0 + r;
            if (gr < NN) {
                CPA(sb + A_OFF + so, (const char*)x + ((size_t)gr * K + k0) * 2 + gofs);
            } else {
                asm volatile("st.shared.v4.b32 [%0], {%1,%1,%1,%1};" :: "r"(sb + A_OFF + so), "r"(0u));
            }
            int gc = col0 + r;
            CPA(sb + B_OFF + so, (const char*)w + ((size_t)gc * K + k0) * 2 + gofs);
        }
        asm volatile("cp.async.commit_group;\n");
    };

    load_chunk(0);
    load_chunk(1);
    for (int c = 0; c < nch; c++) {
        if (c < nch - 1) asm volatile("cp.async.wait_group 1;\n");
        else             asm volatile("cp.async.wait_group 0;\n");
        __syncthreads();
        if (c + 2 < nch) load_chunk(c + 2);

        unsigned base = sbase + (unsigned)((c % 3) * STAGE);
#pragma unroll
        for (int ko = 0; ko < 2; ko++) {
            unsigned kx = (unsigned)(ko << 5);
            unsigned ah[2][4];
#pragma unroll
            for (int mt = 0; mt < 2; mt++)
                ldm4(ah[mt][0], ah[mt][1], ah[mt][2], ah[mt][3],
                     (base + A_OFF + a_base + mt * 1024) ^ kx);
            unsigned bh[2][4];
            ldm4(bh[0][0], bh[0][1], bh[0][2], bh[0][3], (base + B_OFF + b_base) ^ kx);
#pragma unroll
            for (int p = 0; p < 4; p++) {
                int cur = p & 1, nxt = cur ^ 1;
                if (p < 3)
                    ldm4(bh[nxt][0], bh[nxt][1], bh[nxt][2], bh[nxt][3],
                         (base + B_OFF + b_base + (p + 1) * 1024) ^ kx);
#pragma unroll
                for (int q = 0; q < 2; q++) {
                    int nt = p * 2 + q;
#pragma unroll
                    for (int mt = 0; mt < 2; mt++)
                        mma16816(acc[mt][nt], ah[mt], bh[cur][q * 2], bh[cur][q * 2 + 1]);
                }
            }
        }
    }

    // ---- epilogue: store h (fp16) + fused attention dots (fp32) ----
    int head = blockIdx.y * 2 + warp_n;
    float pa[4] = {0, 0, 0, 0}, pd[4] = {0, 0, 0, 0};
#pragma unroll
    for (int nt = 0; nt < 8; nt++) {
        int cc = col0 + warp_n * 64 + nt * 8 + (lane & 3) * 2;
        float s0 = __ldg(&asw[cc]), s1 = __ldg(&asw[cc + 1]);
        float t0 = __ldg(&adw[cc]), t1 = __ldg(&adw[cc + 1]);
#pragma unroll
        for (int mt = 0; mt < 2; mt++) {
            float* a = acc[mt][nt];
            pa[mt * 2]     += a[0] * s0 + a[1] * s1;
            pa[mt * 2 + 1] += a[2] * s0 + a[3] * s1;
            pd[mt * 2]     += a[0] * t0 + a[1] * t1;
            pd[mt * 2 + 1] += a[2] * t0 + a[3] * t1;
            int rr = row0 + warp_m * 32 + mt * 16 + (lane >> 2);
            if (rr < NN)
                *(__half2*)&out[(size_t)rr * HC + cc] = __floats2half2_rn(a[0], a[1]);
            if (rr + 8 < NN)
                *(__half2*)&out[(size_t)(rr + 8) * HC + cc] = __floats2half2_rn(a[2], a[3]);
        }
    }
#pragma unroll
    for (int s = 0; s < 4; s++) {
        pa[s] += __shfl_xor_sync(0xffffffffu, pa[s], 1);
        pa[s] += __shfl_xor_sync(0xffffffffu, pa[s], 2);
        pd[s] += __shfl_xor_sync(0xffffffffu, pd[s], 1);
        pd[s] += __shfl_xor_sync(0xffffffffu, pd[s], 2);
    }
    if ((lane & 3) == 0) {
#pragma unroll
        for (int s = 0; s < 4; s++) {
            int rr = row0 + warp_m * 32 + (s >> 1) * 16 + (s & 1) * 8 + (lane >> 2);
            if (rr < NN) {
                d_as[rr * 4 + head] = pa[s];
                d_ad[rr * 4 + head] = pd[s];
            }
        }
    }
}

__device__ __forceinline__ float lrelu(float v) { return v > 0.f ? v : 0.2f * v; }

// ---------------- fused GAT: softmax stats + alpha + aggregation, 2 warps/node ----------------
__global__ void k_gat(const __half* __restrict__ h, const float* __restrict__ bias,
                      __half* __restrict__ ox) {
    int gw = (blockIdx.x * blockDim.x + threadIdx.x) >> 5;
    int lane = threadIdx.x & 31;
    int n = gw >> 1, half_ = gw & 1;
    if (n >= NN) return;
    int beg = d_off[n], end = d_off[n + 1];
    int head0 = half_ * 2;
    float2 adv = *(const float2*)&d_ad[n * 4 + head0];

    // pass 1: max over edges for this warp's 2 heads
    float m0 = -FLT_MAX, m1 = -FLT_MAX;
    for (int j = beg + lane; j < end; j += 32) {
        int s = d_csr_src[j];
        float2 a = *(const float2*)&d_as[s * 4 + head0];
        m0 = fmaxf(m0, lrelu(a.x + adv.x));
        m1 = fmaxf(m1, lrelu(a.y + adv.y));
    }
#pragma unroll
    for (int o = 16; o > 0; o >>= 1) {
        m0 = fmaxf(m0, __shfl_xor_sync(0xffffffffu, m0, o));
        m1 = fmaxf(m1, __shfl_xor_sync(0xffffffffu, m1, o));
    }

    // pass 2: sum of exp + store unnormalized alpha
    float s0 = 0.f, s1 = 0.f;
    for (int j = beg + lane; j < end; j += 32) {
        int s = d_csr_src[j];
        float2 a = *(const float2*)&d_as[s * 4 + head0];
        float p0 = __expf(lrelu(a.x + adv.x) - m0);
        float p1 = __expf(lrelu(a.y + adv.y) - m1);
        s0 += p0; s1 += p1;
        *(float2*)&d_alpha[(size_t)j * 4 + head0] = make_float2(p0, p1);
    }
#pragma unroll
    for (int o = 16; o > 0; o >>= 1) {
        s0 += __shfl_xor_sync(0xffffffffu, s0, o);
        s1 += __shfl_xor_sync(0xffffffffu, s1, o);
    }
    float rs0 = 1.f / s0, rs1 = 1.f / s1;
    __syncwarp();   // make this warp's alpha stores visible to all its lanes

    // pass 3: gather — 2 edge groups x 16 lanes x 16B
    int eg = lane >> 4;
    int sub = lane & 15;
    int cb = half_ * 128 + sub * 8;
    int head = head0 + (sub >> 3);
    float rs = (sub >> 3) ? rs1 : rs0;

    float acc[8] = {0, 0, 0, 0, 0, 0, 0, 0};
#pragma unroll 2
    for (int j = beg + eg; j < end; j += 2) {
        int s = d_csr_src[j];
        float w = d_alpha[(size_t)j * 4 + head];
        uint4 v = __ldg((const uint4*)(h + (size_t)s * HC + cb));
        float2 f0 = __half22float2(*(__half2*)&v.x);
        float2 f1 = __half22float2(*(__half2*)&v.y);
        float2 f2 = __half22float2(*(__half2*)&v.z);
        float2 f3 = __half22float2(*(__half2*)&v.w);
        acc[0] += w * f0.x; acc[1] += w * f0.y;
        acc[2] += w * f1.x; acc[3] += w * f1.y;
        acc[4] += w * f2.x; acc[5] += w * f2.y;
        acc[6] += w * f3.x; acc[7] += w * f3.y;
    }
#pragma unroll
    for (int i = 0; i < 8; i++)
        acc[i] += __shfl_xor_sync(0xffffffffu, acc[i], 16);

    if (eg == 0) {
        float4 b0 = *(const float4*)&bias[cb];
        float4 b1 = *(const float4*)&bias[cb + 4];
        float o0 = acc[0] * rs + b0.x, o1 = acc[1] * rs + b0.y;
        float o2 = acc[2] * rs + b0.z, o3 = acc[3] * rs + b0.w;
        float o4 = acc[4] * rs + b1.x, o5 = acc[5] * rs + b1.y;
        float o6 = acc[6] * rs + b1.z, o7 = acc[7] * rs + b1.w;
        o0 = o0 > 0.f ? o0 : 0.f; o1 = o1 > 0.f ? o1 : 0.f;
        o2 = o2 > 0.f ? o2 : 0.f; o3 = o3 > 0.f ? o3 : 0.f;
        o4 = o4 > 0.f ? o4 : 0.f; o5 = o5 > 0.f ? o5 : 0.f;
        o6 = o6 > 0.f ? o6 : 0.f; o7 = o7 > 0.f ? o7 : 0.f;
        uint4 pv;
        *(__half2*)&pv.x = __floats2half2_rn(o0, o1);
        *(__half2*)&pv.y = __floats2half2_rn(o2, o3);
        *(__half2*)&pv.z = __floats2half2_rn(o4, o5);
        *(__half2*)&pv.w = __floats2half2_rn(o6, o7);
        *(uint4*)(ox + (size_t)n * HC + cb) = pv;
    }
}

// ---------------- graph pooling piece (per tensor): 4-way node-chunk, atomicMax ----------------
__global__ void k_pool1(const __half* __restrict__ bp, int stride, int colbase) {
    int g = blockIdx.x;
    int c = blockIdx.y * 128 + threadIdx.x;
    if (c >= stride) return;
    int s0 = d_gstart[g], e0 = d_gend[g];
    int len = e0 - s0;
    if (len <= 0) return;
    int per = (len + 3) >> 2;
    int s = s0 + blockIdx.z * per;
    int e = s + per; if (e > e0) e = e0;
    if (s >= e) return;
    float v = 0.f;                       // pooled values are post-ReLU >= 0
    int i = s;
    for (; i + 4 <= e; i += 4) {
        float v0 = __half2float(__ldg(&bp[(i + 0) * stride + c]));
        float v1 = __half2float(__ldg(&bp[(i + 1) * stride + c]));
        float v2 = __half2float(__ldg(&bp[(i + 2) * stride + c]));
        float v3 = __half2float(__ldg(&bp[(i + 3) * stride + c]));
        v = fmaxf(v, fmaxf(fmaxf(v0, v1), fmaxf(v2, v3)));
    }
    for (; i < e; i++)
        v = fmaxf(v, __half2float(__ldg(&bp[i * stride + c])));
    atomicMax((int*)&d_gfeat[g * GFD + colbase + c], __float_as_int(v));
}

// ---------------- fused head MLPs ----------------
__global__ void k_lathead(const float* __restrict__ aggW, const float* __restrict__ aggb,
                          const float* __restrict__ muW, const float* __restrict__ mub,
                          const float* __restrict__ vW, const float* __restrict__ vb,
                          float* __restrict__ out) {
    __shared__ float gs[GFD];
    __shared__ float ls[LATD];
    int g = blockIdx.x, t = threadIdx.x;
    for (int i = t; i < GFD; i += 256) gs[i] = d_gfeat[g * GFD + i];
    __syncthreads();
    float acc = aggb[t];
    for (int k = 0; k < GFD; k++) acc += gs[k] * aggW[k * LATD + t];
    ls[t] = acc;
    __syncthreads();
    float am = mub[t], av = vb[t];
    for (int k = 0; k < LATD; k++) {
        float lv = ls[k];
        am += lv * muW[k * LATD + t];
        av += lv * vW[k * LATD + t];
    }
    out[g * LATD + t] = am;
    out[GG * LATD + g * LATD + t] = av;
}

// ---------------- launch ----------------
extern "C" void kernel_launch(void* const* d_in, const int* in_sizes, int n_in,
                              void* d_out, int out_size) {
    const float* bf   = (const float*)d_in[0];
    const int*   ei   = (const int*)  d_in[1];
    const int*   batch= (const int*)  d_in[2];
    const float* bfW  = (const float*)d_in[3];
    const float* bfb  = (const float*)d_in[4];
    const float* W1   = (const float*)d_in[5];
    const float* as1  = (const float*)d_in[6];
    const float* ad1  = (const float*)d_in[7];
    const float* b1   = (const float*)d_in[8];
    const float* W2   = (const float*)d_in[9];
    const float* as2  = (const float*)d_in[10];
    const float* ad2  = (const float*)d_in[11];
    const float* b2   = (const float*)d_in[12];
    const float* W3   = (const float*)d_in[13];
    const float* as3  = (const float*)d_in[14];
    const float* ad3  = (const float*)d_in[15];
    const float* b3   = (const float*)d_in[16];
    const float* aggW = (const float*)d_in[17];
    const float* aggb = (const float*)d_in[18];
    const float* muW  = (const float*)d_in[19];
    const float* mub  = (const float*)d_in[20];
    const float* vW   = (const float*)d_in[21];
    const float* vb   = (const float*)d_in[22];
    float* out = (float*)d_out;

    __half *p_n0, *p_x1, *p_x2, *p_x3, *p_wt, *p_h;
    int *p_deg, *p_off, *p_gstart, *p_gend;
    float *p_gfeat;
    cudaGetSymbolAddress((void**)&p_n0, d_n0);
    cudaGetSymbolAddress((void**)&p_x1, d_x1);
    cudaGetSymbolAddress((void**)&p_x2, d_x2);
    cudaGetSymbolAddress((void**)&p_x3, d_x3);
    cudaGetSymbolAddress((void**)&p_wt, d_wt);
    cudaGetSymbolAddress((void**)&p_h,  d_h);
    cudaGetSymbolAddress((void**)&p_deg, d_deg);
    cudaGetSymbolAddress((void**)&p_off, d_off);
    cudaGetSymbolAddress((void**)&p_gstart, d_gstart);
    cudaGetSymbolAddress((void**)&p_gend, d_gend);
    cudaGetSymbolAddress((void**)&p_gfeat, d_gfeat);

    static cudaStream_t s2 = nullptr;
    static cudaEvent_t evFork = nullptr, evJoin = nullptr;
    static cudaEvent_t evP = nullptr, ev1 = nullptr, ev2 = nullptr, ev3 = nullptr, evPool = nullptr;
    if (!s2) {
        cudaFuncSetAttribute(k_gemm, cudaFuncAttributeMaxDynamicSharedMemorySize, SMEM_BYTES);
        cudaStreamCreateWithFlags(&s2, cudaStreamNonBlocking);
        cudaEventCreateWithFlags(&evFork, cudaEventDisableTiming);
        cudaEventCreateWithFlags(&evJoin, cudaEventDisableTiming);
        cudaEventCreateWithFlags(&evP, cudaEventDisableTiming);
        cudaEventCreateWithFlags(&ev1, cudaEventDisableTiming);
        cudaEventCreateWithFlags(&ev2, cudaEventDisableTiming);
        cudaEventCreateWithFlags(&ev3, cudaEventDisableTiming);
        cudaEventCreateWithFlags(&evPool, cudaEventDisableTiming);
    }

    const int T = 256;
    dim3 ggrid((NN + 127) / 128, 2);
    int agrid = (2 * NN + 7) / 8;             // 2 warps per node
    int egrid = (EL + T - 1) / T;
    dim3 pg64 (GG, 1, 4);                     // pool grid for 64-col tensor
    dim3 pg256(GG, 2, 4);                     // pool grid for 256-col tensors

    // ---- fork: CSR build + pooling on side stream ----
    cudaEventRecord(evFork, 0);
    cudaStreamWaitEvent(s2, evFork, 0);
    cudaMemsetAsync(p_deg, 0, NN * sizeof(int), s2);
    cudaMemsetAsync(p_gstart, 0x7F, GG * sizeof(int), s2);   // empty-graph sentinel
    cudaMemsetAsync(p_gend, 0, GG * sizeof(int), s2);
    cudaMemsetAsync(p_off, 0, sizeof(int), s2);
    cudaMemsetAsync(p_gfeat, 0, GG * GFD * sizeof(float), s2);
    k_deg    <<<egrid, T, 0, s2>>>(ei);
    k_scan1  <<<NB1, SCAN_B, 0, s2>>>();
    k_scan2  <<<1, 32, 0, s2>>>();
    k_scan3b <<<(NN + T - 1) / T, T, 0, s2>>>(batch);
    k_scatter<<<egrid, T, 0, s2>>>(ei);
    cudaEventRecord(evJoin, s2);

    // ---- main stream: proj -> weights -> gemm1 ----
    k_proj   <<<(NN * FD + T - 1) / T, T>>>(bf, bfW, bfb);
    cudaEventRecord(evP, 0);
    k_cvt_all<<<(FD * HC + 2 * HC * HC + T - 1) / T, T>>>(W1, W2, W3, p_wt);
    k_gemm   <<<ggrid, 256, SMEM_BYTES>>>(p_n0, p_wt, as1, ad1, p_h, FD);

    // side stream: pool n0 once proj + bounds are done
    cudaStreamWaitEvent(s2, evP, 0);
    k_pool1<<<pg64, 128, 0, s2>>>(p_n0, FD, 0);

    // join: attention needs CSR + gemm1 outputs
    cudaStreamWaitEvent(0, evJoin, 0);

    // layer 1
    k_gat<<<agrid, 256>>>(p_h, b1, p_x1);
    cudaEventRecord(ev1, 0);
    cudaStreamWaitEvent(s2, ev1, 0);
    k_pool1<<<pg256, 128, 0, s2>>>(p_x1, HC, 64);
    // layer 2
    k_gemm<<<ggrid, 256, SMEM_BYTES>>>(p_x1, p_wt + HC * HC, as2, ad2, p_h, HC);
    k_gat <<<agrid, 256>>>(p_h, b2, p_x2);
    cudaEventRecord(ev2, 0);
    cudaStreamWaitEvent(s2, ev2, 0);
    k_pool1<<<pg256, 128, 0, s2>>>(p_x2, HC, 320);
    // layer 3
    k_gemm<<<ggrid, 256, SMEM_BYTES>>>(p_x2, p_wt + 2 * HC * HC, as3, ad3, p_h, HC);
    k_gat <<<agrid, 256>>>(p_h, b3, p_x3);
    cudaEventRecord(ev3, 0);
    cudaStreamWaitEvent(s2, ev3, 0);
    k_pool1<<<pg256, 128, 0, s2>>>(p_x3, HC, 576);
    cudaEventRecord(evPool, s2);

    // heads
    cudaStreamWaitEvent(0, evPool, 0);
    k_lathead<<<GG, 256>>>(aggW, aggb, muW, mub, vW, vb, out);
}

// round 11
// speedup vs baseline: 2.6925x; 1.0049x over previous
#include <cuda_runtime.h>
#include <cuda_fp16.h>
#include <math.h>
#include <float.h>

#define NN 50000
#define EE 300000
#define EL (EE + NN)
#define GG 64
#define FD 64
#define NH 4
#define HC 256
#define LATD 256
#define GFD 832
#define SCAN_B 1024
#define NB1 ((NN + SCAN_B - 1) / SCAN_B)   // 49

// GEMM smem: 128B rows (K-chunk 64), XOR swizzle seg^(row&7), 3 stages
#define A_OFF 0
#define B_OFF 16384
#define STAGE 32768
#define SMEM_BYTES (3 * STAGE)

// ---------------- device scratch ----------------
__device__ __half d_n0[NN * FD];
__device__ __half d_x1[NN * HC];
__device__ __half d_x2[NN * HC];
__device__ __half d_x3[NN * HC];
__device__ __half d_wt[3 * HC * HC];
__device__ __half d_h [NN * HC];
__device__ float d_as[NN * NH];
__device__ float d_ad[NN * NH];
__device__ float d_alpha[(size_t)EL * NH];
__device__ int   d_deg[NN];
__device__ int   d_off[NN + 1];
__device__ int   d_cur[NN];
__device__ int   d_csr_src[EL];
__device__ int   d_bsum[NB1 + 1];
__device__ int   d_gstart[GG];
__device__ int   d_gend[GG];
__device__ float d_gfeat[GG * GFD];

// ---------------- CSR build ----------------
__global__ void k_deg(const int* __restrict__ ei) {
    int i = blockIdx.x * blockDim.x + threadIdx.x;
    if (i >= EL) return;
    int dst = (i < EE) ? ei[EE + i] : (i - EE);
    atomicAdd(&d_deg[dst], 1);
}

__global__ void k_scan1() {
    __shared__ int sm[SCAN_B];
    int tid = threadIdx.x;
    int i = blockIdx.x * SCAN_B + tid;
    int v = (i < NN) ? d_deg[i] : 0;
    sm[tid] = v;
    __syncthreads();
    for (int d = 1; d < SCAN_B; d <<= 1) {
        int t = 0;
        if (tid >= d) t = sm[tid - d];
        __syncthreads();
        sm[tid] += t;
        __syncthreads();
    }
    if (i < NN) d_off[i + 1] = sm[tid];
    if (tid == SCAN_B - 1) d_bsum[blockIdx.x] = sm[tid];
}

__global__ void k_scan2() {
    int lane = threadIdx.x;
    int a = (lane < NB1) ? d_bsum[lane] : 0;
    int b = (lane + 32 < NB1) ? d_bsum[lane + 32] : 0;
    int ia = a;
#pragma unroll
    for (int o = 1; o < 32; o <<= 1) {
        int t = __shfl_up_sync(0xffffffffu, ia, o);
        if (lane >= o) ia += t;
    }
    int tot0 = __shfl_sync(0xffffffffu, ia, 31);
    int ib = b;
#pragma unroll
    for (int o = 1; o < 32; o <<= 1) {
        int t = __shfl_up_sync(0xffffffffu, ib, o);
        if (lane >= o) ib += t;
    }
    if (lane < NB1) d_bsum[lane] = ia - a;
    if (lane + 32 < NB1) d_bsum[lane + 32] = tot0 + ib - b;
}

// scan fixup + cursor init + per-graph bounds (sorted-boundary stores)
__global__ void k_scan3b(const int* __restrict__ batch) {
    int i = blockIdx.x * blockDim.x + threadIdx.x;
    if (i >= NN) return;
    int val = d_off[i + 1] + d_bsum[i >> 10];
    d_off[i + 1] = val;
    if (i + 1 < NN) d_cur[i + 1] = val;
    if (i == 0) d_cur[0] = 0;
    int b = batch[i];
    if (i == 0) d_gstart[b] = 0;
    if (i == NN - 1) d_gend[b] = NN;
    if (i + 1 < NN) {
        int b2 = batch[i + 1];
        if (b2 != b) { d_gend[b] = i + 1; d_gstart[b2] = i + 1; }
    }
}

__global__ void k_scatter(const int* __restrict__ ei) {
    int i = blockIdx.x * blockDim.x + threadIdx.x;
    if (i >= EL) return;
    int src, dst;
    if (i < EE) { src = ei[i]; dst = ei[EE + i]; }
    else        { src = i - EE; dst = i - EE; }
    int pos = atomicAdd(&d_cur[dst], 1);
    d_csr_src[pos] = src;
}

// ---------------- all three weight transposes in one kernel ----------------
__global__ void k_cvt_all(const float* __restrict__ W1, const float* __restrict__ W2,
                          const float* __restrict__ W3, __half* __restrict__ wt) {
    int i = blockIdx.x * blockDim.x + threadIdx.x;
    if (i < FD * HC) {
        int k = i / HC, n = i % HC;
        wt[n * FD + k] = __float2half(W1[i]);
    } else if (i < FD * HC + HC * HC) {
        int j = i - FD * HC;
        int k = j / HC, n = j % HC;
        wt[HC * HC + n * HC + k] = __float2half(W2[j]);
    } else if (i < FD * HC + 2 * HC * HC) {
        int j = i - FD * HC - HC * HC;
        int k = j / HC, n = j % HC;
        wt[2 * HC * HC + n * HC + k] = __float2half(W3[j]);
    }
}

// ---------------- input projection ----------------
__global__ void k_proj(const float* __restrict__ bf, const float* __restrict__ W,
                       const float* __restrict__ b) {
    int t = blockIdx.x * blockDim.x + threadIdx.x;
    if (t >= NN * FD) return;
    int n = t >> 6, f = t & 63;
    const float* r = &bf[n * 5];
    float acc = b[f];
    acc += r[0] * W[0 * FD + f];
    acc += r[1] * W[1 * FD + f];
    acc += r[2] * W[2 * FD + f];
    acc += r[3] * W[3 * FD + f];
    acc += r[4] * W[4 * FD + f];
    acc = acc > 0.f ? acc : 0.f;
    d_n0[t] = __float2half(acc);
}

// ---------------- fp16 tensor-core GEMM + fused attention dots ----------------
__device__ __forceinline__ void mma16816(float* d, const unsigned* a, unsigned b0, unsigned b1) {
    asm volatile(
        "mma.sync.aligned.m16n8k16.row.col.f32.f16.f16.f32 "
        "{%0,%1,%2,%3}, {%4,%5,%6,%7}, {%8,%9}, {%0,%1,%2,%3};\n"
        : "+f"(d[0]), "+f"(d[1]), "+f"(d[2]), "+f"(d[3])
        : "r"(a[0]), "r"(a[1]), "r"(a[2]), "r"(a[3]), "r"(b0), "r"(b1));
}

__device__ __forceinline__ void ldm4(unsigned& r0, unsigned& r1, unsigned& r2, unsigned& r3,
                                     unsigned addr) {
    asm volatile("ldmatrix.sync.aligned.m8n8.x4.shared.b16 {%0,%1,%2,%3}, [%4];\n"
                 : "=r"(r0), "=r"(r1), "=r"(r2), "=r"(r3) : "r"(addr));
}

#define CPA(dst, src) asm volatile("cp.async.cg.shared.global [%0], [%1], 16;\n" :: "r"(dst), "l"(src))

extern __shared__ char smem_raw[];

__global__ void __launch_bounds__(256, 2) k_gemm(
    const __half* __restrict__ x, const __half* __restrict__ w,
    const float* __restrict__ asw, const float* __restrict__ adw,
    __half* __restrict__ out, int K)
{
    unsigned sbase;
    asm("{ .reg .u64 t; cvta.to.shared.u64 t, %1; cvt.u32.u64 %0, t; }"
        : "=r"(sbase) : "l"(smem_raw));
    int tid = threadIdx.x, lane = tid & 31, wid = tid >> 5;
    int warp_m = wid & 3, warp_n = wid >> 2;
    int row0 = blockIdx.x * 128, col0 = blockIdx.y * 128;
    int nch = K >> 6;                  // 64-wide K chunks

    // fragment bases: addr = row*128 + ((row&7)<<4), then ^ (col16<<4)
    int row_a = warp_m * 32 + (lane & 15);
    unsigned a_base = (unsigned)(row_a * 128) + (((unsigned)row_a & 7u) << 4);
    unsigned colA = (unsigned)(lane >> 4);          // 0/1
    int row_b = warp_n * 64 + ((lane >> 4) << 3) + (lane & 7);
    unsigned b_base = (unsigned)(row_b * 128) + (((unsigned)row_b & 7u) << 4);
    unsigned colB = (unsigned)((lane >> 3) & 1);    // 0/1

    float acc[2][8][4];
#pragma unroll
    for (int mt = 0; mt < 2; mt++)
#pragma unroll
        for (int nt = 0; nt < 8; nt++)
#pragma unroll
            for (int i = 0; i < 4; i++) acc[mt][nt][i] = 0.f;

    auto load_chunk = [&](int c) {
        unsigned sb = sbase + (unsigned)((c % 3) * STAGE);
        int k0 = c << 6;
#pragma unroll
        for (int i = 0; i < 4; i++) {               // A: 128 rows x 8 segs
            int g = tid + 256 * i;
            int row = g >> 3;
            unsigned seg = (unsigned)(g & 7);
            unsigned so = (unsigned)(row * 128) + ((seg ^ ((unsigned)row & 7u)) << 4);
            int gr = row0 + row;
            if (gr < NN) {
                CPA(sb + A_OFF + so, (const char*)x + ((size_t)gr * K + k0) * 2 + seg * 16);
            } else {
                asm volatile("st.shared.v4.b32 [%0], {%1,%1,%1,%1};" :: "r"(sb + A_OFF + so), "r"(0u));
            }
        }
#pragma unroll
        for (int i = 0; i < 4; i++) {               // B: 128 rows x 8 segs
            int g = tid + 256 * i;
            int row = g >> 3;
            unsigned seg = (unsigned)(g & 7);
            unsigned so = (unsigned)(row * 128) + ((seg ^ ((unsigned)row & 7u)) << 4);
            int gc = col0 + row;
            CPA(sb + B_OFF + so, (const char*)w + ((size_t)gc * K + k0) * 2 + seg * 16);
        }
        asm volatile("cp.async.commit_group;\n");
    };

    load_chunk(0);
    if (nch > 1) load_chunk(1);
    else         asm volatile("cp.async.commit_group;\n");   // keep group counts aligned

    for (int c = 0; c < nch; c++) {
        if (c < nch - 1) asm volatile("cp.async.wait_group 1;\n");
        else             asm volatile("cp.async.wait_group 0;\n");
        __syncthreads();
        if (c + 2 < nch) load_chunk(c + 2);

        unsigned base = sbase + (unsigned)((c % 3) * STAGE);
#pragma unroll
        for (int ko = 0; ko < 4; ko++) {
            unsigned kxa = (colA + 2u * (unsigned)ko) << 4;
            unsigned kxb = (colB + 2u * (unsigned)ko) << 4;
            unsigned ah[2][4];
#pragma unroll
            for (int mt = 0; mt < 2; mt++)
                ldm4(ah[mt][0], ah[mt][1], ah[mt][2], ah[mt][3],
                     (base + A_OFF + a_base + mt * 2048) ^ kxa);
            unsigned bh[2][4];
            ldm4(bh[0][0], bh[0][1], bh[0][2], bh[0][3], (base + B_OFF + b_base) ^ kxb);
#pragma unroll
            for (int p = 0; p < 4; p++) {
                int cur = p & 1, nxt = cur ^ 1;
                if (p < 3)
                    ldm4(bh[nxt][0], bh[nxt][1], bh[nxt][2], bh[nxt][3],
                         (base + B_OFF + b_base + (p + 1) * 2048) ^ kxb);
#pragma unroll
                for (int q = 0; q < 2; q++) {
                    int nt = p * 2 + q;
#pragma unroll
                    for (int mt = 0; mt < 2; mt++)
                        mma16816(acc[mt][nt], ah[mt], bh[cur][q * 2], bh[cur][q * 2 + 1]);
                }
            }
        }
    }

    // ---- epilogue: store h (fp16) + fused attention dots (fp32) ----
    int head = blockIdx.y * 2 + warp_n;
    float pa[4] = {0, 0, 0, 0}, pd[4] = {0, 0, 0, 0};
#pragma unroll
    for (int nt = 0; nt < 8; nt++) {
        int cc = col0 + warp_n * 64 + nt * 8 + (lane & 3) * 2;
        float s0 = __ldg(&asw[cc]), s1 = __ldg(&asw[cc + 1]);
        float t0 = __ldg(&adw[cc]), t1 = __ldg(&adw[cc + 1]);
#pragma unroll
        for (int mt = 0; mt < 2; mt++) {
            float* a = acc[mt][nt];
            pa[mt * 2]     += a[0] * s0 + a[1] * s1;
            pa[mt * 2 + 1] += a[2] * s0 + a[3] * s1;
            pd[mt * 2]     += a[0] * t0 + a[1] * t1;
            pd[mt * 2 + 1] += a[2] * t0 + a[3] * t1;
            int rr = row0 + warp_m * 32 + mt * 16 + (lane >> 2);
            if (rr < NN)
                *(__half2*)&out[(size_t)rr * HC + cc] = __floats2half2_rn(a[0], a[1]);
            if (rr + 8 < NN)
                *(__half2*)&out[(size_t)(rr + 8) * HC + cc] = __floats2half2_rn(a[2], a[3]);
        }
    }
#pragma unroll
    for (int s = 0; s < 4; s++) {
        pa[s] += __shfl_xor_sync(0xffffffffu, pa[s], 1);
        pa[s] += __shfl_xor_sync(0xffffffffu, pa[s], 2);
        pd[s] += __shfl_xor_sync(0xffffffffu, pd[s], 1);
        pd[s] += __shfl_xor_sync(0xffffffffu, pd[s], 2);
    }
    if ((lane & 3) == 0) {
#pragma unroll
        for (int s = 0; s < 4; s++) {
            int rr = row0 + warp_m * 32 + (s >> 1) * 16 + (s & 1) * 8 + (lane >> 2);
            if (rr < NN) {
                d_as[rr * 4 + head] = pa[s];
                d_ad[rr * 4 + head] = pd[s];
            }
        }
    }
}

__device__ __forceinline__ float lrelu(float v) { return v > 0.f ? v : 0.2f * v; }

// ---------------- fused GAT: softmax stats + alpha + aggregation, 2 warps/node ----------------
__global__ void k_gat(const __half* __restrict__ h, const float* __restrict__ bias,
                      __half* __restrict__ ox) {
    int gw = (blockIdx.x * blockDim.x + threadIdx.x) >> 5;
    int lane = threadIdx.x & 31;
    int n = gw >> 1, half_ = gw & 1;
    if (n >= NN) return;
    int beg = d_off[n], end = d_off[n + 1];
    int head0 = half_ * 2;
    float2 adv = *(const float2*)&d_ad[n * 4 + head0];

    // pass 1: max over edges for this warp's 2 heads
    float m0 = -FLT_MAX, m1 = -FLT_MAX;
    for (int j = beg + lane; j < end; j += 32) {
        int s = d_csr_src[j];
        float2 a = *(const float2*)&d_as[s * 4 + head0];
        m0 = fmaxf(m0, lrelu(a.x + adv.x));
        m1 = fmaxf(m1, lrelu(a.y + adv.y));
    }
#pragma unroll
    for (int o = 16; o > 0; o >>= 1) {
        m0 = fmaxf(m0, __shfl_xor_sync(0xffffffffu, m0, o));
        m1 = fmaxf(m1, __shfl_xor_sync(0xffffffffu, m1, o));
    }

    // pass 2: sum of exp + store unnormalized alpha
    float s0 = 0.f, s1 = 0.f;
    for (int j = beg + lane; j < end; j += 32) {
        int s = d_csr_src[j];
        float2 a = *(const float2*)&d_as[s * 4 + head0];
        float p0 = __expf(lrelu(a.x + adv.x) - m0);
        float p1 = __expf(lrelu(a.y + adv.y) - m1);
        s0 += p0; s1 += p1;
        *(float2*)&d_alpha[(size_t)j * 4 + head0] = make_float2(p0, p1);
    }
#pragma unroll
    for (int o = 16; o > 0; o >>= 1) {
        s0 += __shfl_xor_sync(0xffffffffu, s0, o);
        s1 += __shfl_xor_sync(0xffffffffu, s1, o);
    }
    float rs0 = 1.f / s0, rs1 = 1.f / s1;
    __syncwarp();

    // pass 3: gather — 2 edge groups x 16 lanes x 16B
    int eg = lane >> 4;
    int sub = lane & 15;
    int cb = half_ * 128 + sub * 8;
    int head = head0 + (sub >> 3);
    float rs = (sub >> 3) ? rs1 : rs0;

    float acc[8] = {0, 0, 0, 0, 0, 0, 0, 0};
#pragma unroll 2
    for (int j = beg + eg; j < end; j += 2) {
        int s = d_csr_src[j];
        float w = d_alpha[(size_t)j * 4 + head];
        uint4 v = __ldg((const uint4*)(h + (size_t)s * HC + cb));
        float2 f0 = __half22float2(*(__half2*)&v.x);
        float2 f1 = __half22float2(*(__half2*)&v.y);
        float2 f2 = __half22float2(*(__half2*)&v.z);
        float2 f3 = __half22float2(*(__half2*)&v.w);
        acc[0] += w * f0.x; acc[1] += w * f0.y;
        acc[2] += w * f1.x; acc[3] += w * f1.y;
        acc[4] += w * f2.x; acc[5] += w * f2.y;
        acc[6] += w * f3.x; acc[7] += w * f3.y;
    }
#pragma unroll
    for (int i = 0; i < 8; i++)
        acc[i] += __shfl_xor_sync(0xffffffffu, acc[i], 16);

    if (eg == 0) {
        float4 b0 = *(const float4*)&bias[cb];
        float4 b1 = *(const float4*)&bias[cb + 4];
        float o0 = acc[0] * rs + b0.x, o1 = acc[1] * rs + b0.y;
        float o2 = acc[2] * rs + b0.z, o3 = acc[3] * rs + b0.w;
        float o4 = acc[4] * rs + b1.x, o5 = acc[5] * rs + b1.y;
        float o6 = acc[6] * rs + b1.z, o7 = acc[7] * rs + b1.w;
        o0 = o0 > 0.f ? o0 : 0.f; o1 = o1 > 0.f ? o1 : 0.f;
        o2 = o2 > 0.f ? o2 : 0.f; o3 = o3 > 0.f ? o3 : 0.f;
        o4 = o4 > 0.f ? o4 : 0.f; o5 = o5 > 0.f ? o5 : 0.f;
        o6 = o6 > 0.f ? o6 : 0.f; o7 = o7 > 0.f ? o7 : 0.f;
        uint4 pv;
        *(__half2*)&pv.x = __floats2half2_rn(o0, o1);
        *(__half2*)&pv.y = __floats2half2_rn(o2, o3);
        *(__half2*)&pv.z = __floats2half2_rn(o4, o5);
        *(__half2*)&pv.w = __floats2half2_rn(o6, o7);
        *(uint4*)(ox + (size_t)n * HC + cb) = pv;
    }
}

// ---------------- graph pooling piece (per tensor): 4-way node-chunk, atomicMax ----------------
__global__ void k_pool1(const __half* __restrict__ bp, int stride, int colbase) {
    int g = blockIdx.x;
    int c = blockIdx.y * 128 + threadIdx.x;
    if (c >= stride) return;
    int s0 = d_gstart[g], e0 = d_gend[g];
    int len = e0 - s0;
    if (len <= 0) return;
    int per = (len + 3) >> 2;
    int s = s0 + blockIdx.z * per;
    int e = s + per; if (e > e0) e = e0;
    if (s >= e) return;
    float v = 0.f;
    int i = s;
    for (; i + 4 <= e; i += 4) {
        float v0 = __half2float(__ldg(&bp[(i + 0) * stride + c]));
        float v1 = __half2float(__ldg(&bp[(i + 1) * stride + c]));
        float v2 = __half2float(__ldg(&bp[(i + 2) * stride + c]));
        float v3 = __half2float(__ldg(&bp[(i + 3) * stride + c]));
        v = fmaxf(v, fmaxf(fmaxf(v0, v1), fmaxf(v2, v3)));
    }
    for (; i < e; i++)
        v = fmaxf(v, __half2float(__ldg(&bp[i * stride + c])));
    atomicMax((int*)&d_gfeat[g * GFD + colbase + c], __float_as_int(v));
}

// ---------------- fused head MLPs ----------------
__global__ void k_lathead(const float* __restrict__ aggW, const float* __restrict__ aggb,
                          const float* __restrict__ muW, const float* __restrict__ mub,
                          const float* __restrict__ vW, const float* __restrict__ vb,
                          float* __restrict__ out) {
    __shared__ float gs[GFD];
    __shared__ float ls[LATD];
    int g = blockIdx.x, t = threadIdx.x;
    for (int i = t; i < GFD; i += 256) gs[i] = d_gfeat[g * GFD + i];
    __syncthreads();
    float acc = aggb[t];
    for (int k = 0; k < GFD; k++) acc += gs[k] * aggW[k * LATD + t];
    ls[t] = acc;
    __syncthreads();
    float am = mub[t], av = vb[t];
    for (int k = 0; k < LATD; k++) {
        float lv = ls[k];
        am += lv * muW[k * LATD + t];
        av += lv * vW[k * LATD + t];
    }
    out[g * LATD + t] = am;
    out[GG * LATD + g * LATD + t] = av;
}

// ---------------- launch ----------------
extern "C" void kernel_launch(void* const* d_in, const int* in_sizes, int n_in,
                              void* d_out, int out_size) {
    const float* bf   = (const float*)d_in[0];
    const int*   ei   = (const int*)  d_in[1];
    const int*   batch= (const int*)  d_in[2];
    const float* bfW  = (const float*)d_in[3];
    const float* bfb  = (const float*)d_in[4];
    const float* W1   = (const float*)d_in[5];
    const float* as1  = (const float*)d_in[6];
    const float* ad1  = (const float*)d_in[7];
    const float* b1   = (const float*)d_in[8];
    const float* W2   = (const float*)d_in[9];
    const float* as2  = (const float*)d_in[10];
    const float* ad2  = (const float*)d_in[11];
    const float* b2   = (const float*)d_in[12];
    const float* W3   = (const float*)d_in[13];
    const float* as3  = (const float*)d_in[14];
    const float* ad3  = (const float*)d_in[15];
    const float* b3   = (const float*)d_in[16];
    const float* aggW = (const float*)d_in[17];
    const float* aggb = (const float*)d_in[18];
    const float* muW  = (const float*)d_in[19];
    const float* mub  = (const float*)d_in[20];
    const float* vW   = (const float*)d_in[21];
    const float* vb   = (const float*)d_in[22];
    float* out = (float*)d_out;

    __half *p_n0, *p_x1, *p_x2, *p_x3, *p_wt, *p_h;
    int *p_deg, *p_off, *p_gstart, *p_gend;
    float *p_gfeat;
    cudaGetSymbolAddress((void**)&p_n0, d_n0);
    cudaGetSymbolAddress((void**)&p_x1, d_x1);
    cudaGetSymbolAddress((void**)&p_x2, d_x2);
    cudaGetSymbolAddress((void**)&p_x3, d_x3);
    cudaGetSymbolAddress((void**)&p_wt, d_wt);
    cudaGetSymbolAddress((void**)&p_h,  d_h);
    cudaGetSymbolAddress((void**)&p_deg, d_deg);
    cudaGetSymbolAddress((void**)&p_off, d_off);
    cudaGetSymbolAddress((void**)&p_gstart, d_gstart);
    cudaGetSymbolAddress((void**)&p_gend, d_gend);
    cudaGetSymbolAddress((void**)&p_gfeat, d_gfeat);

    static cudaStream_t s2 = nullptr;
    static cudaEvent_t evFork = nullptr, evJoin = nullptr;
    static cudaEvent_t evP = nullptr, ev1 = nullptr, ev2 = nullptr, ev3 = nullptr, evPool = nullptr;
    if (!s2) {
        cudaFuncSetAttribute(k_gemm, cudaFuncAttributeMaxDynamicSharedMemorySize, SMEM_BYTES);
        cudaStreamCreateWithFlags(&s2, cudaStreamNonBlocking);
        cudaEventCreateWithFlags(&evFork, cudaEventDisableTiming);
        cudaEventCreateWithFlags(&evJoin, cudaEventDisableTiming);
        cudaEventCreateWithFlags(&evP, cudaEventDisableTiming);
        cudaEventCreateWithFlags(&ev1, cudaEventDisableTiming);
        cudaEventCreateWithFlags(&ev2, cudaEventDisableTiming);
        cudaEventCreateWithFlags(&ev3, cudaEventDisableTiming);
        cudaEventCreateWithFlags(&evPool, cudaEventDisableTiming);
    }

    const int T = 256;
    dim3 ggrid((NN + 127) / 128, 2);
    int agrid = (2 * NN + 7) / 8;
    int egrid = (EL + T - 1) / T;
    dim3 pg64 (GG, 1, 4);
    dim3 pg256(GG, 2, 4);

    // ---- fork: CSR build + pooling on side stream ----
    cudaEventRecord(evFork, 0);
    cudaStreamWaitEvent(s2, evFork, 0);
    cudaMemsetAsync(p_deg, 0, NN * sizeof(int), s2);
    cudaMemsetAsync(p_gstart, 0x7F, GG * sizeof(int), s2);
    cudaMemsetAsync(p_gend, 0, GG * sizeof(int), s2);
    cudaMemsetAsync(p_off, 0, sizeof(int), s2);
    cudaMemsetAsync(p_gfeat, 0, GG * GFD * sizeof(float), s2);
    k_deg    <<<egrid, T, 0, s2>>>(ei);
    k_scan1  <<<NB1, SCAN_B, 0, s2>>>();
    k_scan2  <<<1, 32, 0, s2>>>();
    k_scan3b <<<(NN + T - 1) / T, T, 0, s2>>>(batch);
    k_scatter<<<egrid, T, 0, s2>>>(ei);
    cudaEventRecord(evJoin, s2);

    // ---- main stream: proj -> weights -> gemm1 ----
    k_proj   <<<(NN * FD + T - 1) / T, T>>>(bf, bfW, bfb);
    cudaEventRecord(evP, 0);
    k_cvt_all<<<(FD * HC + 2 * HC * HC + T - 1) / T, T>>>(W1, W2, W3, p_wt);
    k_gemm   <<<ggrid, 256, SMEM_BYTES>>>(p_n0, p_wt, as1, ad1, p_h, FD);

    // side stream: pool n0 once proj + bounds are done
    cudaStreamWaitEvent(s2, evP, 0);
    k_pool1<<<pg64, 128, 0, s2>>>(p_n0, FD, 0);

    // join: attention needs CSR + gemm1 outputs
    cudaStreamWaitEvent(0, evJoin, 0);

    // layer 1
    k_gat<<<agrid, 256>>>(p_h, b1, p_x1);
    cudaEventRecord(ev1, 0);
    cudaStreamWaitEvent(s2, ev1, 0);
    k_pool1<<<pg256, 128, 0, s2>>>(p_x1, HC, 64);
    // layer 2
    k_gemm<<<ggrid, 256, SMEM_BYTES>>>(p_x1, p_wt + HC * HC, as2, ad2, p_h, HC);
    k_gat <<<agrid, 256>>>(p_h, b2, p_x2);
    cudaEventRecord(ev2, 0);
    cudaStreamWaitEvent(s2, ev2, 0);
    k_pool1<<<pg256, 128, 0, s2>>>(p_x2, HC, 320);
    // layer 3
    k_gemm<<<ggrid, 256, SMEM_BYTES>>>(p_x2, p_wt + 2 * HC * HC, as3, ad3, p_h, HC);
    k_gat <<<agrid, 256>>>(p_h, b3, p_x3);
    cudaEventRecord(ev3, 0);
    cudaStreamWaitEvent(s2, ev3, 0);
    k_pool1<<<pg256, 128, 0, s2>>>(p_x3, HC, 576);
    cudaEventRecord(evPool, s2);

    // heads
    cudaStreamWaitEvent(0, evPool, 0);
    k_lathead<<<GG, 256>>>(aggW, aggb, muW, mub, vW, vb, out);
}

// round 12
// speedup vs baseline: 2.7614x; 1.0256x over previous
#include <cuda_runtime.h>
#include <cuda_fp16.h>
#include <math.h>
#include <float.h>

#define NN 50000
#define EE 300000
#define EL (EE + NN)
#define GG 64
#define FD 64
#define NH 4
#define HC 256
#define LATD 256
#define GFD 832
#define SCAN_B 1024
#define NB1 ((NN + SCAN_B - 1) / SCAN_B)   // 49
#define CVT_TOT (FD * HC + 2 * HC * HC)

// GEMM smem: 128B rows (K-chunk 64), XOR swizzle seg^(row&7), 3 stages
#define A_OFF 0
#define B_OFF 16384
#define STAGE 32768
#define SMEM_BYTES (3 * STAGE)

// ---------------- device scratch (zero-initialized at module load) ----------------
__device__ __half d_n0[NN * FD];
__device__ __half d_x1[NN * HC];
__device__ __half d_x2[NN * HC];
__device__ __half d_x3[NN * HC];
__device__ __half d_wt[3 * HC * HC];
__device__ __half d_h [NN * HC];
__device__ float d_as[NN * NH];
__device__ float d_ad[NN * NH];
__device__ float d_alpha[(size_t)EL * NH];
__device__ int   d_deg[NN];          // self-cleaning: zeroed by k_scan1 after read
__device__ int   d_off[NN + 1];
__device__ int   d_cur[NN];
__device__ int   d_csr_src[EL];
__device__ int   d_bsum[NB1 + 1];
__device__ int   d_gb[2 * GG];       // [0,GG): gstart, [GG,2GG): gend
__device__ float d_gfeat[GG * GFD];  // self-cleaning: zeroed by k_lathead after read

// ---------------- CSR build ----------------
__global__ void k_deg(const int* __restrict__ ei) {
    int i = blockIdx.x * blockDim.x + threadIdx.x;
    if (i >= EL) return;
    int dst = (i < EE) ? ei[EE + i] : (i - EE);
    atomicAdd(&d_deg[dst], 1);
}

__global__ void k_scan1() {
    __shared__ int sm[SCAN_B];
    int tid = threadIdx.x;
    int i = blockIdx.x * SCAN_B + tid;
    int v = 0;
    if (i < NN) { v = d_deg[i]; d_deg[i] = 0; }   // read + self-clean for next replay
    sm[tid] = v;
    __syncthreads();
    for (int d = 1; d < SCAN_B; d <<= 1) {
        int t = 0;
        if (tid >= d) t = sm[tid - d];
        __syncthreads();
        sm[tid] += t;
        __syncthreads();
    }
    if (i < NN) d_off[i + 1] = sm[tid];
    if (tid == SCAN_B - 1) d_bsum[blockIdx.x] = sm[tid];
}

__global__ void k_scan2() {
    int lane = threadIdx.x;
    int a = (lane < NB1) ? d_bsum[lane] : 0;
    int b = (lane + 32 < NB1) ? d_bsum[lane + 32] : 0;
    int ia = a;
#pragma unroll
    for (int o = 1; o < 32; o <<= 1) {
        int t = __shfl_up_sync(0xffffffffu, ia, o);
        if (lane >= o) ia += t;
    }
    int tot0 = __shfl_sync(0xffffffffu, ia, 31);
    int ib = b;
#pragma unroll
    for (int o = 1; o < 32; o <<= 1) {
        int t = __shfl_up_sync(0xffffffffu, ib, o);
        if (lane >= o) ib += t;
    }
    if (lane < NB1) d_bsum[lane] = ia - a;
    if (lane + 32 < NB1) d_bsum[lane + 32] = tot0 + ib - b;
}

// scan fixup + cursor init + per-graph bounds (sorted-boundary stores)
__global__ void k_scan3b(const int* __restrict__ batch) {
    int i = blockIdx.x * blockDim.x + threadIdx.x;
    if (i >= NN) return;
    int val = d_off[i + 1] + d_bsum[i >> 10];
    d_off[i + 1] = val;
    if (i + 1 < NN) d_cur[i + 1] = val;
    if (i == 0) { d_cur[0] = 0; d_off[0] = 0; }
    int b = batch[i];
    if (i == 0) d_gb[b] = 0;
    if (i == NN - 1) d_gb[GG + b] = NN;
    if (i + 1 < NN) {
        int b2 = batch[i + 1];
        if (b2 != b) { d_gb[GG + b] = i + 1; d_gb[b2] = i + 1; }
    }
}

__global__ void k_scatter(const int* __restrict__ ei) {
    int i = blockIdx.x * blockDim.x + threadIdx.x;
    if (i >= EL) return;
    int src, dst;
    if (i < EE) { src = ei[i]; dst = ei[EE + i]; }
    else        { src = i - EE; dst = i - EE; }
    int pos = atomicAdd(&d_cur[dst], 1);
    d_csr_src[pos] = src;
}

// ---------------- input projection + all three weight transposes ----------------
__global__ void k_projcvt(const float* __restrict__ bf, const float* __restrict__ W,
                          const float* __restrict__ b,
                          const float* __restrict__ W1, const float* __restrict__ W2,
                          const float* __restrict__ W3, __half* __restrict__ wt) {
    int t = blockIdx.x * blockDim.x + threadIdx.x;
    if (t < NN * FD) {
        int n = t >> 6, f = t & 63;
        const float* r = &bf[n * 5];
        float acc = b[f];
        acc += r[0] * W[0 * FD + f];
        acc += r[1] * W[1 * FD + f];
        acc += r[2] * W[2 * FD + f];
        acc += r[3] * W[3 * FD + f];
        acc += r[4] * W[4 * FD + f];
        acc = acc > 0.f ? acc : 0.f;
        d_n0[t] = __float2half(acc);
    } else {
        int i = t - NN * FD;
        if (i >= CVT_TOT) return;
        if (i < FD * HC) {
            int k = i / HC, n = i % HC;
            wt[n * FD + k] = __float2half(W1[i]);
        } else if (i < FD * HC + HC * HC) {
            int j = i - FD * HC;
            int k = j / HC, n = j % HC;
            wt[HC * HC + n * HC + k] = __float2half(W2[j]);
        } else {
            int j = i - FD * HC - HC * HC;
            int k = j / HC, n = j % HC;
            wt[2 * HC * HC + n * HC + k] = __float2half(W3[j]);
        }
    }
}

// ---------------- fp16 tensor-core GEMM + fused attention dots ----------------
__device__ __forceinline__ void mma16816(float* d, const unsigned* a, unsigned b0, unsigned b1) {
    asm volatile(
        "mma.sync.aligned.m16n8k16.row.col.f32.f16.f16.f32 "
        "{%0,%1,%2,%3}, {%4,%5,%6,%7}, {%8,%9}, {%0,%1,%2,%3};\n"
        : "+f"(d[0]), "+f"(d[1]), "+f"(d[2]), "+f"(d[3])
        : "r"(a[0]), "r"(a[1]), "r"(a[2]), "r"(a[3]), "r"(b0), "r"(b1));
}

__device__ __forceinline__ void ldm4(unsigned& r0, unsigned& r1, unsigned& r2, unsigned& r3,
                                     unsigned addr) {
    asm volatile("ldmatrix.sync.aligned.m8n8.x4.shared.b16 {%0,%1,%2,%3}, [%4];\n"
                 : "=r"(r0), "=r"(r1), "=r"(r2), "=r"(r3) : "r"(addr));
}

#define CPA(dst, src) asm volatile("cp.async.cg.shared.global [%0], [%1], 16;\n" :: "r"(dst), "l"(src))

extern __shared__ char smem_raw[];

__global__ void __launch_bounds__(256, 2) k_gemm(
    const __half* __restrict__ x, const __half* __restrict__ w,
    const float* __restrict__ asw, const float* __restrict__ adw,
    __half* __restrict__ out, int K)
{
    unsigned sbase;
    asm("{ .reg .u64 t; cvta.to.shared.u64 t, %1; cvt.u32.u64 %0, t; }"
        : "=r"(sbase) : "l"(smem_raw));
    int tid = threadIdx.x, lane = tid & 31, wid = tid >> 5;
    int warp_m = wid & 3, warp_n = wid >> 2;
    int row0 = blockIdx.x * 128, col0 = blockIdx.y * 128;
    int nch = K >> 6;

    int row_a = warp_m * 32 + (lane & 15);
    unsigned a_base = (unsigned)(row_a * 128) + (((unsigned)row_a & 7u) << 4);
    unsigned colA = (unsigned)(lane >> 4);
    int row_b = warp_n * 64 + ((lane >> 4) << 3) + (lane & 7);
    unsigned b_base = (unsigned)(row_b * 128) + (((unsigned)row_b & 7u) << 4);
    unsigned colB = (unsigned)((lane >> 3) & 1);

    float acc[2][8][4];
#pragma unroll
    for (int mt = 0; mt < 2; mt++)
#pragma unroll
        for (int nt = 0; nt < 8; nt++)
#pragma unroll
            for (int i = 0; i < 4; i++) acc[mt][nt][i] = 0.f;

    auto load_chunk = [&](int c) {
        unsigned sb = sbase + (unsigned)((c % 3) * STAGE);
        int k0 = c << 6;
#pragma unroll
        for (int i = 0; i < 4; i++) {
            int g = tid + 256 * i;
            int row = g >> 3;
            unsigned seg = (unsigned)(g & 7);
            unsigned so = (unsigned)(row * 128) + ((seg ^ ((unsigned)row & 7u)) << 4);
            int gr = row0 + row;
            if (gr < NN) {
                CPA(sb + A_OFF + so, (const char*)x + ((size_t)gr * K + k0) * 2 + seg * 16);
            } else {
                asm volatile("st.shared.v4.b32 [%0], {%1,%1,%1,%1};" :: "r"(sb + A_OFF + so), "r"(0u));
            }
        }
#pragma unroll
        for (int i = 0; i < 4; i++) {
            int g = tid + 256 * i;
            int row = g >> 3;
            unsigned seg = (unsigned)(g & 7);
            unsigned so = (unsigned)(row * 128) + ((seg ^ ((unsigned)row & 7u)) << 4);
            int gc = col0 + row;
            CPA(sb + B_OFF + so, (const char*)w + ((size_t)gc * K + k0) * 2 + seg * 16);
        }
        asm volatile("cp.async.commit_group;\n");
    };

    load_chunk(0);
    if (nch > 1) load_chunk(1);
    else         asm volatile("cp.async.commit_group;\n");

    for (int c = 0; c < nch; c++) {
        if (c < nch - 1) asm volatile("cp.async.wait_group 1;\n");
        else             asm volatile("cp.async.wait_group 0;\n");
        __syncthreads();
        if (c + 2 < nch) load_chunk(c + 2);

        unsigned base = sbase + (unsigned)((c % 3) * STAGE);
#pragma unroll
        for (int ko = 0; ko < 4; ko++) {
            unsigned kxa = (colA + 2u * (unsigned)ko) << 4;
            unsigned kxb = (colB + 2u * (unsigned)ko) << 4;
            unsigned ah[2][4];
#pragma unroll
            for (int mt = 0; mt < 2; mt++)
                ldm4(ah[mt][0], ah[mt][1], ah[mt][2], ah[mt][3],
                     (base + A_OFF + a_base + mt * 2048) ^ kxa);
            unsigned bh[2][4];
            ldm4(bh[0][0], bh[0][1], bh[0][2], bh[0][3], (base + B_OFF + b_base) ^ kxb);
#pragma unroll
            for (int p = 0; p < 4; p++) {
                int cur = p & 1, nxt = cur ^ 1;
                if (p < 3)
                    ldm4(bh[nxt][0], bh[nxt][1], bh[nxt][2], bh[nxt][3],
                         (base + B_OFF + b_base + (p + 1) * 2048) ^ kxb);
#pragma unroll
                for (int q = 0; q < 2; q++) {
                    int nt = p * 2 + q;
#pragma unroll
                    for (int mt = 0; mt < 2; mt++)
                        mma16816(acc[mt][nt], ah[mt], bh[cur][q * 2], bh[cur][q * 2 + 1]);
                }
            }
        }
    }

    // ---- epilogue: store h (fp16) + fused attention dots (fp32) ----
    int head = blockIdx.y * 2 + warp_n;
    float pa[4] = {0, 0, 0, 0}, pd[4] = {0, 0, 0, 0};
#pragma unroll
    for (int nt = 0; nt < 8; nt++) {
        int cc = col0 + warp_n * 64 + nt * 8 + (lane & 3) * 2;
        float s0 = __ldg(&asw[cc]), s1 = __ldg(&asw[cc + 1]);
        float t0 = __ldg(&adw[cc]), t1 = __ldg(&adw[cc + 1]);
#pragma unroll
        for (int mt = 0; mt < 2; mt++) {
            float* a = acc[mt][nt];
            pa[mt * 2]     += a[0] * s0 + a[1] * s1;
            pa[mt * 2 + 1] += a[2] * s0 + a[3] * s1;
            pd[mt * 2]     += a[0] * t0 + a[1] * t1;
            pd[mt * 2 + 1] += a[2] * t0 + a[3] * t1;
            int rr = row0 + warp_m * 32 + mt * 16 + (lane >> 2);
            if (rr < NN)
                *(__half2*)&out[(size_t)rr * HC + cc] = __floats2half2_rn(a[0], a[1]);
            if (rr + 8 < NN)
                *(__half2*)&out[(size_t)(rr + 8) * HC + cc] = __floats2half2_rn(a[2], a[3]);
        }
    }
#pragma unroll
    for (int s = 0; s < 4; s++) {
        pa[s] += __shfl_xor_sync(0xffffffffu, pa[s], 1);
        pa[s] += __shfl_xor_sync(0xffffffffu, pa[s], 2);
        pd[s] += __shfl_xor_sync(0xffffffffu, pd[s], 1);
        pd[s] += __shfl_xor_sync(0xffffffffu, pd[s], 2);
    }
    if ((lane & 3) == 0) {
#pragma unroll
        for (int s = 0; s < 4; s++) {
            int rr = row0 + warp_m * 32 + (s >> 1) * 16 + (s & 1) * 8 + (lane >> 2);
            if (rr < NN) {
                d_as[rr * 4 + head] = pa[s];
                d_ad[rr * 4 + head] = pd[s];
            }
        }
    }
}

__device__ __forceinline__ float lrelu(float v) { return v > 0.f ? v : 0.2f * v; }

// ---------------- fused GAT: softmax stats + alpha + aggregation, 2 warps/node ----------------
__global__ void k_gat(const __half* __restrict__ h, const float* __restrict__ bias,
                      __half* __restrict__ ox) {
    int gw = (blockIdx.x * blockDim.x + threadIdx.x) >> 5;
    int lane = threadIdx.x & 31;
    int n = gw >> 1, half_ = gw & 1;
    if (n >= NN) return;
    int beg = d_off[n], end = d_off[n + 1];
    int head0 = half_ * 2;
    float2 adv = *(const float2*)&d_ad[n * 4 + head0];

    // pass 1: max over edges for this warp's 2 heads
    float m0 = -FLT_MAX, m1 = -FLT_MAX;
    for (int j = beg + lane; j < end; j += 32) {
        int s = d_csr_src[j];
        float2 a = *(const float2*)&d_as[s * 4 + head0];
        m0 = fmaxf(m0, lrelu(a.x + adv.x));
        m1 = fmaxf(m1, lrelu(a.y + adv.y));
    }
#pragma unroll
    for (int o = 16; o > 0; o >>= 1) {
        m0 = fmaxf(m0, __shfl_xor_sync(0xffffffffu, m0, o));
        m1 = fmaxf(m1, __shfl_xor_sync(0xffffffffu, m1, o));
    }

    // pass 2: sum of exp + store unnormalized alpha
    float s0 = 0.f, s1 = 0.f;
    for (int j = beg + lane; j < end; j += 32) {
        int s = d_csr_src[j];
        float2 a = *(const float2*)&d_as[s * 4 + head0];
        float p0 = __expf(lrelu(a.x + adv.x) - m0);
        float p1 = __expf(lrelu(a.y + adv.y) - m1);
        s0 += p0; s1 += p1;
        *(float2*)&d_alpha[(size_t)j * 4 + head0] = make_float2(p0, p1);
    }
#pragma unroll
    for (int o = 16; o > 0; o >>= 1) {
        s0 += __shfl_xor_sync(0xffffffffu, s0, o);
        s1 += __shfl_xor_sync(0xffffffffu, s1, o);
    }
    float rs0 = 1.f / s0, rs1 = 1.f / s1;
    __syncwarp();

    // pass 3: gather — 2 edge groups x 16 lanes x 16B
    int eg = lane >> 4;
    int sub = lane & 15;
    int cb = half_ * 128 + sub * 8;
    int head = head0 + (sub >> 3);
    float rs = (sub >> 3) ? rs1 : rs0;

    float acc[8] = {0, 0, 0, 0, 0, 0, 0, 0};
#pragma unroll 2
    for (int j = beg + eg; j < end; j += 2) {
        int s = d_csr_src[j];
        float w = d_alpha[(size_t)j * 4 + head];
        uint4 v = __ldg((const uint4*)(h + (size_t)s * HC + cb));
        float2 f0 = __half22float2(*(__half2*)&v.x);
        float2 f1 = __half22float2(*(__half2*)&v.y);
        float2 f2 = __half22float2(*(__half2*)&v.z);
        float2 f3 = __half22float2(*(__half2*)&v.w);
        acc[0] += w * f0.x; acc[1] += w * f0.y;
        acc[2] += w * f1.x; acc[3] += w * f1.y;
        acc[4] += w * f2.x; acc[5] += w * f2.y;
        acc[6] += w * f3.x; acc[7] += w * f3.y;
    }
#pragma unroll
    for (int i = 0; i < 8; i++)
        acc[i] += __shfl_xor_sync(0xffffffffu, acc[i], 16);

    if (eg == 0) {
        float4 b0 = *(const float4*)&bias[cb];
        float4 b1 = *(const float4*)&bias[cb + 4];
        float o0 = acc[0] * rs + b0.x, o1 = acc[1] * rs + b0.y;
        float o2 = acc[2] * rs + b0.z, o3 = acc[3] * rs + b0.w;
        float o4 = acc[4] * rs + b1.x, o5 = acc[5] * rs + b1.y;
        float o6 = acc[6] * rs + b1.z, o7 = acc[7] * rs + b1.w;
        o0 = o0 > 0.f ? o0 : 0.f; o1 = o1 > 0.f ? o1 : 0.f;
        o2 = o2 > 0.f ? o2 : 0.f; o3 = o3 > 0.f ? o3 : 0.f;
        o4 = o4 > 0.f ? o4 : 0.f; o5 = o5 > 0.f ? o5 : 0.f;
        o6 = o6 > 0.f ? o6 : 0.f; o7 = o7 > 0.f ? o7 : 0.f;
        uint4 pv;
        *(__half2*)&pv.x = __floats2half2_rn(o0, o1);
        *(__half2*)&pv.y = __floats2half2_rn(o2, o3);
        *(__half2*)&pv.z = __floats2half2_rn(o4, o5);
        *(__half2*)&pv.w = __floats2half2_rn(o6, o7);
        *(uint4*)(ox + (size_t)n * HC + cb) = pv;
    }
}

// ---------------- graph pooling piece (per tensor): 8-way node-chunk, atomicMax ----------------
__global__ void k_pool1(const __half* __restrict__ bp, int stride, int colbase) {
    int g = blockIdx.x;
    int c = blockIdx.y * 128 + threadIdx.x;
    if (c >= stride) return;
    int s0 = d_gb[g], e0 = d_gb[GG + g];
    int len = e0 - s0;
    if (len <= 0) return;
    int per = (len + 7) >> 3;
    int s = s0 + blockIdx.z * per;
    int e = s + per; if (e > e0) e = e0;
    if (s >= e) return;
    float v = 0.f;
    int i = s;
    for (; i + 4 <= e; i += 4) {
        float v0 = __half2float(__ldg(&bp[(i + 0) * stride + c]));
        float v1 = __half2float(__ldg(&bp[(i + 1) * stride + c]));
        float v2 = __half2float(__ldg(&bp[(i + 2) * stride + c]));
        float v3 = __half2float(__ldg(&bp[(i + 3) * stride + c]));
        v = fmaxf(v, fmaxf(fmaxf(v0, v1), fmaxf(v2, v3)));
    }
    for (; i < e; i++)
        v = fmaxf(v, __half2float(__ldg(&bp[i * stride + c])));
    atomicMax((int*)&d_gfeat[g * GFD + colbase + c], __float_as_int(v));
}

// ---------------- fused head MLPs + inline x3 pooling + gfeat self-clean ----------------
__global__ void k_lathead(const float* __restrict__ aggW, const float* __restrict__ aggb,
                          const float* __restrict__ muW, const float* __restrict__ mub,
                          const float* __restrict__ vW, const float* __restrict__ vb,
                          float* __restrict__ out) {
    __shared__ float gs[GFD];
    __shared__ float ls[LATD];
    int g = blockIdx.x, t = threadIdx.x;
    // cols 0..575 from gfeat (n0, x1, x2 pools)
    for (int i = t; i < 576; i += 256) gs[i] = d_gfeat[g * GFD + i];
    // cols 576..831: pool x3 inline (coalesced 512B row reads)
    {
        int s0 = d_gb[g], e0 = d_gb[GG + g];
        float v = 0.f;
        for (int i = s0; i < e0; i++)
            v = fmaxf(v, __half2float(__ldg(&d_x3[(size_t)i * HC + t])));
        gs[576 + t] = v;
    }
    __syncthreads();
    // self-clean gfeat for next replay
    for (int i = t; i < 576; i += 256) d_gfeat[g * GFD + i] = 0.f;

    float acc = aggb[t];
    for (int k = 0; k < GFD; k++) acc += gs[k] * aggW[k * LATD + t];
    ls[t] = acc;
    __syncthreads();
    float am = mub[t], av = vb[t];
    for (int k = 0; k < LATD; k++) {
        float lv = ls[k];
        am += lv * muW[k * LATD + t];
        av += lv * vW[k * LATD + t];
    }
    out[g * LATD + t] = am;
    out[GG * LATD + g * LATD + t] = av;
}

// ---------------- launch ----------------
extern "C" void kernel_launch(void* const* d_in, const int* in_sizes, int n_in,
                              void* d_out, int out_size) {
    const float* bf   = (const float*)d_in[0];
    const int*   ei   = (const int*)  d_in[1];
    const int*   batch= (const int*)  d_in[2];
    const float* bfW  = (const float*)d_in[3];
    const float* bfb  = (const float*)d_in[4];
    const float* W1   = (const float*)d_in[5];
    const float* as1  = (const float*)d_in[6];
    const float* ad1  = (const float*)d_in[7];
    const float* b1   = (const float*)d_in[8];
    const float* W2   = (const float*)d_in[9];
    const float* as2  = (const float*)d_in[10];
    const float* ad2  = (const float*)d_in[11];
    const float* b2   = (const float*)d_in[12];
    const float* W3   = (const float*)d_in[13];
    const float* as3  = (const float*)d_in[14];
    const float* ad3  = (const float*)d_in[15];
    const float* b3   = (const float*)d_in[16];
    const float* aggW = (const float*)d_in[17];
    const float* aggb = (const float*)d_in[18];
    const float* muW  = (const float*)d_in[19];
    const float* mub  = (const float*)d_in[20];
    const float* vW   = (const float*)d_in[21];
    const float* vb   = (const float*)d_in[22];
    float* out = (float*)d_out;

    __half *p_n0, *p_x1, *p_x2, *p_x3, *p_wt, *p_h;
    int *p_gb;
    cudaGetSymbolAddress((void**)&p_n0, d_n0);
    cudaGetSymbolAddress((void**)&p_x1, d_x1);
    cudaGetSymbolAddress((void**)&p_x2, d_x2);
    cudaGetSymbolAddress((void**)&p_x3, d_x3);
    cudaGetSymbolAddress((void**)&p_wt, d_wt);
    cudaGetSymbolAddress((void**)&p_h,  d_h);
    cudaGetSymbolAddress((void**)&p_gb, d_gb);

    static cudaStream_t s2 = nullptr;
    static cudaEvent_t evFork = nullptr, evJoin = nullptr;
    static cudaEvent_t evP = nullptr, ev1 = nullptr, ev2 = nullptr, evPool = nullptr;
    if (!s2) {
        cudaFuncSetAttribute(k_gemm, cudaFuncAttributeMaxDynamicSharedMemorySize, SMEM_BYTES);
        cudaStreamCreateWithFlags(&s2, cudaStreamNonBlocking);
        cudaEventCreateWithFlags(&evFork, cudaEventDisableTiming);
        cudaEventCreateWithFlags(&evJoin, cudaEventDisableTiming);
        cudaEventCreateWithFlags(&evP, cudaEventDisableTiming);
        cudaEventCreateWithFlags(&ev1, cudaEventDisableTiming);
        cudaEventCreateWithFlags(&ev2, cudaEventDisableTiming);
        cudaEventCreateWithFlags(&evPool, cudaEventDisableTiming);
    }

    const int T = 256;
    dim3 ggrid((NN + 127) / 128, 2);
    int agrid = (2 * NN + 7) / 8;
    int egrid = (EL + T - 1) / T;
    dim3 pg64 (GG, 1, 8);
    dim3 pg256(GG, 2, 8);

    // ---- fork: CSR build on side stream (deg/off/gfeat are self-cleaning) ----
    cudaEventRecord(evFork, 0);
    cudaStreamWaitEvent(s2, evFork, 0);
    cudaMemsetAsync(p_gb, 0x7F, 2 * GG * sizeof(int), s2);   // empty-graph sentinel
    k_deg    <<<egrid, T, 0, s2>>>(ei);
    k_scan1  <<<NB1, SCAN_B, 0, s2>>>();
    k_scan2  <<<1, 32, 0, s2>>>();
    k_scan3b <<<(NN + T - 1) / T, T, 0, s2>>>(batch);
    k_scatter<<<egrid, T, 0, s2>>>(ei);
    cudaEventRecord(evJoin, s2);

    // ---- main stream: proj+cvt -> gemm1 ----
    k_projcvt<<<(NN * FD + CVT_TOT + T - 1) / T, T>>>(bf, bfW, bfb, W1, W2, W3, p_wt);
    cudaEventRecord(evP, 0);
    k_gemm   <<<ggrid, 256, SMEM_BYTES>>>(p_n0, p_wt, as1, ad1, p_h, FD);

    // side stream: pool n0 once proj + bounds are done
    cudaStreamWaitEvent(s2, evP, 0);
    k_pool1<<<pg64, 128, 0, s2>>>(p_n0, FD, 0);

    // join: attention needs CSR + gemm1 outputs
    cudaStreamWaitEvent(0, evJoin, 0);

    // layer 1
    k_gat<<<agrid, 256>>>(p_h, b1, p_x1);
    cudaEventRecord(ev1, 0);
    cudaStreamWaitEvent(s2, ev1, 0);
    k_pool1<<<pg256, 128, 0, s2>>>(p_x1, HC, 64);
    // layer 2
    k_gemm<<<ggrid, 256, SMEM_BYTES>>>(p_x1, p_wt + HC * HC, as2, ad2, p_h, HC);
    k_gat <<<agrid, 256>>>(p_h, b2, p_x2);
    cudaEventRecord(ev2, 0);
    cudaStreamWaitEvent(s2, ev2, 0);
    k_pool1<<<pg256, 128, 0, s2>>>(p_x2, HC, 320);
    cudaEventRecord(evPool, s2);
    // layer 3
    k_gemm<<<ggrid, 256, SMEM_BYTES>>>(p_x2, p_wt + 2 * HC * HC, as3, ad3, p_h, HC);
    k_gat <<<agrid, 256>>>(p_h, b3, p_x3);

    // heads (x3 pooled inline; waits for n0/x1/x2 pools via evPool)
    cudaStreamWaitEvent(0, evPool, 0);
    k_lathead<<<GG, 256>>>(aggW, aggb, muW, mub, vW, vb, out);
}